// round 8
// baseline (speedup 1.0000x reference)
#include <cuda_runtime.h>
#include <cstdint>
#include <math.h>

#define B    64
#define C    768
#define HW   576
#define NM   50
#define NSEL (B*NM)   // 3200
#define EPSV 1e-5f
#define KC   32
#define NCH  (C/KC)    // 24
#define NCH2 (NSEL/KC) // 100

typedef unsigned long long ull;

// ---------------- scratch ----------------
__device__ float  g_a2[B*HW], g_b2[B*HW];
__device__ ull    g_key[2][B*HW];
__device__ int    g_sel_in[2][NSEL];
__device__ int    g_sel_c [2][NSEL];
__device__ float  g_X[4][(size_t)NSEL*C];
__device__ float  g_S[6][(size_t)C*C];
__device__ float  g_csp[6][16][C];
__device__ float  g_colsum[6][C];
__device__ double g_acc[32];

// ---------------- helpers ----------------
__device__ __forceinline__ void mma_tf32(float c[4],
                                         uint32_t a0, uint32_t a1, uint32_t a2, uint32_t a3,
                                         uint32_t b0, uint32_t b1) {
    asm volatile(
        "mma.sync.aligned.m16n8k8.row.col.f32.tf32.tf32.f32 "
        "{%0,%1,%2,%3}, {%4,%5,%6,%7}, {%8,%9}, {%0,%1,%2,%3};"
        : "+f"(c[0]), "+f"(c[1]), "+f"(c[2]), "+f"(c[3])
        : "r"(a0), "r"(a1), "r"(a2), "r"(a3), "r"(b0), "r"(b1));
}
#define CP_A16(d, s) asm volatile("cp.async.ca.shared.global [%0], [%1], 16;" :: "r"(d), "l"(s))
#define CP_COMMIT()  asm volatile("cp.async.commit_group;" ::: "memory")
#define CP_WAIT1()   asm volatile("cp.async.wait_group 1;" ::: "memory")
#define CP_WAIT0()   asm volatile("cp.async.wait_group 0;" ::: "memory")

__device__ __forceinline__ uint32_t smem_u32(const void* p) {
    uint32_t a;
    asm("{ .reg .u64 t; cvta.to.shared.u64 t, %1; cvt.u32.u64 %0, t; }" : "=r"(a) : "l"(p));
    return a;
}
__device__ __forceinline__ ull enc_key(float f, int idx) {
    uint32_t u = __float_as_uint(f);
    u = (u & 0x80000000u) ? ~u : (u | 0x80000000u);
    return ((ull)u << 32) | (uint32_t)idx;
}
__device__ __forceinline__ float dec_val(ull k) {
    uint32_t e = (uint32_t)(k >> 32);
    uint32_t u = (e & 0x80000000u) ? (e ^ 0x80000000u) : ~e;
    return __uint_as_float(u);
}

__device__ __forceinline__ float blockReduceSum(float v) {
    __shared__ float sw[32];
    int lane = threadIdx.x & 31, w = threadIdx.x >> 5;
    #pragma unroll
    for (int o = 16; o; o >>= 1) v += __shfl_xor_sync(~0u, v, o);
    if (lane == 0) sw[w] = v;
    __syncthreads();
    int nw = (blockDim.x + 31) >> 5;
    v = (threadIdx.x < nw) ? sw[threadIdx.x] : 0.f;
    if (w == 0) {
        #pragma unroll
        for (int o = 16; o; o >>= 1) v += __shfl_xor_sync(~0u, v, o);
    }
    return v;
}

// ---------------- kernels ----------------
__global__ void k_init() { if (threadIdx.x < 32) g_acc[threadIdx.x] = 0.0; }
__global__ void k_keyinit() {
    int i = blockIdx.x * blockDim.x + threadIdx.x;
    if (i < 2 * B * HW) ((ull*)g_key)[i] = ~0ull;
}

__global__ void k_norms(const float* __restrict__ s1, const float* __restrict__ s2) {
    int b = blockIdx.x, p = threadIdx.x;
    const float* src = blockIdx.y ? s2 : s1;
    float*       dst = blockIdx.y ? g_b2 : g_a2;
    const float* base = src + (size_t)b * C * HW + p;
    float s = 0.f;
    #pragma unroll 8
    for (int c = 0; c < C; c++) { float v = base[(size_t)c * HW]; s += v * v; }
    dst[b * HW + p] = s;
}

#define LDW     136               // 136 % 32 == 8 -> conflict-free LDS.128 fragment fetch
#define MATW    (32*LDW)
#define SSTRIDE (2*MATW)          // u32 per stage
#define NSTG    3
#define GSMEM   (NSTG * SSTRIDE * 4)   // 104448 B

// logical->physical remap (read side only):
//   A frag (i, half) <-> m = wm + (i>>1)*32 + gr*4 + (i&1)*2 + half
//   B frag j, reg rb <-> n = wn + 8*gc + 4*rb + j
#define FRAG_MMA(As, Bs, ks)                                                       \
    {                                                                              \
        uint4 a_lo0 = *(const uint4*)&As[(ks + gc    ) * LDW + wm      + gr * 4];  \
        uint4 a_lo1 = *(const uint4*)&As[(ks + gc    ) * LDW + wm + 32 + gr * 4];  \
        uint4 a_hi0 = *(const uint4*)&As[(ks + gc + 4) * LDW + wm      + gr * 4];  \
        uint4 a_hi1 = *(const uint4*)&As[(ks + gc + 4) * LDW + wm + 32 + gr * 4];  \
        uint4 b_lo  = *(const uint4*)&Bs[(ks + gc    ) * LDW + wn      + gr * 4];  \
        uint4 b_hi  = *(const uint4*)&Bs[(ks + gc + 4) * LDW + wn      + gr * 4];  \
        mma_tf32(acc[0][0], a_lo0.x, a_lo0.y, a_hi0.x, a_hi0.y, b_lo.x, b_hi.x);   \
        mma_tf32(acc[0][1], a_lo0.x, a_lo0.y, a_hi0.x, a_hi0.y, b_lo.y, b_hi.y);   \
        mma_tf32(acc[0][2], a_lo0.x, a_lo0.y, a_hi0.x, a_hi0.y, b_lo.z, b_hi.z);   \
        mma_tf32(acc[0][3], a_lo0.x, a_lo0.y, a_hi0.x, a_hi0.y, b_lo.w, b_hi.w);   \
        mma_tf32(acc[1][0], a_lo0.z, a_lo0.w, a_hi0.z, a_hi0.w, b_lo.x, b_hi.x);   \
        mma_tf32(acc[1][1], a_lo0.z, a_lo0.w, a_hi0.z, a_hi0.w, b_lo.y, b_hi.y);   \
        mma_tf32(acc[1][2], a_lo0.z, a_lo0.w, a_hi0.z, a_hi0.w, b_lo.z, b_hi.z);   \
        mma_tf32(acc[1][3], a_lo0.z, a_lo0.w, a_hi0.z, a_hi0.w, b_lo.w, b_hi.w);   \
        mma_tf32(acc[2][0], a_lo1.x, a_lo1.y, a_hi1.x, a_hi1.y, b_lo.x, b_hi.x);   \
        mma_tf32(acc[2][1], a_lo1.x, a_lo1.y, a_hi1.x, a_hi1.y, b_lo.y, b_hi.y);   \
        mma_tf32(acc[2][2], a_lo1.x, a_lo1.y, a_hi1.x, a_hi1.y, b_lo.z, b_hi.z);   \
        mma_tf32(acc[2][3], a_lo1.x, a_lo1.y, a_hi1.x, a_hi1.y, b_lo.w, b_hi.w);   \
        mma_tf32(acc[3][0], a_lo1.z, a_lo1.w, a_hi1.z, a_hi1.w, b_lo.x, b_hi.x);   \
        mma_tf32(acc[3][1], a_lo1.z, a_lo1.w, a_hi1.z, a_hi1.w, b_lo.y, b_hi.y);   \
        mma_tf32(acc[3][2], a_lo1.z, a_lo1.w, a_hi1.z, a_hi1.w, b_lo.z, b_hi.z);   \
        mma_tf32(acc[3][3], a_lo1.z, a_lo1.w, a_hi1.z, a_hi1.w, b_lo.w, b_hi.w);   \
    }

// ---- fused tf32 GEMM + row/col argmin. CTA 128x128, 8 warps (2m x 4n), 3-stage ----
__global__ void __launch_bounds__(256, 2) k_gemm_fused(const float* __restrict__ s1,
                                                       const float* __restrict__ s2) {
    extern __shared__ uint32_t dyn[];
    int b  = blockIdx.z;
    int m0 = blockIdx.y * 128, n0 = blockIdx.x * 128;
    int tid = threadIdx.x, w = tid >> 5, lane = tid & 31;
    int wm = (w & 1) * 64, wn = (w >> 1) * 32;
    int gr = lane >> 2, gc = lane & 3;

    const float* Ag = s1 + (size_t)b * C * HW;
    const float* Bg = s2 + (size_t)b * C * HW;
    uint32_t sbase = smem_u32(dyn);

    int rowv[4], colA[4], colB[4];
    #pragma unroll
    for (int t = 0; t < 4; t++) {
        int v = tid + t * 256;
        rowv[t] = v >> 5;
        int col = (v & 31) * 4;
        int ca = m0 + col; if (ca > HW - 4) ca = HW - 4;
        int cb = n0 + col; if (cb > HW - 4) cb = HW - 4;
        colA[t] = ca; colB[t] = cb;
    }
    auto issue_chunk = [&](int s) {
        int k0 = s * KC;
        uint32_t sA = sbase + (s % NSTG) * (SSTRIDE * 4);
        uint32_t sB = sA + MATW * 4;
        #pragma unroll
        for (int t = 0; t < 4; t++) {
            int v = tid + t * 256;
            uint32_t so = ((v >> 5) * LDW + (v & 31) * 4) * 4;
            CP_A16(sA + so, (const char*)&Ag[(size_t)(k0 + rowv[t]) * HW + colA[t]]);
            CP_A16(sB + so, (const char*)&Bg[(size_t)(k0 + rowv[t]) * HW + colB[t]]);
        }
        CP_COMMIT();
    };

    float acc[4][4][4] = {};
    issue_chunk(0);
    issue_chunk(1);
    for (int s = 0; s < NCH; s++) {
        if (s < NCH - 1) CP_WAIT1(); else CP_WAIT0();
        __syncthreads();
        if (s + 2 < NCH) issue_chunk(s + 2);
        const uint32_t* As = dyn + (s % NSTG) * SSTRIDE;
        const uint32_t* Bs = As + MATW;
        #pragma unroll
        for (int ks = 0; ks < KC; ks += 8) FRAG_MMA(As, Bs, ks)
    }
    __syncthreads();

    // ---- fused argmin epilogue ----
    ull* rkey = (ull*)dyn;
    ull* ckey = rkey + 128;
    if (tid < 128) { rkey[tid] = ~0ull; ckey[tid] = ~0ull; }
    __syncthreads();

    const float* a2p = g_a2 + b * HW;
    const float* b2p = g_b2 + b * HW;

    #pragma unroll
    for (int i = 0; i < 4; i++) {
        int mbase = wm + (i >> 1) * 32 + gr * 4 + (i & 1) * 2;
        #pragma unroll
        for (int half = 0; half < 2; half++) {
            int ml = mbase + half;
            ull rb_ = ~0ull;
            #pragma unroll
            for (int j = 0; j < 4; j++)
                #pragma unroll
                for (int rb = 0; rb < 2; rb++) {
                    int n_g = n0 + wn + 8 * gc + 4 * rb + j;
                    if (n_g < HW) {
                        ull k = enc_key(b2p[n_g] - 2.f * acc[i][j][half * 2 + rb], n_g);
                        if (k < rb_) rb_ = k;
                    }
                }
            if (rb_ != ~0ull) atomicMin(&rkey[ml], rb_);
        }
    }
    #pragma unroll
    for (int j = 0; j < 4; j++)
        #pragma unroll
        for (int rb = 0; rb < 2; rb++) {
            int nl = wn + 8 * gc + 4 * rb + j;
            ull cbest = ~0ull;
            #pragma unroll
            for (int i = 0; i < 4; i++) {
                int mbase = m0 + wm + (i >> 1) * 32 + gr * 4 + (i & 1) * 2;
                #pragma unroll
                for (int half = 0; half < 2; half++) {
                    int m_g = mbase + half;
                    if (m_g < HW) {
                        ull k = enc_key(a2p[m_g] - 2.f * acc[i][j][half * 2 + rb], m_g);
                        if (k < cbest) cbest = k;
                    }
                }
            }
            if (cbest != ~0ull) atomicMin(&ckey[nl], cbest);
        }
    __syncthreads();
    if (tid < 128) {
        int m = m0 + tid;
        if (m < HW) atomicMin(&g_key[0][b * HW + m], rkey[tid]);
    } else {
        int n = n0 + tid - 128;
        if (n < HW) atomicMin(&g_key[1][b * HW + n], ckey[tid - 128]);
    }
}

// ---- tf32 MMA Gram for the 4 big X tensors: S[t] = X^T X, upper 128x128 tiles ----
__global__ void __launch_bounds__(256, 2) k_gram_mma() {
    extern __shared__ uint32_t dyn[];
    int t = blockIdx.y;
    const float* X = g_X[t];
    int idx = blockIdx.x, ti = 0;
    while (idx >= 6 - ti) { idx -= 6 - ti; ti++; }
    int tj = ti + idx;
    int i0 = ti * 128, j0 = tj * 128;

    int tid = threadIdx.x, w = tid >> 5, lane = tid & 31;
    int wm = (w & 1) * 64, wn = (w >> 1) * 32;
    int gr = lane >> 2, gc = lane & 3;
    uint32_t sbase = smem_u32(dyn);

    auto issue_chunk = [&](int s) {
        int k0 = s * KC;
        uint32_t sA = sbase + (s % NSTG) * (SSTRIDE * 4);
        uint32_t sB = sA + MATW * 4;
        #pragma unroll
        for (int tt = 0; tt < 4; tt++) {
            int v = tid + tt * 256;
            int row = v >> 5, col = (v & 31) * 4;
            uint32_t so = (row * LDW + col) * 4;
            CP_A16(sA + so, (const char*)&X[(size_t)(k0 + row) * C + i0 + col]);
            CP_A16(sB + so, (const char*)&X[(size_t)(k0 + row) * C + j0 + col]);
        }
        CP_COMMIT();
    };

    float acc[4][4][4] = {};
    issue_chunk(0);
    issue_chunk(1);
    for (int s = 0; s < NCH2; s++) {
        if (s < NCH2 - 1) CP_WAIT1(); else CP_WAIT0();
        __syncthreads();
        if (s + 2 < NCH2) issue_chunk(s + 2);
        const uint32_t* As = dyn + (s % NSTG) * SSTRIDE;
        const uint32_t* Bs = As + MATW;
        #pragma unroll
        for (int ks = 0; ks < KC; ks += 8) FRAG_MMA(As, Bs, ks)
    }

    // epilogue: j is contiguous in n -> float4 stores
    float* Sp = g_S[t];
    #pragma unroll
    for (int i = 0; i < 4; i++) {
        int mbase = i0 + wm + (i >> 1) * 32 + gr * 4 + (i & 1) * 2;
        #pragma unroll
        for (int half = 0; half < 2; half++)
            #pragma unroll
            for (int rb = 0; rb < 2; rb++) {
                int c2 = j0 + wn + 8 * gc + 4 * rb;
                float4 o = make_float4(acc[i][0][half * 2 + rb], acc[i][1][half * 2 + rb],
                                       acc[i][2][half * 2 + rb], acc[i][3][half * 2 + rb]);
                *(float4*)&Sp[(size_t)(mbase + half) * C + c2] = o;
            }
    }
}

// rank-based top-50 smallest d2 (ties -> lowest index)
__global__ void k_select() {
    int b = blockIdx.x, dir = blockIdx.y;
    __shared__ float sd[HW];
    __shared__ int   sn[HW];
    int i = threadIdx.x;
    ull key = g_key[dir][b * HW + i];
    const float* own = dir ? g_b2 : g_a2;
    float d2 = own[b * HW + i] + dec_val(key);
    if (d2 < 0.f) d2 = 0.f;
    sd[i] = d2;
    sn[i] = (int)(uint32_t)key;
    __syncthreads();
    float di = sd[i];
    int rank = 0;
    for (int j = 0; j < HW; j++) {
        float dj = sd[j];
        rank += (dj < di) || (dj == di && j < i);
    }
    if (rank < NM) {
        g_sel_in[dir][b * NM + rank] = i;
        g_sel_c [dir][b * NM + rank] = sn[i];
    }
}

__global__ void k_gather(const float* __restrict__ s1, const float* __restrict__ s2) {
    int k = blockIdx.x, b = blockIdx.y, dir = blockIdx.z;
    const float* srcin = dir ? s2 : s1;
    const float* srcc  = dir ? s1 : s2;
    int pin = g_sel_in[dir][b * NM + k];
    int pc  = g_sel_c [dir][b * NM + k];
    float* Xin = g_X[dir * 2 + 0];
    float* Xc  = g_X[dir * 2 + 1];
    int row = b * NM + k;
    float lsum = 0.f;
    for (int c = threadIdx.x; c < C; c += 256) {
        float vi = srcin[((size_t)b * C + c) * HW + pin];
        float vc = srcc [((size_t)b * C + c) * HW + pc];
        Xin[(size_t)row * C + c] = vi;
        Xc [(size_t)row * C + c] = vc;
        float d = vi - vc; lsum += d * d;
    }
    float tot = blockReduceSum(lsum);
    if (threadIdx.x == 0) atomicAdd(&g_acc[1 + dir], (double)tot);
}

__global__ void k_pooled_inv(const float* __restrict__ p1, const float* __restrict__ p2) {
    float lsum = 0.f;
    for (int i = blockIdx.x * blockDim.x + threadIdx.x; i < B * C; i += gridDim.x * blockDim.x) {
        float d = p1[i] - p2[i]; lsum += d * d;
    }
    float tot = blockReduceSum(lsum);
    if (threadIdx.x == 0) atomicAdd(&g_acc[0], (double)tot);
}

__device__ __forceinline__ const float* tensor_ptr(int t, const float* p1, const float* p2) {
    if (t < 4) return g_X[t];
    return (t == 4) ? p1 : p2;
}
__device__ __forceinline__ int tensor_n(int t) { return (t < 4) ? NSEL : B; }

__global__ void k_colsum_part(const float* __restrict__ p1, const float* __restrict__ p2) {
    int t = blockIdx.x, chunk = blockIdx.y, c = threadIdx.x;
    const float* X = tensor_ptr(t, p1, p2);
    int n = tensor_n(t);
    int step = n / 16;
    int n0 = chunk * step, n1 = n0 + step;
    float s = 0.f;
    for (int i = n0; i < n1; i++) s += X[(size_t)i * C + c];
    g_csp[t][chunk][c] = s;
}
__global__ void k_colsum_fin() {
    int t = blockIdx.x, c = threadIdx.x;
    float s = 0.f;
    #pragma unroll
    for (int k = 0; k < 16; k++) s += g_csp[t][k][c];
    g_colsum[t][c] = s;
}

// exact fp32 Gram for the 2 pooled tensors (n=64), upper 64x64 tiles
__global__ void __launch_bounds__(256) k_gram(const float* __restrict__ p1,
                                              const float* __restrict__ p2) {
    int t = 4 + blockIdx.y;
    const float* X = tensor_ptr(t, p1, p2);
    int n = tensor_n(t);
    int idx = blockIdx.x, ti = 0;
    while (idx >= 12 - ti) { idx -= 12 - ti; ti++; }
    int tj = ti + idx;
    int i0 = ti * 64, j0 = tj * 64;

    __shared__ float As[16][64], Bs[16][64];
    int tid = threadIdx.x;
    int tx = tid & 15, ty = tid >> 4;
    int lk = tid >> 4, lo = (tid & 15) * 4;
    float acc[4][4] = {};
    for (int k0 = 0; k0 < n; k0 += 16) {
        *(float4*)&As[lk][lo] = *(const float4*)&X[(size_t)(k0 + lk) * C + i0 + lo];
        *(float4*)&Bs[lk][lo] = *(const float4*)&X[(size_t)(k0 + lk) * C + j0 + lo];
        __syncthreads();
        #pragma unroll
        for (int kk = 0; kk < 16; kk++) {
            float a[4], bb[4];
            *(float4*)a  = *(float4*)&As[kk][ty * 4];
            *(float4*)bb = *(float4*)&Bs[kk][tx * 4];
            #pragma unroll
            for (int i = 0; i < 4; i++)
                #pragma unroll
                for (int j = 0; j < 4; j++) acc[i][j] += a[i] * bb[j];
        }
        __syncthreads();
    }
    float* Sp = g_S[t];
    #pragma unroll
    for (int i = 0; i < 4; i++) {
        int c1 = i0 + ty * 4 + i;
        *(float4*)&Sp[(size_t)c1 * C + j0 + tx * 4] = *(float4*)acc[i];
    }
}

__global__ void k_std() {
    int t = blockIdx.x, c = threadIdx.x;
    float n  = (float)tensor_n(t);
    float mu = g_colsum[t][c] / n;
    float Scc = g_S[t][(size_t)c * C + c];
    float var = (Scc - n * mu * mu) / (n - 1.f);
    float sd  = sqrtf(var + EPSV);
    float contrib = fmaxf(1.f - sd, 0.f);
    float tot = blockReduceSum(contrib);
    if (threadIdx.x == 0) atomicAdd(&g_acc[3 + t], (double)tot);
}

__global__ void k_cov() {
    int t = blockIdx.y;
    float n = (float)tensor_n(t);
    float inv_nm1 = 1.f / (n - 1.f);
    int idx = blockIdx.x, ti = 0;
    while (idx >= 12 - ti) { idx -= 12 - ti; ti++; }
    int tj = ti + idx;
    int i0 = ti * 64, j0 = tj * 64;
    const float* Sp = g_S[t];
    float lsum = 0.f;
    #pragma unroll
    for (int it = 0; it < 16; it++) {
        int e = it * 256 + threadIdx.x;
        int r = e >> 6, cc = e & 63;
        int c1 = i0 + r, c2 = j0 + cc;
        if (c2 > c1) {
            float mu1 = g_colsum[t][c1] / n;
            float mu2 = g_colsum[t][c2] / n;
            float cov = (Sp[(size_t)c1 * C + c2] - n * mu1 * mu2) * inv_nm1;
            lsum += 2.f * cov * cov;
        }
    }
    float tot = blockReduceSum(lsum);
    if (threadIdx.x == 0) atomicAdd(&g_acc[10 + t], (double)tot);
}

__global__ void k_final(float* __restrict__ out) {
    double inv_g = g_acc[0] / (double)(B * C);
    double inv1  = g_acc[1] / (double)((size_t)NSEL * C);
    double inv2  = g_acc[2] / (double)((size_t)NSEL * C);
    double stdt[6], covt[6];
    for (int t = 0; t < 6; t++) {
        stdt[t] = (g_acc[3 + t] / (double)C) * 0.5;
        covt[t] = g_acc[10 + t] / (double)C;
    }
    double glob = 25.0 * inv_g + 25.0 * (stdt[4] + stdt[5]) + (covt[4] + covt[5]);
    double loc  = 0.5 * (25.0 * inv1 + 25.0 * inv2)
                + 0.5 * (25.0 * (stdt[0] + stdt[1]) + 25.0 * (stdt[2] + stdt[3]))
                + 0.5 * ((covt[0] + covt[1]) + (covt[2] + covt[3]));
    out[0] = (float)(0.5 * glob + 0.5 * loc);
}

// ---------------- launch ----------------
extern "C" void kernel_launch(void* const* d_in, const int* in_sizes, int n_in,
                              void* d_out, int out_size) {
    const float* s1 = (const float*)d_in[0];
    const float* p1 = (const float*)d_in[1];
    const float* s2 = (const float*)d_in[2];
    const float* p2 = (const float*)d_in[3];
    float* out = (float*)d_out;

    cudaFuncSetAttribute(k_gemm_fused, cudaFuncAttributeMaxDynamicSharedMemorySize, GSMEM);
    cudaFuncSetAttribute(k_gram_mma,   cudaFuncAttributeMaxDynamicSharedMemorySize, GSMEM);

    k_init<<<1, 32>>>();
    k_keyinit<<<(2 * B * HW + 255) / 256, 256>>>();
    k_norms<<<dim3(B, 2), HW>>>(s1, s2);
    k_gemm_fused<<<dim3(5, 5, B), 256, GSMEM>>>(s1, s2);
    k_select<<<dim3(B, 2), HW>>>();
    k_gather<<<dim3(NM, B, 2), 256>>>(s1, s2);
    k_pooled_inv<<<48, 256>>>(p1, p2);
    k_colsum_part<<<dim3(6, 16), C>>>(p1, p2);
    k_colsum_fin<<<6, C>>>();
    k_gram_mma<<<dim3(21, 4), 256, GSMEM>>>();
    k_gram<<<dim3(78, 2), 256>>>(p1, p2);
    k_std<<<6, C>>>();
    k_cov<<<dim3(78, 6), 256>>>();
    k_final<<<1, 1>>>(out);
}

// round 9
// speedup vs baseline: 1.1515x; 1.1515x over previous
#include <cuda_runtime.h>
#include <cstdint>
#include <math.h>

#define B    64
#define C    768
#define HW   576
#define NM   50
#define NSEL (B*NM)   // 3200
#define EPSV 1e-5f
#define KC   32
#define NCH  (C/KC)    // 24
#define NCH2 (NSEL/KC) // 100

typedef unsigned long long ull;

// ---------------- scratch ----------------
__device__ float  g_a2[B*HW], g_b2[B*HW];
__device__ ull    g_key[2][B*HW];
__device__ int    g_sel_in[2][NSEL];
__device__ int    g_sel_c [2][NSEL];
__device__ float  g_X[4][(size_t)NSEL*C];
__device__ float  g_S[6][(size_t)C*C];
__device__ float  g_csp[6][16][C];
__device__ float  g_colsum[6][C];
__device__ double g_acc[32];

// ---------------- helpers ----------------
__device__ __forceinline__ void mma_bf16(float c[4],
                                         uint32_t a0, uint32_t a1, uint32_t a2, uint32_t a3,
                                         uint32_t b0, uint32_t b1) {
    asm volatile(
        "mma.sync.aligned.m16n8k16.row.col.f32.bf16.bf16.f32 "
        "{%0,%1,%2,%3}, {%4,%5,%6,%7}, {%8,%9}, {%0,%1,%2,%3};"
        : "+f"(c[0]), "+f"(c[1]), "+f"(c[2]), "+f"(c[3])
        : "r"(a0), "r"(a1), "r"(a2), "r"(a3), "r"(b0), "r"(b1));
}
// pack two f32 -> bf16x2 (lo in low half, hi in high half), round-to-nearest
__device__ __forceinline__ uint32_t packbf(float lo, float hi) {
    uint32_t r;
    asm("cvt.rn.bf16x2.f32 %0, %1, %2;" : "=r"(r) : "f"(hi), "f"(lo));
    return r;
}
#define F(u) __uint_as_float(u)

#define CP_A16(d, s) asm volatile("cp.async.ca.shared.global [%0], [%1], 16;" :: "r"(d), "l"(s))
#define CP_COMMIT()  asm volatile("cp.async.commit_group;" ::: "memory")
#define CP_WAIT1()   asm volatile("cp.async.wait_group 1;" ::: "memory")
#define CP_WAIT0()   asm volatile("cp.async.wait_group 0;" ::: "memory")

__device__ __forceinline__ uint32_t smem_u32(const void* p) {
    uint32_t a;
    asm("{ .reg .u64 t; cvta.to.shared.u64 t, %1; cvt.u32.u64 %0, t; }" : "=r"(a) : "l"(p));
    return a;
}
__device__ __forceinline__ ull enc_key(float f, int idx) {
    uint32_t u = __float_as_uint(f);
    u = (u & 0x80000000u) ? ~u : (u | 0x80000000u);
    return ((ull)u << 32) | (uint32_t)idx;
}
__device__ __forceinline__ float dec_val(ull k) {
    uint32_t e = (uint32_t)(k >> 32);
    uint32_t u = (e & 0x80000000u) ? (e ^ 0x80000000u) : ~e;
    return __uint_as_float(u);
}

__device__ __forceinline__ float blockReduceSum(float v) {
    __shared__ float sw[32];
    int lane = threadIdx.x & 31, w = threadIdx.x >> 5;
    #pragma unroll
    for (int o = 16; o; o >>= 1) v += __shfl_xor_sync(~0u, v, o);
    if (lane == 0) sw[w] = v;
    __syncthreads();
    int nw = (blockDim.x + 31) >> 5;
    v = (threadIdx.x < nw) ? sw[threadIdx.x] : 0.f;
    if (w == 0) {
        #pragma unroll
        for (int o = 16; o; o >>= 1) v += __shfl_xor_sync(~0u, v, o);
    }
    return v;
}

// ---------------- kernels ----------------
__global__ void k_init() { if (threadIdx.x < 32) g_acc[threadIdx.x] = 0.0; }
__global__ void k_keyinit() {
    int i = blockIdx.x * blockDim.x + threadIdx.x;
    if (i < 2 * B * HW) ((ull*)g_key)[i] = ~0ull;
}

__global__ void k_norms(const float* __restrict__ s1, const float* __restrict__ s2) {
    int b = blockIdx.x, p = threadIdx.x;
    const float* src = blockIdx.y ? s2 : s1;
    float*       dst = blockIdx.y ? g_b2 : g_a2;
    const float* base = src + (size_t)b * C * HW + p;
    float s = 0.f;
    #pragma unroll 8
    for (int c = 0; c < C; c++) { float v = base[(size_t)c * HW]; s += v * v; }
    dst[b * HW + p] = s;
}

// LDW=132: fragment rows kb+2gc(+1,+8,+9); 2*132*gc + 4*gr distinct mod 32 -> conflict-free
#define LDW     132
#define MATW    (32*LDW)
#define SSTRIDE (2*MATW)          // u32 per stage
#define GSMEM   (2 * SSTRIDE * 4) // 67584 B

// bf16 k16 step: pack f32 smem pairs -> bf16x2 fragments, 16 HMMAs.
// remap (same as tf32 version): A frag (i,half) <-> m = wm+(i>>1)*32+gr*4+(i&1)*2+half
//                               B frag j, reg rb <-> n = wn+8*gc+4*rb+j
#define FRAG_MMA16(As, Bs, kb)                                                      \
    {                                                                               \
        uint4 w0 = *(const uint4*)&Bs[(kb + 2*gc    ) * LDW + wn + gr * 4];         \
        uint4 w1 = *(const uint4*)&Bs[(kb + 2*gc + 1) * LDW + wn + gr * 4];         \
        uint4 w2 = *(const uint4*)&Bs[(kb + 2*gc + 8) * LDW + wn + gr * 4];         \
        uint4 w3 = *(const uint4*)&Bs[(kb + 2*gc + 9) * LDW + wn + gr * 4];         \
        uint32_t bx0 = packbf(F(w0.x), F(w1.x)), bx1 = packbf(F(w2.x), F(w3.x));    \
        uint32_t by0 = packbf(F(w0.y), F(w1.y)), by1 = packbf(F(w2.y), F(w3.y));    \
        uint32_t bz0 = packbf(F(w0.z), F(w1.z)), bz1 = packbf(F(w2.z), F(w3.z));    \
        uint32_t bw0 = packbf(F(w0.w), F(w1.w)), bw1 = packbf(F(w2.w), F(w3.w));    \
        uint4 u0 = *(const uint4*)&As[(kb + 2*gc    ) * LDW + wm + gr * 4];         \
        uint4 u1 = *(const uint4*)&As[(kb + 2*gc + 1) * LDW + wm + gr * 4];         \
        uint4 u2 = *(const uint4*)&As[(kb + 2*gc + 8) * LDW + wm + gr * 4];         \
        uint4 u3 = *(const uint4*)&As[(kb + 2*gc + 9) * LDW + wm + gr * 4];         \
        {                                                                           \
            uint32_t a0 = packbf(F(u0.x), F(u1.x)), a1 = packbf(F(u0.y), F(u1.y));  \
            uint32_t a2 = packbf(F(u2.x), F(u3.x)), a3 = packbf(F(u2.y), F(u3.y));  \
            mma_bf16(acc[0][0], a0, a1, a2, a3, bx0, bx1);                          \
            mma_bf16(acc[0][1], a0, a1, a2, a3, by0, by1);                          \
            mma_bf16(acc[0][2], a0, a1, a2, a3, bz0, bz1);                          \
            mma_bf16(acc[0][3], a0, a1, a2, a3, bw0, bw1);                          \
        }                                                                           \
        {                                                                           \
            uint32_t a0 = packbf(F(u0.z), F(u1.z)), a1 = packbf(F(u0.w), F(u1.w));  \
            uint32_t a2 = packbf(F(u2.z), F(u3.z)), a3 = packbf(F(u2.w), F(u3.w));  \
            mma_bf16(acc[1][0], a0, a1, a2, a3, bx0, bx1);                          \
            mma_bf16(acc[1][1], a0, a1, a2, a3, by0, by1);                          \
            mma_bf16(acc[1][2], a0, a1, a2, a3, bz0, bz1);                          \
            mma_bf16(acc[1][3], a0, a1, a2, a3, bw0, bw1);                          \
        }                                                                           \
        u0 = *(const uint4*)&As[(kb + 2*gc    ) * LDW + wm + 32 + gr * 4];          \
        u1 = *(const uint4*)&As[(kb + 2*gc + 1) * LDW + wm + 32 + gr * 4];          \
        u2 = *(const uint4*)&As[(kb + 2*gc + 8) * LDW + wm + 32 + gr * 4];          \
        u3 = *(const uint4*)&As[(kb + 2*gc + 9) * LDW + wm + 32 + gr * 4];          \
        {                                                                           \
            uint32_t a0 = packbf(F(u0.x), F(u1.x)), a1 = packbf(F(u0.y), F(u1.y));  \
            uint32_t a2 = packbf(F(u2.x), F(u3.x)), a3 = packbf(F(u2.y), F(u3.y));  \
            mma_bf16(acc[2][0], a0, a1, a2, a3, bx0, bx1);                          \
            mma_bf16(acc[2][1], a0, a1, a2, a3, by0, by1);                          \
            mma_bf16(acc[2][2], a0, a1, a2, a3, bz0, bz1);                          \
            mma_bf16(acc[2][3], a0, a1, a2, a3, bw0, bw1);                          \
        }                                                                           \
        {                                                                           \
            uint32_t a0 = packbf(F(u0.z), F(u1.z)), a1 = packbf(F(u0.w), F(u1.w));  \
            uint32_t a2 = packbf(F(u2.z), F(u3.z)), a3 = packbf(F(u2.w), F(u3.w));  \
            mma_bf16(acc[3][0], a0, a1, a2, a3, bx0, bx1);                          \
            mma_bf16(acc[3][1], a0, a1, a2, a3, by0, by1);                          \
            mma_bf16(acc[3][2], a0, a1, a2, a3, bz0, bz1);                          \
            mma_bf16(acc[3][3], a0, a1, a2, a3, bw0, bw1);                          \
        }                                                                           \
    }

// ---- fused bf16 GEMM + row/col argmin. CTA 128x128, 8 warps (2m x 4n), 2-stage ----
__global__ void __launch_bounds__(256, 2) k_gemm_fused(const float* __restrict__ s1,
                                                       const float* __restrict__ s2) {
    extern __shared__ uint32_t dyn[];
    int b  = blockIdx.z;
    int m0 = blockIdx.y * 128, n0 = blockIdx.x * 128;
    int tid = threadIdx.x, w = tid >> 5, lane = tid & 31;
    int wm = (w & 1) * 64, wn = (w >> 1) * 32;
    int gr = lane >> 2, gc = lane & 3;

    const float* Ag = s1 + (size_t)b * C * HW;
    const float* Bg = s2 + (size_t)b * C * HW;
    uint32_t sbase = smem_u32(dyn);

    int rowv[4], colA[4], colB[4];
    #pragma unroll
    for (int t = 0; t < 4; t++) {
        int v = tid + t * 256;
        rowv[t] = v >> 5;
        int col = (v & 31) * 4;
        int ca = m0 + col; if (ca > HW - 4) ca = HW - 4;
        int cb = n0 + col; if (cb > HW - 4) cb = HW - 4;
        colA[t] = ca; colB[t] = cb;
    }
    auto issue_chunk = [&](int s, int stage) {
        int k0 = s * KC;
        uint32_t sA = sbase + stage * (SSTRIDE * 4);
        uint32_t sB = sA + MATW * 4;
        #pragma unroll
        for (int t = 0; t < 4; t++) {
            int v = tid + t * 256;
            uint32_t so = ((v >> 5) * LDW + (v & 31) * 4) * 4;
            CP_A16(sA + so, (const char*)&Ag[(size_t)(k0 + rowv[t]) * HW + colA[t]]);
            CP_A16(sB + so, (const char*)&Bg[(size_t)(k0 + rowv[t]) * HW + colB[t]]);
        }
        CP_COMMIT();
    };

    float acc[4][4][4] = {};
    issue_chunk(0, 0);
    for (int s = 0; s < NCH; s++) {
        if (s + 1 < NCH) { issue_chunk(s + 1, (s + 1) & 1); CP_WAIT1(); }
        else             { CP_WAIT0(); }
        __syncthreads();
        const uint32_t* As = dyn + (s & 1) * SSTRIDE;
        const uint32_t* Bs = As + MATW;
        FRAG_MMA16(As, Bs, 0)
        FRAG_MMA16(As, Bs, 16)
        __syncthreads();
    }

    // ---- fused argmin epilogue ----
    ull* rkey = (ull*)dyn;
    ull* ckey = rkey + 128;
    if (tid < 128) { rkey[tid] = ~0ull; ckey[tid] = ~0ull; }
    __syncthreads();

    const float* a2p = g_a2 + b * HW;
    const float* b2p = g_b2 + b * HW;

    #pragma unroll
    for (int i = 0; i < 4; i++) {
        int mbase = wm + (i >> 1) * 32 + gr * 4 + (i & 1) * 2;
        #pragma unroll
        for (int half = 0; half < 2; half++) {
            int ml = mbase + half;
            ull rb_ = ~0ull;
            #pragma unroll
            for (int j = 0; j < 4; j++)
                #pragma unroll
                for (int rb = 0; rb < 2; rb++) {
                    int n_g = n0 + wn + 8 * gc + 4 * rb + j;
                    if (n_g < HW) {
                        ull k = enc_key(b2p[n_g] - 2.f * acc[i][j][half * 2 + rb], n_g);
                        if (k < rb_) rb_ = k;
                    }
                }
            if (rb_ != ~0ull) atomicMin(&rkey[ml], rb_);
        }
    }
    #pragma unroll
    for (int j = 0; j < 4; j++)
        #pragma unroll
        for (int rb = 0; rb < 2; rb++) {
            int nl = wn + 8 * gc + 4 * rb + j;
            ull cbest = ~0ull;
            #pragma unroll
            for (int i = 0; i < 4; i++) {
                int mbase = m0 + wm + (i >> 1) * 32 + gr * 4 + (i & 1) * 2;
                #pragma unroll
                for (int half = 0; half < 2; half++) {
                    int m_g = mbase + half;
                    if (m_g < HW) {
                        ull k = enc_key(a2p[m_g] - 2.f * acc[i][j][half * 2 + rb], m_g);
                        if (k < cbest) cbest = k;
                    }
                }
            }
            if (cbest != ~0ull) atomicMin(&ckey[nl], cbest);
        }
    __syncthreads();
    if (tid < 128) {
        int m = m0 + tid;
        if (m < HW) atomicMin(&g_key[0][b * HW + m], rkey[tid]);
    } else {
        int n = n0 + tid - 128;
        if (n < HW) atomicMin(&g_key[1][b * HW + n], ckey[tid - 128]);
    }
}

// ---- bf16 MMA Gram for the 4 big X tensors: S[t] = X^T X, upper 128x128 tiles ----
__global__ void __launch_bounds__(256, 2) k_gram_mma() {
    extern __shared__ uint32_t dyn[];
    int t = blockIdx.y;
    const float* X = g_X[t];
    int idx = blockIdx.x, ti = 0;
    while (idx >= 6 - ti) { idx -= 6 - ti; ti++; }
    int tj = ti + idx;
    int i0 = ti * 128, j0 = tj * 128;

    int tid = threadIdx.x, w = tid >> 5, lane = tid & 31;
    int wm = (w & 1) * 64, wn = (w >> 1) * 32;
    int gr = lane >> 2, gc = lane & 3;
    uint32_t sbase = smem_u32(dyn);

    auto issue_chunk = [&](int s, int stage) {
        int k0 = s * KC;
        uint32_t sA = sbase + stage * (SSTRIDE * 4);
        uint32_t sB = sA + MATW * 4;
        #pragma unroll
        for (int tt = 0; tt < 4; tt++) {
            int v = tid + tt * 256;
            int row = v >> 5, col = (v & 31) * 4;
            uint32_t so = (row * LDW + col) * 4;
            CP_A16(sA + so, (const char*)&X[(size_t)(k0 + row) * C + i0 + col]);
            CP_A16(sB + so, (const char*)&X[(size_t)(k0 + row) * C + j0 + col]);
        }
        CP_COMMIT();
    };

    float acc[4][4][4] = {};
    issue_chunk(0, 0);
    for (int s = 0; s < NCH2; s++) {
        if (s + 1 < NCH2) { issue_chunk(s + 1, (s + 1) & 1); CP_WAIT1(); }
        else              { CP_WAIT0(); }
        __syncthreads();
        const uint32_t* As = dyn + (s & 1) * SSTRIDE;
        const uint32_t* Bs = As + MATW;
        FRAG_MMA16(As, Bs, 0)
        FRAG_MMA16(As, Bs, 16)
        __syncthreads();
    }

    // epilogue: j contiguous in n -> float4 stores
    float* Sp = g_S[t];
    #pragma unroll
    for (int i = 0; i < 4; i++) {
        int mbase = i0 + wm + (i >> 1) * 32 + gr * 4 + (i & 1) * 2;
        #pragma unroll
        for (int half = 0; half < 2; half++)
            #pragma unroll
            for (int rb = 0; rb < 2; rb++) {
                int c2 = j0 + wn + 8 * gc + 4 * rb;
                float4 o = make_float4(acc[i][0][half * 2 + rb], acc[i][1][half * 2 + rb],
                                       acc[i][2][half * 2 + rb], acc[i][3][half * 2 + rb]);
                *(float4*)&Sp[(size_t)(mbase + half) * C + c2] = o;
            }
    }
}

// rank-based top-50 smallest d2 (ties -> lowest index)
__global__ void k_select() {
    int b = blockIdx.x, dir = blockIdx.y;
    __shared__ float sd[HW];
    __shared__ int   sn[HW];
    int i = threadIdx.x;
    ull key = g_key[dir][b * HW + i];
    const float* own = dir ? g_b2 : g_a2;
    float d2 = own[b * HW + i] + dec_val(key);
    if (d2 < 0.f) d2 = 0.f;
    sd[i] = d2;
    sn[i] = (int)(uint32_t)key;
    __syncthreads();
    float di = sd[i];
    int rank = 0;
    for (int j = 0; j < HW; j++) {
        float dj = sd[j];
        rank += (dj < di) || (dj == di && j < i);
    }
    if (rank < NM) {
        g_sel_in[dir][b * NM + rank] = i;
        g_sel_c [dir][b * NM + rank] = sn[i];
    }
}

__global__ void k_gather(const float* __restrict__ s1, const float* __restrict__ s2) {
    int k = blockIdx.x, b = blockIdx.y, dir = blockIdx.z;
    const float* srcin = dir ? s2 : s1;
    const float* srcc  = dir ? s1 : s2;
    int pin = g_sel_in[dir][b * NM + k];
    int pc  = g_sel_c [dir][b * NM + k];
    float* Xin = g_X[dir * 2 + 0];
    float* Xc  = g_X[dir * 2 + 1];
    int row = b * NM + k;
    float lsum = 0.f;
    for (int c = threadIdx.x; c < C; c += 256) {
        float vi = srcin[((size_t)b * C + c) * HW + pin];
        float vc = srcc [((size_t)b * C + c) * HW + pc];
        Xin[(size_t)row * C + c] = vi;
        Xc [(size_t)row * C + c] = vc;
        float d = vi - vc; lsum += d * d;
    }
    float tot = blockReduceSum(lsum);
    if (threadIdx.x == 0) atomicAdd(&g_acc[1 + dir], (double)tot);
}

__global__ void k_pooled_inv(const float* __restrict__ p1, const float* __restrict__ p2) {
    float lsum = 0.f;
    for (int i = blockIdx.x * blockDim.x + threadIdx.x; i < B * C; i += gridDim.x * blockDim.x) {
        float d = p1[i] - p2[i]; lsum += d * d;
    }
    float tot = blockReduceSum(lsum);
    if (threadIdx.x == 0) atomicAdd(&g_acc[0], (double)tot);
}

__device__ __forceinline__ const float* tensor_ptr(int t, const float* p1, const float* p2) {
    if (t < 4) return g_X[t];
    return (t == 4) ? p1 : p2;
}
__device__ __forceinline__ int tensor_n(int t) { return (t < 4) ? NSEL : B; }

__global__ void k_colsum_part(const float* __restrict__ p1, const float* __restrict__ p2) {
    int t = blockIdx.x, chunk = blockIdx.y, c = threadIdx.x;
    const float* X = tensor_ptr(t, p1, p2);
    int n = tensor_n(t);
    int step = n / 16;
    int n0 = chunk * step, n1 = n0 + step;
    float s = 0.f;
    for (int i = n0; i < n1; i++) s += X[(size_t)i * C + c];
    g_csp[t][chunk][c] = s;
}
__global__ void k_colsum_fin() {
    int t = blockIdx.x, c = threadIdx.x;
    float s = 0.f;
    #pragma unroll
    for (int k = 0; k < 16; k++) s += g_csp[t][k][c];
    g_colsum[t][c] = s;
}

// exact fp32 Gram for the 2 pooled tensors (n=64), upper 64x64 tiles
__global__ void __launch_bounds__(256) k_gram(const float* __restrict__ p1,
                                              const float* __restrict__ p2) {
    int t = 4 + blockIdx.y;
    const float* X = tensor_ptr(t, p1, p2);
    int n = tensor_n(t);
    int idx = blockIdx.x, ti = 0;
    while (idx >= 12 - ti) { idx -= 12 - ti; ti++; }
    int tj = ti + idx;
    int i0 = ti * 64, j0 = tj * 64;

    __shared__ float As[16][64], Bs[16][64];
    int tid = threadIdx.x;
    int tx = tid & 15, ty = tid >> 4;
    int lk = tid >> 4, lo = (tid & 15) * 4;
    float acc[4][4] = {};
    for (int k0 = 0; k0 < n; k0 += 16) {
        *(float4*)&As[lk][lo] = *(const float4*)&X[(size_t)(k0 + lk) * C + i0 + lo];
        *(float4*)&Bs[lk][lo] = *(const float4*)&X[(size_t)(k0 + lk) * C + j0 + lo];
        __syncthreads();
        #pragma unroll
        for (int kk = 0; kk < 16; kk++) {
            float a[4], bb[4];
            *(float4*)a  = *(float4*)&As[kk][ty * 4];
            *(float4*)bb = *(float4*)&Bs[kk][tx * 4];
            #pragma unroll
            for (int i = 0; i < 4; i++)
                #pragma unroll
                for (int j = 0; j < 4; j++) acc[i][j] += a[i] * bb[j];
        }
        __syncthreads();
    }
    float* Sp = g_S[t];
    #pragma unroll
    for (int i = 0; i < 4; i++) {
        int c1 = i0 + ty * 4 + i;
        *(float4*)&Sp[(size_t)c1 * C + j0 + tx * 4] = *(float4*)acc[i];
    }
}

__global__ void k_std() {
    int t = blockIdx.x, c = threadIdx.x;
    float n  = (float)tensor_n(t);
    float mu = g_colsum[t][c] / n;
    float Scc = g_S[t][(size_t)c * C + c];
    float var = (Scc - n * mu * mu) / (n - 1.f);
    float sd  = sqrtf(var + EPSV);
    float contrib = fmaxf(1.f - sd, 0.f);
    float tot = blockReduceSum(contrib);
    if (threadIdx.x == 0) atomicAdd(&g_acc[3 + t], (double)tot);
}

__global__ void k_cov() {
    int t = blockIdx.y;
    float n = (float)tensor_n(t);
    float inv_nm1 = 1.f / (n - 1.f);
    int idx = blockIdx.x, ti = 0;
    while (idx >= 12 - ti) { idx -= 12 - ti; ti++; }
    int tj = ti + idx;
    int i0 = ti * 64, j0 = tj * 64;
    const float* Sp = g_S[t];
    float lsum = 0.f;
    #pragma unroll
    for (int it = 0; it < 16; it++) {
        int e = it * 256 + threadIdx.x;
        int r = e >> 6, cc = e & 63;
        int c1 = i0 + r, c2 = j0 + cc;
        if (c2 > c1) {
            float mu1 = g_colsum[t][c1] / n;
            float mu2 = g_colsum[t][c2] / n;
            float cov = (Sp[(size_t)c1 * C + c2] - n * mu1 * mu2) * inv_nm1;
            lsum += 2.f * cov * cov;
        }
    }
    float tot = blockReduceSum(lsum);
    if (threadIdx.x == 0) atomicAdd(&g_acc[10 + t], (double)tot);
}

__global__ void k_final(float* __restrict__ out) {
    double inv_g = g_acc[0] / (double)(B * C);
    double inv1  = g_acc[1] / (double)((size_t)NSEL * C);
    double inv2  = g_acc[2] / (double)((size_t)NSEL * C);
    double stdt[6], covt[6];
    for (int t = 0; t < 6; t++) {
        stdt[t] = (g_acc[3 + t] / (double)C) * 0.5;
        covt[t] = g_acc[10 + t] / (double)C;
    }
    double glob = 25.0 * inv_g + 25.0 * (stdt[4] + stdt[5]) + (covt[4] + covt[5]);
    double loc  = 0.5 * (25.0 * inv1 + 25.0 * inv2)
                + 0.5 * (25.0 * (stdt[0] + stdt[1]) + 25.0 * (stdt[2] + stdt[3]))
                + 0.5 * ((covt[0] + covt[1]) + (covt[2] + covt[3]));
    out[0] = (float)(0.5 * glob + 0.5 * loc);
}

// ---------------- launch ----------------
extern "C" void kernel_launch(void* const* d_in, const int* in_sizes, int n_in,
                              void* d_out, int out_size) {
    const float* s1 = (const float*)d_in[0];
    const float* p1 = (const float*)d_in[1];
    const float* s2 = (const float*)d_in[2];
    const float* p2 = (const float*)d_in[3];
    float* out = (float*)d_out;

    cudaFuncSetAttribute(k_gemm_fused, cudaFuncAttributeMaxDynamicSharedMemorySize, GSMEM);
    cudaFuncSetAttribute(k_gram_mma,   cudaFuncAttributeMaxDynamicSharedMemorySize, GSMEM);

    k_init<<<1, 32>>>();
    k_keyinit<<<(2 * B * HW + 255) / 256, 256>>>();
    k_norms<<<dim3(B, 2), HW>>>(s1, s2);
    k_gemm_fused<<<dim3(5, 5, B), 256, GSMEM>>>(s1, s2);
    k_select<<<dim3(B, 2), HW>>>();
    k_gather<<<dim3(NM, B, 2), 256>>>(s1, s2);
    k_pooled_inv<<<48, 256>>>(p1, p2);
    k_colsum_part<<<dim3(6, 16), C>>>(p1, p2);
    k_colsum_fin<<<6, C>>>();
    k_gram_mma<<<dim3(21, 4), 256, GSMEM>>>();
    k_gram<<<dim3(78, 2), 256>>>(p1, p2);
    k_std<<<6, C>>>();
    k_cov<<<dim3(78, 6), 256>>>();
    k_final<<<1, 1>>>(out);
}

// round 10
// speedup vs baseline: 1.3475x; 1.1702x over previous
#include <cuda_runtime.h>
#include <cstdint>
#include <math.h>

#define B    64
#define C    768
#define HW   576
#define NM   50
#define NSEL (B*NM)   // 3200
#define EPSV 1e-5f
#define KC   32
#define NCH  (C/KC)    // 24
#define NCH2 (NSEL/KC) // 100

typedef unsigned long long ull;

// ---------------- scratch ----------------
__device__ float    g_a2[B*HW], g_b2[B*HW];
__device__ ull      g_key[2][B*HW];
__device__ int      g_sel_in[2][NSEL];
__device__ int      g_sel_c [2][NSEL];
__device__ float    g_X[4][(size_t)NSEL*C];
__device__ uint32_t g_sbf[2][(size_t)B*(C/2)*HW];      // packed bf16x2 spatial [b][k2][m]
__device__ uint32_t g_Xbf[4][(size_t)(NSEL/2)*C];      // packed bf16x2 gathered [k2][c]
__device__ float    g_S[6][(size_t)C*C];
__device__ float    g_csp[6][16][C];
__device__ float    g_colsum[6][C];
__device__ double   g_acc[32];

// ---------------- helpers ----------------
__device__ __forceinline__ void mma_bf16(float c[4],
                                         uint32_t a0, uint32_t a1, uint32_t a2, uint32_t a3,
                                         uint32_t b0, uint32_t b1) {
    asm volatile(
        "mma.sync.aligned.m16n8k16.row.col.f32.bf16.bf16.f32 "
        "{%0,%1,%2,%3}, {%4,%5,%6,%7}, {%8,%9}, {%0,%1,%2,%3};"
        : "+f"(c[0]), "+f"(c[1]), "+f"(c[2]), "+f"(c[3])
        : "r"(a0), "r"(a1), "r"(a2), "r"(a3), "r"(b0), "r"(b1));
}
// pack two f32 -> bf16x2, lo in low half (RN)
__device__ __forceinline__ uint32_t packbf(float lo, float hi) {
    uint32_t r;
    asm("cvt.rn.bf16x2.f32 %0, %1, %2;" : "=r"(r) : "f"(hi), "f"(lo));
    return r;
}

#define CP_A16(d, s) asm volatile("cp.async.ca.shared.global [%0], [%1], 16;" :: "r"(d), "l"(s))
#define CP_COMMIT()  asm volatile("cp.async.commit_group;" ::: "memory")
#define CP_WAIT1()   asm volatile("cp.async.wait_group 1;" ::: "memory")
#define CP_WAIT0()   asm volatile("cp.async.wait_group 0;" ::: "memory")

__device__ __forceinline__ uint32_t smem_u32(const void* p) {
    uint32_t a;
    asm("{ .reg .u64 t; cvta.to.shared.u64 t, %1; cvt.u32.u64 %0, t; }" : "=r"(a) : "l"(p));
    return a;
}
__device__ __forceinline__ ull enc_key(float f, int idx) {
    uint32_t u = __float_as_uint(f);
    u = (u & 0x80000000u) ? ~u : (u | 0x80000000u);
    return ((ull)u << 32) | (uint32_t)idx;
}
__device__ __forceinline__ float dec_val(ull k) {
    uint32_t e = (uint32_t)(k >> 32);
    uint32_t u = (e & 0x80000000u) ? (e ^ 0x80000000u) : ~e;
    return __uint_as_float(u);
}

__device__ __forceinline__ float blockReduceSum(float v) {
    __shared__ float sw[32];
    int lane = threadIdx.x & 31, w = threadIdx.x >> 5;
    #pragma unroll
    for (int o = 16; o; o >>= 1) v += __shfl_xor_sync(~0u, v, o);
    if (lane == 0) sw[w] = v;
    __syncthreads();
    int nw = (blockDim.x + 31) >> 5;
    v = (threadIdx.x < nw) ? sw[threadIdx.x] : 0.f;
    if (w == 0) {
        #pragma unroll
        for (int o = 16; o; o >>= 1) v += __shfl_xor_sync(~0u, v, o);
    }
    return v;
}

// ---------------- small kernels ----------------
__global__ void k_init() { if (threadIdx.x < 32) g_acc[threadIdx.x] = 0.0; }
__global__ void k_keyinit() {
    int i = blockIdx.x * blockDim.x + threadIdx.x;
    if (i < 2 * B * HW) ((ull*)g_key)[i] = ~0ull;
}

__global__ void k_norms(const float* __restrict__ s1, const float* __restrict__ s2) {
    int b = blockIdx.x, p = threadIdx.x;
    const float* src = blockIdx.y ? s2 : s1;
    float*       dst = blockIdx.y ? g_b2 : g_a2;
    const float* base = src + (size_t)b * C * HW + p;
    float s = 0.f;
    #pragma unroll 8
    for (int c = 0; c < C; c++) { float v = base[(size_t)c * HW]; s += v * v; }
    dst[b * HW + p] = s;
}

// pack spatial f32 -> bf16x2 words [b][k2][m]; one uint4 (4 m's) per thread
#define SPACK_SLOTS ((C/2)*(HW/4))   // 55296 per batch
__global__ void k_pack_s(const float* __restrict__ s1, const float* __restrict__ s2) {
    int t = blockIdx.y;
    const float* src = t ? s2 : s1;
    int idx = blockIdx.x * 256 + threadIdx.x;
    int b  = idx / SPACK_SLOTS;
    int r  = idx % SPACK_SLOTS;
    int k2 = r / (HW/4);
    int m4 = (r % (HW/4)) * 4;
    const float* p0 = src + ((size_t)b * C + 2 * k2) * HW + m4;
    float4 lo = *(const float4*)p0;
    float4 hi = *(const float4*)(p0 + HW);
    uint4 o;
    o.x = packbf(lo.x, hi.x); o.y = packbf(lo.y, hi.y);
    o.z = packbf(lo.z, hi.z); o.w = packbf(lo.w, hi.w);
    *(uint4*)&g_sbf[t][((size_t)b * (C/2) + k2) * HW + m4] = o;
}

// pack gathered X f32 -> bf16x2 words [k2][c]
#define XPACK_SLOTS ((NSEL/2)*(C/4))   // 307200 per tensor
__global__ void k_pack_x() {
    int t = blockIdx.y;
    int idx = blockIdx.x * 256 + threadIdx.x;
    int k2 = idx / (C/4);
    int c4 = (idx % (C/4)) * 4;
    const float* p0 = g_X[t] + (size_t)(2 * k2) * C + c4;
    float4 lo = *(const float4*)p0;
    float4 hi = *(const float4*)(p0 + C);
    uint4 o;
    o.x = packbf(lo.x, hi.x); o.y = packbf(lo.y, hi.y);
    o.z = packbf(lo.z, hi.z); o.w = packbf(lo.w, hi.w);
    *(uint4*)&g_Xbf[t][(size_t)k2 * C + c4] = o;
}

// ---------------- bf16 MMA machinery ----------------
#define LDW2   136                 // words/row; 136 % 32 == 8 -> conflict-free
#define MATW2  (16*LDW2)           // 2176 words per chunk-matrix
#define SSTR2  (2*MATW2)           // 4352 words per stage
#define GS2    (2 * SSTR2 * 4)     // 34816 B

// per k16 step (kb2 = 0 or 8): 6x LDS.128, 16 HMMA, zero cvt.
#define FRAGP(As, Bs, kb2)                                                       \
    {                                                                            \
        uint4 A0 = *(const uint4*)&As[(kb2 + gc    ) * LDW2 + wm      + gr * 4]; \
        uint4 A1 = *(const uint4*)&As[(kb2 + gc + 4) * LDW2 + wm      + gr * 4]; \
        uint4 A2 = *(const uint4*)&As[(kb2 + gc    ) * LDW2 + wm + 32 + gr * 4]; \
        uint4 A3 = *(const uint4*)&As[(kb2 + gc + 4) * LDW2 + wm + 32 + gr * 4]; \
        uint4 B0 = *(const uint4*)&Bs[(kb2 + gc    ) * LDW2 + wn      + gr * 4]; \
        uint4 B1 = *(const uint4*)&Bs[(kb2 + gc + 4) * LDW2 + wn      + gr * 4]; \
        mma_bf16(acc[0][0], A0.x, A0.y, A1.x, A1.y, B0.x, B1.x);                 \
        mma_bf16(acc[0][1], A0.x, A0.y, A1.x, A1.y, B0.y, B1.y);                 \
        mma_bf16(acc[0][2], A0.x, A0.y, A1.x, A1.y, B0.z, B1.z);                 \
        mma_bf16(acc[0][3], A0.x, A0.y, A1.x, A1.y, B0.w, B1.w);                 \
        mma_bf16(acc[1][0], A0.z, A0.w, A1.z, A1.w, B0.x, B1.x);                 \
        mma_bf16(acc[1][1], A0.z, A0.w, A1.z, A1.w, B0.y, B1.y);                 \
        mma_bf16(acc[1][2], A0.z, A0.w, A1.z, A1.w, B0.z, B1.z);                 \
        mma_bf16(acc[1][3], A0.z, A0.w, A1.z, A1.w, B0.w, B1.w);                 \
        mma_bf16(acc[2][0], A2.x, A2.y, A3.x, A3.y, B0.x, B1.x);                 \
        mma_bf16(acc[2][1], A2.x, A2.y, A3.x, A3.y, B0.y, B1.y);                 \
        mma_bf16(acc[2][2], A2.x, A2.y, A3.x, A3.y, B0.z, B1.z);                 \
        mma_bf16(acc[2][3], A2.x, A2.y, A3.x, A3.y, B0.w, B1.w);                 \
        mma_bf16(acc[3][0], A2.z, A2.w, A3.z, A3.w, B0.x, B1.x);                 \
        mma_bf16(acc[3][1], A2.z, A2.w, A3.z, A3.w, B0.y, B1.y);                 \
        mma_bf16(acc[3][2], A2.z, A2.w, A3.z, A3.w, B0.z, B1.z);                 \
        mma_bf16(acc[3][3], A2.z, A2.w, A3.z, A3.w, B0.w, B1.w);                 \
    }

// ---- fused bf16 GEMM + row/col argmin. CTA 128x128, 8 warps (2m x 4n), 2-stage ----
__global__ void __launch_bounds__(256, 2) k_gemm_fused() {
    extern __shared__ uint32_t dyn[];
    int b  = blockIdx.z;
    int m0 = blockIdx.y * 128, n0 = blockIdx.x * 128;
    int tid = threadIdx.x, w = tid >> 5, lane = tid & 31;
    int wm = (w & 1) * 64, wn = (w >> 1) * 32;
    int gr = lane >> 2, gc = lane & 3;

    const uint32_t* Ag = g_sbf[0] + (size_t)b * (C/2) * HW;
    const uint32_t* Bg = g_sbf[1] + (size_t)b * (C/2) * HW;
    uint32_t sbase = smem_u32(dyn);

    // copy slots: 512 uint4 per matrix per chunk; 2 per thread per matrix
    int rowv[2], colA[2], colB[2];
    #pragma unroll
    for (int t = 0; t < 2; t++) {
        int v = tid + t * 256;
        rowv[t] = v >> 5;                 // 0..15 (k2 row)
        int col = (v & 31) * 4;           // word col
        int ca = m0 + col; if (ca > HW - 4) ca = HW - 4;
        int cb = n0 + col; if (cb > HW - 4) cb = HW - 4;
        colA[t] = ca; colB[t] = cb;
    }
    auto issue_chunk = [&](int s, int stage) {
        int k20 = s * 16;
        uint32_t sA = sbase + stage * (SSTR2 * 4);
        uint32_t sB = sA + MATW2 * 4;
        #pragma unroll
        for (int t = 0; t < 2; t++) {
            int v = tid + t * 256;
            uint32_t so = ((v >> 5) * LDW2 + (v & 31) * 4) * 4;
            CP_A16(sA + so, (const char*)&Ag[(size_t)(k20 + rowv[t]) * HW + colA[t]]);
            CP_A16(sB + so, (const char*)&Bg[(size_t)(k20 + rowv[t]) * HW + colB[t]]);
        }
        CP_COMMIT();
    };

    float acc[4][4][4] = {};
    issue_chunk(0, 0);
    for (int s = 0; s < NCH; s++) {
        if (s + 1 < NCH) { issue_chunk(s + 1, (s + 1) & 1); CP_WAIT1(); }
        else             { CP_WAIT0(); }
        __syncthreads();
        const uint32_t* As = dyn + (s & 1) * SSTR2;
        const uint32_t* Bs = As + MATW2;
        FRAGP(As, Bs, 0)
        FRAGP(As, Bs, 8)
        __syncthreads();
    }

    // ---- fused argmin epilogue (same remap as R9) ----
    ull* rkey = (ull*)dyn;
    ull* ckey = rkey + 128;
    if (tid < 128) { rkey[tid] = ~0ull; ckey[tid] = ~0ull; }
    __syncthreads();

    const float* a2p = g_a2 + b * HW;
    const float* b2p = g_b2 + b * HW;

    #pragma unroll
    for (int i = 0; i < 4; i++) {
        int mbase = wm + (i >> 1) * 32 + gr * 4 + (i & 1) * 2;
        #pragma unroll
        for (int half = 0; half < 2; half++) {
            int ml = mbase + half;
            ull rb_ = ~0ull;
            #pragma unroll
            for (int j = 0; j < 4; j++)
                #pragma unroll
                for (int rb = 0; rb < 2; rb++) {
                    int n_g = n0 + wn + 8 * gc + 4 * rb + j;
                    if (n_g < HW) {
                        ull k = enc_key(b2p[n_g] - 2.f * acc[i][j][half * 2 + rb], n_g);
                        if (k < rb_) rb_ = k;
                    }
                }
            if (rb_ != ~0ull) atomicMin(&rkey[ml], rb_);
        }
    }
    #pragma unroll
    for (int j = 0; j < 4; j++)
        #pragma unroll
        for (int rb = 0; rb < 2; rb++) {
            int nl = wn + 8 * gc + 4 * rb + j;
            ull cbest = ~0ull;
            #pragma unroll
            for (int i = 0; i < 4; i++) {
                int mbase = m0 + wm + (i >> 1) * 32 + gr * 4 + (i & 1) * 2;
                #pragma unroll
                for (int half = 0; half < 2; half++) {
                    int m_g = mbase + half;
                    if (m_g < HW) {
                        ull k = enc_key(a2p[m_g] - 2.f * acc[i][j][half * 2 + rb], m_g);
                        if (k < cbest) cbest = k;
                    }
                }
            }
            if (cbest != ~0ull) atomicMin(&ckey[nl], cbest);
        }
    __syncthreads();
    if (tid < 128) {
        int m = m0 + tid;
        if (m < HW) atomicMin(&g_key[0][b * HW + m], rkey[tid]);
    } else {
        int n = n0 + tid - 128;
        if (n < HW) atomicMin(&g_key[1][b * HW + n], ckey[tid - 128]);
    }
}

// ---- bf16 MMA Gram from packed X: S[t] = X^T X, upper 128x128 tiles ----
__global__ void __launch_bounds__(256, 2) k_gram_mma() {
    extern __shared__ uint32_t dyn[];
    int t = blockIdx.y;
    const uint32_t* X = g_Xbf[t];
    int idx = blockIdx.x, ti = 0;
    while (idx >= 6 - ti) { idx -= 6 - ti; ti++; }
    int tj = ti + idx;
    int i0 = ti * 128, j0 = tj * 128;

    int tid = threadIdx.x, w = tid >> 5, lane = tid & 31;
    int wm = (w & 1) * 64, wn = (w >> 1) * 32;
    int gr = lane >> 2, gc = lane & 3;
    uint32_t sbase = smem_u32(dyn);

    auto issue_chunk = [&](int s, int stage) {
        int k20 = s * 16;
        uint32_t sA = sbase + stage * (SSTR2 * 4);
        uint32_t sB = sA + MATW2 * 4;
        #pragma unroll
        for (int tt = 0; tt < 2; tt++) {
            int v = tid + tt * 256;
            int row = v >> 5, col = (v & 31) * 4;
            uint32_t so = (row * LDW2 + col) * 4;
            CP_A16(sA + so, (const char*)&X[(size_t)(k20 + row) * C + i0 + col]);
            CP_A16(sB + so, (const char*)&X[(size_t)(k20 + row) * C + j0 + col]);
        }
        CP_COMMIT();
    };

    float acc[4][4][4] = {};
    issue_chunk(0, 0);
    for (int s = 0; s < NCH2; s++) {
        if (s + 1 < NCH2) { issue_chunk(s + 1, (s + 1) & 1); CP_WAIT1(); }
        else              { CP_WAIT0(); }
        __syncthreads();
        const uint32_t* As = dyn + (s & 1) * SSTR2;
        const uint32_t* Bs = As + MATW2;
        FRAGP(As, Bs, 0)
        FRAGP(As, Bs, 8)
        __syncthreads();
    }

    float* Sp = g_S[t];
    #pragma unroll
    for (int i = 0; i < 4; i++) {
        int mbase = i0 + wm + (i >> 1) * 32 + gr * 4 + (i & 1) * 2;
        #pragma unroll
        for (int half = 0; half < 2; half++)
            #pragma unroll
            for (int rb = 0; rb < 2; rb++) {
                int c2 = j0 + wn + 8 * gc + 4 * rb;
                float4 o = make_float4(acc[i][0][half * 2 + rb], acc[i][1][half * 2 + rb],
                                       acc[i][2][half * 2 + rb], acc[i][3][half * 2 + rb]);
                *(float4*)&Sp[(size_t)(mbase + half) * C + c2] = o;
            }
    }
}

// rank-based top-50 smallest d2 (ties -> lowest index)
__global__ void k_select() {
    int b = blockIdx.x, dir = blockIdx.y;
    __shared__ float sd[HW];
    __shared__ int   sn[HW];
    int i = threadIdx.x;
    ull key = g_key[dir][b * HW + i];
    const float* own = dir ? g_b2 : g_a2;
    float d2 = own[b * HW + i] + dec_val(key);
    if (d2 < 0.f) d2 = 0.f;
    sd[i] = d2;
    sn[i] = (int)(uint32_t)key;
    __syncthreads();
    float di = sd[i];
    int rank = 0;
    for (int j = 0; j < HW; j++) {
        float dj = sd[j];
        rank += (dj < di) || (dj == di && j < i);
    }
    if (rank < NM) {
        g_sel_in[dir][b * NM + rank] = i;
        g_sel_c [dir][b * NM + rank] = sn[i];
    }
}

__global__ void k_gather(const float* __restrict__ s1, const float* __restrict__ s2) {
    int k = blockIdx.x, b = blockIdx.y, dir = blockIdx.z;
    const float* srcin = dir ? s2 : s1;
    const float* srcc  = dir ? s1 : s2;
    int pin = g_sel_in[dir][b * NM + k];
    int pc  = g_sel_c [dir][b * NM + k];
    float* Xin = g_X[dir * 2 + 0];
    float* Xc  = g_X[dir * 2 + 1];
    int row = b * NM + k;
    float lsum = 0.f;
    for (int c = threadIdx.x; c < C; c += 256) {
        float vi = srcin[((size_t)b * C + c) * HW + pin];
        float vc = srcc [((size_t)b * C + c) * HW + pc];
        Xin[(size_t)row * C + c] = vi;
        Xc [(size_t)row * C + c] = vc;
        float d = vi - vc; lsum += d * d;
    }
    float tot = blockReduceSum(lsum);
    if (threadIdx.x == 0) atomicAdd(&g_acc[1 + dir], (double)tot);
}

__global__ void k_pooled_inv(const float* __restrict__ p1, const float* __restrict__ p2) {
    float lsum = 0.f;
    for (int i = blockIdx.x * blockDim.x + threadIdx.x; i < B * C; i += gridDim.x * blockDim.x) {
        float d = p1[i] - p2[i]; lsum += d * d;
    }
    float tot = blockReduceSum(lsum);
    if (threadIdx.x == 0) atomicAdd(&g_acc[0], (double)tot);
}

__device__ __forceinline__ const float* tensor_ptr(int t, const float* p1, const float* p2) {
    if (t < 4) return g_X[t];
    return (t == 4) ? p1 : p2;
}
__device__ __forceinline__ int tensor_n(int t) { return (t < 4) ? NSEL : B; }

__global__ void k_colsum_part(const float* __restrict__ p1, const float* __restrict__ p2) {
    int t = blockIdx.x, chunk = blockIdx.y, c = threadIdx.x;
    const float* X = tensor_ptr(t, p1, p2);
    int n = tensor_n(t);
    int step = n / 16;
    int n0 = chunk * step, n1 = n0 + step;
    float s = 0.f;
    for (int i = n0; i < n1; i++) s += X[(size_t)i * C + c];
    g_csp[t][chunk][c] = s;
}
__global__ void k_colsum_fin() {
    int t = blockIdx.x, c = threadIdx.x;
    float s = 0.f;
    #pragma unroll
    for (int k = 0; k < 16; k++) s += g_csp[t][k][c];
    g_colsum[t][c] = s;
}

// exact fp32 Gram for the 2 pooled tensors (n=64), upper 64x64 tiles
__global__ void __launch_bounds__(256) k_gram(const float* __restrict__ p1,
                                              const float* __restrict__ p2) {
    int t = 4 + blockIdx.y;
    const float* X = tensor_ptr(t, p1, p2);
    int n = tensor_n(t);
    int idx = blockIdx.x, ti = 0;
    while (idx >= 12 - ti) { idx -= 12 - ti; ti++; }
    int tj = ti + idx;
    int i0 = ti * 64, j0 = tj * 64;

    __shared__ float As[16][64], Bs[16][64];
    int tid = threadIdx.x;
    int tx = tid & 15, ty = tid >> 4;
    int lk = tid >> 4, lo = (tid & 15) * 4;
    float acc[4][4] = {};
    for (int k0 = 0; k0 < n; k0 += 16) {
        *(float4*)&As[lk][lo] = *(const float4*)&X[(size_t)(k0 + lk) * C + i0 + lo];
        *(float4*)&Bs[lk][lo] = *(const float4*)&X[(size_t)(k0 + lk) * C + j0 + lo];
        __syncthreads();
        #pragma unroll
        for (int kk = 0; kk < 16; kk++) {
            float a[4], bb[4];
            *(float4*)a  = *(float4*)&As[kk][ty * 4];
            *(float4*)bb = *(float4*)&Bs[kk][tx * 4];
            #pragma unroll
            for (int i = 0; i < 4; i++)
                #pragma unroll
                for (int j = 0; j < 4; j++) acc[i][j] += a[i] * bb[j];
        }
        __syncthreads();
    }
    float* Sp = g_S[t];
    #pragma unroll
    for (int i = 0; i < 4; i++) {
        int c1 = i0 + ty * 4 + i;
        *(float4*)&Sp[(size_t)c1 * C + j0 + tx * 4] = *(float4*)acc[i];
    }
}

__global__ void k_std() {
    int t = blockIdx.x, c = threadIdx.x;
    float n  = (float)tensor_n(t);
    float mu = g_colsum[t][c] / n;
    float Scc = g_S[t][(size_t)c * C + c];
    float var = (Scc - n * mu * mu) / (n - 1.f);
    float sd  = sqrtf(var + EPSV);
    float contrib = fmaxf(1.f - sd, 0.f);
    float tot = blockReduceSum(contrib);
    if (threadIdx.x == 0) atomicAdd(&g_acc[3 + t], (double)tot);
}

__global__ void k_cov() {
    int t = blockIdx.y;
    float n = (float)tensor_n(t);
    float inv_nm1 = 1.f / (n - 1.f);
    int idx = blockIdx.x, ti = 0;
    while (idx >= 12 - ti) { idx -= 12 - ti; ti++; }
    int tj = ti + idx;
    int i0 = ti * 64, j0 = tj * 64;
    const float* Sp = g_S[t];
    float lsum = 0.f;
    #pragma unroll
    for (int it = 0; it < 16; it++) {
        int e = it * 256 + threadIdx.x;
        int r = e >> 6, cc = e & 63;
        int c1 = i0 + r, c2 = j0 + cc;
        if (c2 > c1) {
            float mu1 = g_colsum[t][c1] / n;
            float mu2 = g_colsum[t][c2] / n;
            float cov = (Sp[(size_t)c1 * C + c2] - n * mu1 * mu2) * inv_nm1;
            lsum += 2.f * cov * cov;
        }
    }
    float tot = blockReduceSum(lsum);
    if (threadIdx.x == 0) atomicAdd(&g_acc[10 + t], (double)tot);
}

__global__ void k_final(float* __restrict__ out) {
    double inv_g = g_acc[0] / (double)(B * C);
    double inv1  = g_acc[1] / (double)((size_t)NSEL * C);
    double inv2  = g_acc[2] / (double)((size_t)NSEL * C);
    double stdt[6], covt[6];
    for (int t = 0; t < 6; t++) {
        stdt[t] = (g_acc[3 + t] / (double)C) * 0.5;
        covt[t] = g_acc[10 + t] / (double)C;
    }
    double glob = 25.0 * inv_g + 25.0 * (stdt[4] + stdt[5]) + (covt[4] + covt[5]);
    double loc  = 0.5 * (25.0 * inv1 + 25.0 * inv2)
                + 0.5 * (25.0 * (stdt[0] + stdt[1]) + 25.0 * (stdt[2] + stdt[3]))
                + 0.5 * ((covt[0] + covt[1]) + (covt[2] + covt[3]));
    out[0] = (float)(0.5 * glob + 0.5 * loc);
}

// ---------------- launch ----------------
extern "C" void kernel_launch(void* const* d_in, const int* in_sizes, int n_in,
                              void* d_out, int out_size) {
    const float* s1 = (const float*)d_in[0];
    const float* p1 = (const float*)d_in[1];
    const float* s2 = (const float*)d_in[2];
    const float* p2 = (const float*)d_in[3];
    float* out = (float*)d_out;

    cudaFuncSetAttribute(k_gemm_fused, cudaFuncAttributeMaxDynamicSharedMemorySize, GS2);
    cudaFuncSetAttribute(k_gram_mma,   cudaFuncAttributeMaxDynamicSharedMemorySize, GS2);

    k_init<<<1, 32>>>();
    k_keyinit<<<(2 * B * HW + 255) / 256, 256>>>();
    k_norms<<<dim3(B, 2), HW>>>(s1, s2);
    k_pack_s<<<dim3(B * SPACK_SLOTS / 256, 2), 256>>>(s1, s2);
    k_gemm_fused<<<dim3(5, 5, B), 256, GS2>>>();
    k_select<<<dim3(B, 2), HW>>>();
    k_gather<<<dim3(NM, B, 2), 256>>>(s1, s2);
    k_pack_x<<<dim3(XPACK_SLOTS / 256, 4), 256>>>();
    k_pooled_inv<<<48, 256>>>(p1, p2);
    k_colsum_part<<<dim3(6, 16), C>>>(p1, p2);
    k_colsum_fin<<<6, C>>>();
    k_gram_mma<<<dim3(21, 4), 256, GS2>>>();
    k_gram<<<dim3(78, 2), 256>>>(p1, p2);
    k_std<<<6, C>>>();
    k_cov<<<dim3(78, 6), 256>>>();
    k_final<<<1, 1>>>(out);
}

// round 11
// speedup vs baseline: 1.4713x; 1.0919x over previous
#include <cuda_runtime.h>
#include <cstdint>
#include <math.h>

#define B    64
#define C    768
#define HW   576
#define NM   50
#define NSEL (B*NM)   // 3200
#define EPSV 1e-5f
#define KC   32
#define NCH  (C/KC)    // 24
#define NCH2 (NSEL/KC) // 100

typedef unsigned long long ull;

// ---------------- scratch ----------------
__device__ float    g_a2[B*HW], g_b2[B*HW];
__device__ ull      g_key[2][B*HW];
__device__ int      g_sel_in[2][NSEL];
__device__ int      g_sel_c [2][NSEL];
__device__ uint32_t g_sbf[2][(size_t)B*(C/2)*HW];      // packed bf16x2 spatial [b][k2][m]
__device__ uint32_t g_Xbf[4][(size_t)(NSEL/2)*C];      // packed bf16x2 gathered [n2][c]
__device__ float    g_S[6][(size_t)C*C];
__device__ float    g_csp[6][16][C];
__device__ float    g_colsum[6][C];
__device__ double   g_acc[32];

// ---------------- helpers ----------------
__device__ __forceinline__ void mma_bf16(float c[4],
                                         uint32_t a0, uint32_t a1, uint32_t a2, uint32_t a3,
                                         uint32_t b0, uint32_t b1) {
    asm volatile(
        "mma.sync.aligned.m16n8k16.row.col.f32.bf16.bf16.f32 "
        "{%0,%1,%2,%3}, {%4,%5,%6,%7}, {%8,%9}, {%0,%1,%2,%3};"
        : "+f"(c[0]), "+f"(c[1]), "+f"(c[2]), "+f"(c[3])
        : "r"(a0), "r"(a1), "r"(a2), "r"(a3), "r"(b0), "r"(b1));
}
__device__ __forceinline__ uint32_t packbf(float lo, float hi) {
    uint32_t r;
    asm("cvt.rn.bf16x2.f32 %0, %1, %2;" : "=r"(r) : "f"(hi), "f"(lo));
    return r;
}
__device__ __forceinline__ float bf_lo(uint32_t w) { return __uint_as_float(w << 16); }
__device__ __forceinline__ float bf_hi(uint32_t w) { return __uint_as_float(w & 0xffff0000u); }

#define CP_A16(d, s) asm volatile("cp.async.ca.shared.global [%0], [%1], 16;" :: "r"(d), "l"(s))
#define CP_COMMIT()  asm volatile("cp.async.commit_group;" ::: "memory")
#define CP_WAIT1()   asm volatile("cp.async.wait_group 1;" ::: "memory")
#define CP_WAIT0()   asm volatile("cp.async.wait_group 0;" ::: "memory")

__device__ __forceinline__ uint32_t smem_u32(const void* p) {
    uint32_t a;
    asm("{ .reg .u64 t; cvta.to.shared.u64 t, %1; cvt.u32.u64 %0, t; }" : "=r"(a) : "l"(p));
    return a;
}
__device__ __forceinline__ ull enc_key(float f, int idx) {
    uint32_t u = __float_as_uint(f);
    u = (u & 0x80000000u) ? ~u : (u | 0x80000000u);
    return ((ull)u << 32) | (uint32_t)idx;
}
__device__ __forceinline__ float dec_val(ull k) {
    uint32_t e = (uint32_t)(k >> 32);
    uint32_t u = (e & 0x80000000u) ? (e ^ 0x80000000u) : ~e;
    return __uint_as_float(u);
}

__device__ __forceinline__ float blockReduceSum(float v) {
    __shared__ float sw[32];
    int lane = threadIdx.x & 31, w = threadIdx.x >> 5;
    #pragma unroll
    for (int o = 16; o; o >>= 1) v += __shfl_xor_sync(~0u, v, o);
    if (lane == 0) sw[w] = v;
    __syncthreads();
    int nw = (blockDim.x + 31) >> 5;
    v = (threadIdx.x < nw) ? sw[threadIdx.x] : 0.f;
    if (w == 0) {
        #pragma unroll
        for (int o = 16; o; o >>= 1) v += __shfl_xor_sync(~0u, v, o);
    }
    return v;
}

// ---------------- small kernels ----------------
__global__ void k_init() { if (threadIdx.x < 32) g_acc[threadIdx.x] = 0.0; }
__global__ void k_keyinit() {
    int i = blockIdx.x * blockDim.x + threadIdx.x;
    if (i < 2 * B * HW) ((ull*)g_key)[i] = ~0ull;
}

// pack spatial f32 -> bf16x2 words [b][k2][m]
#define SPACK_SLOTS ((C/2)*(HW/4))   // 55296 per batch
__global__ void k_pack_s(const float* __restrict__ s1, const float* __restrict__ s2) {
    int t = blockIdx.y;
    const float* src = t ? s2 : s1;
    int idx = blockIdx.x * 256 + threadIdx.x;
    int b  = idx / SPACK_SLOTS;
    int r  = idx % SPACK_SLOTS;
    int k2 = r / (HW/4);
    int m4 = (r % (HW/4)) * 4;
    const float* p0 = src + ((size_t)b * C + 2 * k2) * HW + m4;
    float4 lo = *(const float4*)p0;
    float4 hi = *(const float4*)(p0 + HW);
    uint4 o;
    o.x = packbf(lo.x, hi.x); o.y = packbf(lo.y, hi.y);
    o.z = packbf(lo.z, hi.z); o.w = packbf(lo.w, hi.w);
    *(uint4*)&g_sbf[t][((size_t)b * (C/2) + k2) * HW + m4] = o;
}

// squared norms from packed bf16 (selection-only -> bf16 precision is fine)
__global__ void k_norms_p() {
    int b = blockIdx.x, m = threadIdx.x, t = blockIdx.y;
    const uint32_t* src = g_sbf[t] + (size_t)b * (C/2) * HW + m;
    float s = 0.f;
    #pragma unroll 8
    for (int k2 = 0; k2 < C/2; k2++) {
        uint32_t w = src[(size_t)k2 * HW];
        float lo = bf_lo(w), hi = bf_hi(w);
        s += lo * lo + hi * hi;
    }
    (t ? g_b2 : g_a2)[b * HW + m] = s;
}

// ---------------- bf16 MMA machinery ----------------
#define LDW2   136                 // words/row; 136 % 32 == 8 -> conflict-free
#define MATW2  (16*LDW2)
#define SSTR2  (2*MATW2)
#define GS2    (2 * SSTR2 * 4)     // 34816 B

#define FRAGP(As, Bs, kb2)                                                       \
    {                                                                            \
        uint4 A0 = *(const uint4*)&As[(kb2 + gc    ) * LDW2 + wm      + gr * 4]; \
        uint4 A1 = *(const uint4*)&As[(kb2 + gc + 4) * LDW2 + wm      + gr * 4]; \
        uint4 A2 = *(const uint4*)&As[(kb2 + gc    ) * LDW2 + wm + 32 + gr * 4]; \
        uint4 A3 = *(const uint4*)&As[(kb2 + gc + 4) * LDW2 + wm + 32 + gr * 4]; \
        uint4 B0 = *(const uint4*)&Bs[(kb2 + gc    ) * LDW2 + wn      + gr * 4]; \
        uint4 B1 = *(const uint4*)&Bs[(kb2 + gc + 4) * LDW2 + wn      + gr * 4]; \
        mma_bf16(acc[0][0], A0.x, A0.y, A1.x, A1.y, B0.x, B1.x);                 \
        mma_bf16(acc[0][1], A0.x, A0.y, A1.x, A1.y, B0.y, B1.y);                 \
        mma_bf16(acc[0][2], A0.x, A0.y, A1.x, A1.y, B0.z, B1.z);                 \
        mma_bf16(acc[0][3], A0.x, A0.y, A1.x, A1.y, B0.w, B1.w);                 \
        mma_bf16(acc[1][0], A0.z, A0.w, A1.z, A1.w, B0.x, B1.x);                 \
        mma_bf16(acc[1][1], A0.z, A0.w, A1.z, A1.w, B0.y, B1.y);                 \
        mma_bf16(acc[1][2], A0.z, A0.w, A1.z, A1.w, B0.z, B1.z);                 \
        mma_bf16(acc[1][3], A0.z, A0.w, A1.z, A1.w, B0.w, B1.w);                 \
        mma_bf16(acc[2][0], A2.x, A2.y, A3.x, A3.y, B0.x, B1.x);                 \
        mma_bf16(acc[2][1], A2.x, A2.y, A3.x, A3.y, B0.y, B1.y);                 \
        mma_bf16(acc[2][2], A2.x, A2.y, A3.x, A3.y, B0.z, B1.z);                 \
        mma_bf16(acc[2][3], A2.x, A2.y, A3.x, A3.y, B0.w, B1.w);                 \
        mma_bf16(acc[3][0], A2.z, A2.w, A3.z, A3.w, B0.x, B1.x);                 \
        mma_bf16(acc[3][1], A2.z, A2.w, A3.z, A3.w, B0.y, B1.y);                 \
        mma_bf16(acc[3][2], A2.z, A2.w, A3.z, A3.w, B0.z, B1.z);                 \
        mma_bf16(acc[3][3], A2.z, A2.w, A3.z, A3.w, B0.w, B1.w);                 \
    }

// ---- fused bf16 GEMM + row/col argmin. CTA 128x128, 8 warps (2m x 4n), 2-stage ----
__global__ void __launch_bounds__(256, 2) k_gemm_fused() {
    extern __shared__ uint32_t dyn[];
    int b  = blockIdx.z;
    int m0 = blockIdx.y * 128, n0 = blockIdx.x * 128;
    int tid = threadIdx.x, w = tid >> 5, lane = tid & 31;
    int wm = (w & 1) * 64, wn = (w >> 1) * 32;
    int gr = lane >> 2, gc = lane & 3;

    const uint32_t* Ag = g_sbf[0] + (size_t)b * (C/2) * HW;
    const uint32_t* Bg = g_sbf[1] + (size_t)b * (C/2) * HW;
    uint32_t sbase = smem_u32(dyn);

    int rowv[2], colA[2], colB[2];
    #pragma unroll
    for (int t = 0; t < 2; t++) {
        int v = tid + t * 256;
        rowv[t] = v >> 5;
        int col = (v & 31) * 4;
        int ca = m0 + col; if (ca > HW - 4) ca = HW - 4;
        int cb = n0 + col; if (cb > HW - 4) cb = HW - 4;
        colA[t] = ca; colB[t] = cb;
    }
    auto issue_chunk = [&](int s, int stage) {
        int k20 = s * 16;
        uint32_t sA = sbase + stage * (SSTR2 * 4);
        uint32_t sB = sA + MATW2 * 4;
        #pragma unroll
        for (int t = 0; t < 2; t++) {
            int v = tid + t * 256;
            uint32_t so = ((v >> 5) * LDW2 + (v & 31) * 4) * 4;
            CP_A16(sA + so, (const char*)&Ag[(size_t)(k20 + rowv[t]) * HW + colA[t]]);
            CP_A16(sB + so, (const char*)&Bg[(size_t)(k20 + rowv[t]) * HW + colB[t]]);
        }
        CP_COMMIT();
    };

    float acc[4][4][4] = {};
    issue_chunk(0, 0);
    for (int s = 0; s < NCH; s++) {
        if (s + 1 < NCH) { issue_chunk(s + 1, (s + 1) & 1); CP_WAIT1(); }
        else             { CP_WAIT0(); }
        __syncthreads();
        const uint32_t* As = dyn + (s & 1) * SSTR2;
        const uint32_t* Bs = As + MATW2;
        FRAGP(As, Bs, 0)
        FRAGP(As, Bs, 8)
        __syncthreads();
    }

    // ---- fused argmin epilogue ----
    ull* rkey = (ull*)dyn;
    ull* ckey = rkey + 128;
    if (tid < 128) { rkey[tid] = ~0ull; ckey[tid] = ~0ull; }
    __syncthreads();

    const float* a2p = g_a2 + b * HW;
    const float* b2p = g_b2 + b * HW;

    #pragma unroll
    for (int i = 0; i < 4; i++) {
        int mbase = wm + (i >> 1) * 32 + gr * 4 + (i & 1) * 2;
        #pragma unroll
        for (int half = 0; half < 2; half++) {
            int ml = mbase + half;
            ull rb_ = ~0ull;
            #pragma unroll
            for (int j = 0; j < 4; j++)
                #pragma unroll
                for (int rb = 0; rb < 2; rb++) {
                    int n_g = n0 + wn + 8 * gc + 4 * rb + j;
                    if (n_g < HW) {
                        ull k = enc_key(b2p[n_g] - 2.f * acc[i][j][half * 2 + rb], n_g);
                        if (k < rb_) rb_ = k;
                    }
                }
            if (rb_ != ~0ull) atomicMin(&rkey[ml], rb_);
        }
    }
    #pragma unroll
    for (int j = 0; j < 4; j++)
        #pragma unroll
        for (int rb = 0; rb < 2; rb++) {
            int nl = wn + 8 * gc + 4 * rb + j;
            ull cbest = ~0ull;
            #pragma unroll
            for (int i = 0; i < 4; i++) {
                int mbase = m0 + wm + (i >> 1) * 32 + gr * 4 + (i & 1) * 2;
                #pragma unroll
                for (int half = 0; half < 2; half++) {
                    int m_g = mbase + half;
                    if (m_g < HW) {
                        ull k = enc_key(a2p[m_g] - 2.f * acc[i][j][half * 2 + rb], m_g);
                        if (k < cbest) cbest = k;
                    }
                }
            }
            if (cbest != ~0ull) atomicMin(&ckey[nl], cbest);
        }
    __syncthreads();
    if (tid < 128) {
        int m = m0 + tid;
        if (m < HW) atomicMin(&g_key[0][b * HW + m], rkey[tid]);
    } else {
        int n = n0 + tid - 128;
        if (n < HW) atomicMin(&g_key[1][b * HW + n], ckey[tid - 128]);
    }
}

// ---- bf16 MMA Gram from packed X: S[t] = X^T X, upper 128x128 tiles ----
__global__ void __launch_bounds__(256, 2) k_gram_mma() {
    extern __shared__ uint32_t dyn[];
    int t = blockIdx.y;
    const uint32_t* X = g_Xbf[t];
    int idx = blockIdx.x, ti = 0;
    while (idx >= 6 - ti) { idx -= 6 - ti; ti++; }
    int tj = ti + idx;
    int i0 = ti * 128, j0 = tj * 128;

    int tid = threadIdx.x, w = tid >> 5, lane = tid & 31;
    int wm = (w & 1) * 64, wn = (w >> 1) * 32;
    int gr = lane >> 2, gc = lane & 3;
    uint32_t sbase = smem_u32(dyn);

    auto issue_chunk = [&](int s, int stage) {
        int k20 = s * 16;
        uint32_t sA = sbase + stage * (SSTR2 * 4);
        uint32_t sB = sA + MATW2 * 4;
        #pragma unroll
        for (int tt = 0; tt < 2; tt++) {
            int v = tid + tt * 256;
            int row = v >> 5, col = (v & 31) * 4;
            uint32_t so = (row * LDW2 + col) * 4;
            CP_A16(sA + so, (const char*)&X[(size_t)(k20 + row) * C + i0 + col]);
            CP_A16(sB + so, (const char*)&X[(size_t)(k20 + row) * C + j0 + col]);
        }
        CP_COMMIT();
    };

    float acc[4][4][4] = {};
    issue_chunk(0, 0);
    for (int s = 0; s < NCH2; s++) {
        if (s + 1 < NCH2) { issue_chunk(s + 1, (s + 1) & 1); CP_WAIT1(); }
        else              { CP_WAIT0(); }
        __syncthreads();
        const uint32_t* As = dyn + (s & 1) * SSTR2;
        const uint32_t* Bs = As + MATW2;
        FRAGP(As, Bs, 0)
        FRAGP(As, Bs, 8)
        __syncthreads();
    }

    float* Sp = g_S[t];
    #pragma unroll
    for (int i = 0; i < 4; i++) {
        int mbase = i0 + wm + (i >> 1) * 32 + gr * 4 + (i & 1) * 2;
        #pragma unroll
        for (int half = 0; half < 2; half++)
            #pragma unroll
            for (int rb = 0; rb < 2; rb++) {
                int c2 = j0 + wn + 8 * gc + 4 * rb;
                float4 o = make_float4(acc[i][0][half * 2 + rb], acc[i][1][half * 2 + rb],
                                       acc[i][2][half * 2 + rb], acc[i][3][half * 2 + rb]);
                *(float4*)&Sp[(size_t)(mbase + half) * C + c2] = o;
            }
    }
}

// rank-based top-50 smallest d2 (ties -> lowest index)
__global__ void k_select() {
    int b = blockIdx.x, dir = blockIdx.y;
    __shared__ float sd[HW];
    __shared__ int   sn[HW];
    int i = threadIdx.x;
    ull key = g_key[dir][b * HW + i];
    const float* own = dir ? g_b2 : g_a2;
    float d2 = own[b * HW + i] + dec_val(key);
    if (d2 < 0.f) d2 = 0.f;
    sd[i] = d2;
    sn[i] = (int)(uint32_t)key;
    __syncthreads();
    float di = sd[i];
    int rank = 0;
    for (int j = 0; j < HW; j++) {
        float dj = sd[j];
        rank += (dj < di) || (dj == di && j < i);
    }
    if (rank < NM) {
        g_sel_in[dir][b * NM + rank] = i;
        g_sel_c [dir][b * NM + rank] = sn[i];
    }
}

// gather row PAIRS -> packed bf16 X; exact f32 inv accumulated in-flight
__global__ void k_gather(const float* __restrict__ s1, const float* __restrict__ s2) {
    int p = blockIdx.x;            // 0..NSEL/2-1
    int dir = blockIdx.y;
    const float* srcin = dir ? s2 : s1;
    const float* srcc  = dir ? s1 : s2;
    int r0 = 2 * p, r1 = 2 * p + 1;
    int b = r0 / NM;               // NM even -> r0, r1 same batch
    int pin0 = g_sel_in[dir][r0], pin1 = g_sel_in[dir][r1];
    int pc0  = g_sel_c [dir][r0], pc1  = g_sel_c [dir][r1];
    uint32_t* Xin = g_Xbf[dir * 2 + 0];
    uint32_t* Xc  = g_Xbf[dir * 2 + 1];
    float lsum = 0.f;
    for (int c = threadIdx.x; c < C; c += 256) {
        size_t base = ((size_t)b * C + c) * HW;
        float vi0 = srcin[base + pin0], vi1 = srcin[base + pin1];
        float vc0 = srcc [base + pc0],  vc1 = srcc [base + pc1];
        Xin[(size_t)p * C + c] = packbf(vi0, vi1);
        Xc [(size_t)p * C + c] = packbf(vc0, vc1);
        float d0 = vi0 - vc0, d1 = vi1 - vc1;
        lsum += d0 * d0 + d1 * d1;
    }
    float tot = blockReduceSum(lsum);
    if (threadIdx.x == 0) atomicAdd(&g_acc[1 + dir], (double)tot);
}

__global__ void k_pooled_inv(const float* __restrict__ p1, const float* __restrict__ p2) {
    float lsum = 0.f;
    for (int i = blockIdx.x * blockDim.x + threadIdx.x; i < B * C; i += gridDim.x * blockDim.x) {
        float d = p1[i] - p2[i]; lsum += d * d;
    }
    float tot = blockReduceSum(lsum);
    if (threadIdx.x == 0) atomicAdd(&g_acc[0], (double)tot);
}

__device__ __forceinline__ int tensor_n(int t) { return (t < 4) ? NSEL : B; }

// column sums: t<4 from packed bf16 X, t>=4 from pooled f32
__global__ void k_colsum_part(const float* __restrict__ p1, const float* __restrict__ p2) {
    int t = blockIdx.x, chunk = blockIdx.y, c = threadIdx.x;
    float s = 0.f;
    if (t < 4) {
        const uint32_t* X = g_Xbf[t];
        int n20 = chunk * (NSEL / 2 / 16), n21 = n20 + NSEL / 2 / 16;  // 100 rows
        for (int i = n20; i < n21; i++) {
            uint32_t w = X[(size_t)i * C + c];
            s += bf_lo(w) + bf_hi(w);
        }
    } else {
        const float* X = (t == 4) ? p1 : p2;
        int n0 = chunk * (B / 16), n1 = n0 + B / 16;
        for (int i = n0; i < n1; i++) s += X[(size_t)i * C + c];
    }
    g_csp[t][chunk][c] = s;
}
__global__ void k_colsum_fin() {
    int t = blockIdx.x, c = threadIdx.x;
    float s = 0.f;
    #pragma unroll
    for (int k = 0; k < 16; k++) s += g_csp[t][k][c];
    g_colsum[t][c] = s;
}

// exact fp32 Gram for the 2 pooled tensors (n=64), upper 64x64 tiles
__global__ void __launch_bounds__(256) k_gram(const float* __restrict__ p1,
                                              const float* __restrict__ p2) {
    int t = 4 + blockIdx.y;
    const float* X = (t == 4) ? p1 : p2;
    int n = B;
    int idx = blockIdx.x, ti = 0;
    while (idx >= 12 - ti) { idx -= 12 - ti; ti++; }
    int tj = ti + idx;
    int i0 = ti * 64, j0 = tj * 64;

    __shared__ float As[16][64], Bs[16][64];
    int tid = threadIdx.x;
    int tx = tid & 15, ty = tid >> 4;
    int lk = tid >> 4, lo = (tid & 15) * 4;
    float acc[4][4] = {};
    for (int k0 = 0; k0 < n; k0 += 16) {
        *(float4*)&As[lk][lo] = *(const float4*)&X[(size_t)(k0 + lk) * C + i0 + lo];
        *(float4*)&Bs[lk][lo] = *(const float4*)&X[(size_t)(k0 + lk) * C + j0 + lo];
        __syncthreads();
        #pragma unroll
        for (int kk = 0; kk < 16; kk++) {
            float a[4], bb[4];
            *(float4*)a  = *(float4*)&As[kk][ty * 4];
            *(float4*)bb = *(float4*)&Bs[kk][tx * 4];
            #pragma unroll
            for (int i = 0; i < 4; i++)
                #pragma unroll
                for (int j = 0; j < 4; j++) acc[i][j] += a[i] * bb[j];
        }
        __syncthreads();
    }
    float* Sp = g_S[t];
    #pragma unroll
    for (int i = 0; i < 4; i++) {
        int c1 = i0 + ty * 4 + i;
        *(float4*)&Sp[(size_t)c1 * C + j0 + tx * 4] = *(float4*)acc[i];
    }
}

__global__ void k_std() {
    int t = blockIdx.x, c = threadIdx.x;
    float n  = (float)tensor_n(t);
    float mu = g_colsum[t][c] / n;
    float Scc = g_S[t][(size_t)c * C + c];
    float var = (Scc - n * mu * mu) / (n - 1.f);
    float sd  = sqrtf(var + EPSV);
    float contrib = fmaxf(1.f - sd, 0.f);
    float tot = blockReduceSum(contrib);
    if (threadIdx.x == 0) atomicAdd(&g_acc[3 + t], (double)tot);
}

__global__ void k_cov() {
    int t = blockIdx.y;
    float n = (float)tensor_n(t);
    float inv_nm1 = 1.f / (n - 1.f);
    int idx = blockIdx.x, ti = 0;
    while (idx >= 12 - ti) { idx -= 12 - ti; ti++; }
    int tj = ti + idx;
    int i0 = ti * 64, j0 = tj * 64;
    const float* Sp = g_S[t];
    float lsum = 0.f;
    #pragma unroll
    for (int it = 0; it < 16; it++) {
        int e = it * 256 + threadIdx.x;
        int r = e >> 6, cc = e & 63;
        int c1 = i0 + r, c2 = j0 + cc;
        if (c2 > c1) {
            float mu1 = g_colsum[t][c1] / n;
            float mu2 = g_colsum[t][c2] / n;
            float cov = (Sp[(size_t)c1 * C + c2] - n * mu1 * mu2) * inv_nm1;
            lsum += 2.f * cov * cov;
        }
    }
    float tot = blockReduceSum(lsum);
    if (threadIdx.x == 0) atomicAdd(&g_acc[10 + t], (double)tot);
}

__global__ void k_final(float* __restrict__ out) {
    double inv_g = g_acc[0] / (double)(B * C);
    double inv1  = g_acc[1] / (double)((size_t)NSEL * C);
    double inv2  = g_acc[2] / (double)((size_t)NSEL * C);
    double stdt[6], covt[6];
    for (int t = 0; t < 6; t++) {
        stdt[t] = (g_acc[3 + t] / (double)C) * 0.5;
        covt[t] = g_acc[10 + t] / (double)C;
    }
    double glob = 25.0 * inv_g + 25.0 * (stdt[4] + stdt[5]) + (covt[4] + covt[5]);
    double loc  = 0.5 * (25.0 * inv1 + 25.0 * inv2)
                + 0.5 * (25.0 * (stdt[0] + stdt[1]) + 25.0 * (stdt[2] + stdt[3]))
                + 0.5 * ((covt[0] + covt[1]) + (covt[2] + covt[3]));
    out[0] = (float)(0.5 * glob + 0.5 * loc);
}

// ---------------- launch ----------------
extern "C" void kernel_launch(void* const* d_in, const int* in_sizes, int n_in,
                              void* d_out, int out_size) {
    const float* s1 = (const float*)d_in[0];
    const float* p1 = (const float*)d_in[1];
    const float* s2 = (const float*)d_in[2];
    const float* p2 = (const float*)d_in[3];
    float* out = (float*)d_out;

    cudaFuncSetAttribute(k_gemm_fused, cudaFuncAttributeMaxDynamicSharedMemorySize, GS2);
    cudaFuncSetAttribute(k_gram_mma,   cudaFuncAttributeMaxDynamicSharedMemorySize, GS2);

    k_init<<<1, 32>>>();
    k_keyinit<<<(2 * B * HW + 255) / 256, 256>>>();
    k_pack_s<<<dim3(B * SPACK_SLOTS / 256, 2), 256>>>(s1, s2);
    k_norms_p<<<dim3(B, 2), HW>>>();
    k_gemm_fused<<<dim3(5, 5, B), 256, GS2>>>();
    k_select<<<dim3(B, 2), HW>>>();
    k_gather<<<dim3(NSEL / 2, 2), 256>>>(s1, s2);
    k_pooled_inv<<<48, 256>>>(p1, p2);
    k_colsum_part<<<dim3(6, 16), C>>>(p1, p2);
    k_colsum_fin<<<6, C>>>();
    k_gram_mma<<<dim3(21, 4), 256, GS2>>>();
    k_gram<<<dim3(78, 2), 256>>>(p1, p2);
    k_std<<<6, C>>>();
    k_cov<<<dim3(78, 6), 256>>>();
    k_final<<<1, 1>>>(out);
}

// round 12
// speedup vs baseline: 1.7116x; 1.1633x over previous
#include <cuda_runtime.h>
#include <cstdint>
#include <math.h>

#define B    64
#define C    768
#define HW   576
#define NM   50
#define NSEL (B*NM)   // 3200
#define EPSV 1e-5f
#define KC   32
#define NCH  (C/KC)    // 24
#define NCH2 (NSEL/KC) // 100

typedef unsigned long long ull;

// ---------------- scratch ----------------
__device__ float    g_a2[B*HW], g_b2[B*HW];
__device__ ull      g_key[2][B*HW];
__device__ int      g_sel_in[2][NSEL];
__device__ int      g_sel_c [2][NSEL];
__device__ uint32_t g_sbf[2][(size_t)B*(C/2)*HW];      // packed bf16x2 spatial [b][k2][m]  (GEMM layout)
__device__ uint32_t g_sbt[2][(size_t)B*HW*(C/2)];      // packed bf16x2 spatial [b][m][k2]  (gather layout)
__device__ uint32_t g_Xbf[4][(size_t)(NSEL/2)*C];      // packed bf16x2 gathered [n2][c]
__device__ float    g_S[6][(size_t)C*C];
__device__ float    g_csp[6][16][C];
__device__ float    g_colsum[6][C];
__device__ double   g_acc[32];

// ---------------- helpers ----------------
__device__ __forceinline__ void mma_bf16(float c[4],
                                         uint32_t a0, uint32_t a1, uint32_t a2, uint32_t a3,
                                         uint32_t b0, uint32_t b1) {
    asm volatile(
        "mma.sync.aligned.m16n8k16.row.col.f32.bf16.bf16.f32 "
        "{%0,%1,%2,%3}, {%4,%5,%6,%7}, {%8,%9}, {%0,%1,%2,%3};"
        : "+f"(c[0]), "+f"(c[1]), "+f"(c[2]), "+f"(c[3])
        : "r"(a0), "r"(a1), "r"(a2), "r"(a3), "r"(b0), "r"(b1));
}
__device__ __forceinline__ uint32_t packbf(float lo, float hi) {
    uint32_t r;
    asm("cvt.rn.bf16x2.f32 %0, %1, %2;" : "=r"(r) : "f"(hi), "f"(lo));
    return r;
}
__device__ __forceinline__ float bf_lo(uint32_t w) { return __uint_as_float(w << 16); }
__device__ __forceinline__ float bf_hi(uint32_t w) { return __uint_as_float(w & 0xffff0000u); }

#define CP_A16(d, s) asm volatile("cp.async.ca.shared.global [%0], [%1], 16;" :: "r"(d), "l"(s))
#define CP_COMMIT()  asm volatile("cp.async.commit_group;" ::: "memory")
#define CP_WAIT1()   asm volatile("cp.async.wait_group 1;" ::: "memory")
#define CP_WAIT0()   asm volatile("cp.async.wait_group 0;" ::: "memory")

__device__ __forceinline__ uint32_t smem_u32(const void* p) {
    uint32_t a;
    asm("{ .reg .u64 t; cvta.to.shared.u64 t, %1; cvt.u32.u64 %0, t; }" : "=r"(a) : "l"(p));
    return a;
}
__device__ __forceinline__ ull enc_key(float f, int idx) {
    uint32_t u = __float_as_uint(f);
    u = (u & 0x80000000u) ? ~u : (u | 0x80000000u);
    return ((ull)u << 32) | (uint32_t)idx;
}
__device__ __forceinline__ float dec_val(ull k) {
    uint32_t e = (uint32_t)(k >> 32);
    uint32_t u = (e & 0x80000000u) ? (e ^ 0x80000000u) : ~e;
    return __uint_as_float(u);
}

__device__ __forceinline__ float blockReduceSum(float v) {
    __shared__ float sw[32];
    int lane = threadIdx.x & 31, w = threadIdx.x >> 5;
    #pragma unroll
    for (int o = 16; o; o >>= 1) v += __shfl_xor_sync(~0u, v, o);
    if (lane == 0) sw[w] = v;
    __syncthreads();
    int nw = (blockDim.x + 31) >> 5;
    v = (threadIdx.x < nw) ? sw[threadIdx.x] : 0.f;
    if (w == 0) {
        #pragma unroll
        for (int o = 16; o; o >>= 1) v += __shfl_xor_sync(~0u, v, o);
    }
    return v;
}

// ---------------- small kernels ----------------
__global__ void k_init() { if (threadIdx.x < 32) g_acc[threadIdx.x] = 0.0; }
__global__ void k_keyinit() {
    int i = blockIdx.x * blockDim.x + threadIdx.x;
    if (i < 2 * B * HW) ((ull*)g_key)[i] = ~0ull;
}

// ---- single pass: f32 spatial -> both bf16 layouts + exact f32 norms ----
// block = 32 m x 8 k-groups; smem word tile [32][C/2] padded to 385
#define PAD   385
#define PKSM  (32 * PAD * 4 + 8 * 32 * 4)   // 50304 B
__global__ void __launch_bounds__(256) k_packall(const float* __restrict__ s1,
                                                 const float* __restrict__ s2) {
    extern __shared__ uint32_t sm[];                 // [32][PAD]
    float* nsum = (float*)(sm + 32 * PAD);           // [8][32]
    int t = blockIdx.y;
    const float* src = t ? s2 : s1;
    int b  = blockIdx.x / (HW / 32);
    int m0 = (blockIdx.x % (HW / 32)) * 32;
    int tid = threadIdx.x, tx = tid & 31, ty = tid >> 5;
    int m = m0 + tx;

    const float* base = src + (size_t)b * C * HW + m;
    float s = 0.f;
    for (int k2 = ty; k2 < C/2; k2 += 8) {
        float v0 = base[(size_t)(2 * k2) * HW];
        float v1 = base[(size_t)(2 * k2 + 1) * HW];
        s += v0 * v0 + v1 * v1;
        sm[tx * PAD + k2] = packbf(v0, v1);
    }
    nsum[ty * 32 + tx] = s;
    __syncthreads();
    if (ty == 0) {
        float tot = 0.f;
        #pragma unroll
        for (int q = 0; q < 8; q++) tot += nsum[q * 32 + tx];
        (t ? g_b2 : g_a2)[b * HW + m] = tot;
    }
    // transposed layout [b][m][k2] — lanes span consecutive k2 (coalesced)
    uint32_t* dstT = g_sbt[t] + ((size_t)b * HW + m0) * (C/2);
    for (int idx = tid; idx < 32 * (C/2); idx += 256) {
        int r = idx / (C/2), k2 = idx % (C/2);
        dstT[(size_t)r * (C/2) + k2] = sm[r * PAD + k2];
    }
    // GEMM layout [b][k2][m] — lanes span consecutive m (coalesced); PAD%32==1 -> no bank conflicts
    uint32_t* dstK = g_sbf[t] + (size_t)b * (C/2) * HW + m0;
    for (int idx = tid; idx < 32 * (C/2); idx += 256) {
        int k2 = idx >> 5, mm = idx & 31;
        dstK[(size_t)k2 * HW + mm] = sm[mm * PAD + k2];
    }
}

// ---------------- bf16 MMA machinery ----------------
#define LDW2   136                 // words/row; 136 % 32 == 8 -> conflict-free
#define MATW2  (16*LDW2)
#define SSTR2  (2*MATW2)
#define GS2    (2 * SSTR2 * 4)     // 34816 B

#define FRAGP(As, Bs, kb2)                                                       \
    {                                                                            \
        uint4 A0 = *(const uint4*)&As[(kb2 + gc    ) * LDW2 + wm      + gr * 4]; \
        uint4 A1 = *(const uint4*)&As[(kb2 + gc + 4) * LDW2 + wm      + gr * 4]; \
        uint4 A2 = *(const uint4*)&As[(kb2 + gc    ) * LDW2 + wm + 32 + gr * 4]; \
        uint4 A3 = *(const uint4*)&As[(kb2 + gc + 4) * LDW2 + wm + 32 + gr * 4]; \
        uint4 B0 = *(const uint4*)&Bs[(kb2 + gc    ) * LDW2 + wn      + gr * 4]; \
        uint4 B1 = *(const uint4*)&Bs[(kb2 + gc + 4) * LDW2 + wn      + gr * 4]; \
        mma_bf16(acc[0][0], A0.x, A0.y, A1.x, A1.y, B0.x, B1.x);                 \
        mma_bf16(acc[0][1], A0.x, A0.y, A1.x, A1.y, B0.y, B1.y);                 \
        mma_bf16(acc[0][2], A0.x, A0.y, A1.x, A1.y, B0.z, B1.z);                 \
        mma_bf16(acc[0][3], A0.x, A0.y, A1.x, A1.y, B0.w, B1.w);                 \
        mma_bf16(acc[1][0], A0.z, A0.w, A1.z, A1.w, B0.x, B1.x);                 \
        mma_bf16(acc[1][1], A0.z, A0.w, A1.z, A1.w, B0.y, B1.y);                 \
        mma_bf16(acc[1][2], A0.z, A0.w, A1.z, A1.w, B0.z, B1.z);                 \
        mma_bf16(acc[1][3], A0.z, A0.w, A1.z, A1.w, B0.w, B1.w);                 \
        mma_bf16(acc[2][0], A2.x, A2.y, A3.x, A3.y, B0.x, B1.x);                 \
        mma_bf16(acc[2][1], A2.x, A2.y, A3.x, A3.y, B0.y, B1.y);                 \
        mma_bf16(acc[2][2], A2.x, A2.y, A3.x, A3.y, B0.z, B1.z);                 \
        mma_bf16(acc[2][3], A2.x, A2.y, A3.x, A3.y, B0.w, B1.w);                 \
        mma_bf16(acc[3][0], A2.z, A2.w, A3.z, A3.w, B0.x, B1.x);                 \
        mma_bf16(acc[3][1], A2.z, A2.w, A3.z, A3.w, B0.y, B1.y);                 \
        mma_bf16(acc[3][2], A2.z, A2.w, A3.z, A3.w, B0.z, B1.z);                 \
        mma_bf16(acc[3][3], A2.z, A2.w, A3.z, A3.w, B0.w, B1.w);                 \
    }

// ---- fused bf16 GEMM + row/col argmin. CTA 128x128, 8 warps (2m x 4n), 2-stage ----
__global__ void __launch_bounds__(256, 2) k_gemm_fused() {
    extern __shared__ uint32_t dyn[];
    int b  = blockIdx.z;
    int m0 = blockIdx.y * 128, n0 = blockIdx.x * 128;
    int tid = threadIdx.x, w = tid >> 5, lane = tid & 31;
    int wm = (w & 1) * 64, wn = (w >> 1) * 32;
    int gr = lane >> 2, gc = lane & 3;

    const uint32_t* Ag = g_sbf[0] + (size_t)b * (C/2) * HW;
    const uint32_t* Bg = g_sbf[1] + (size_t)b * (C/2) * HW;
    uint32_t sbase = smem_u32(dyn);

    int rowv[2], colA[2], colB[2];
    #pragma unroll
    for (int t = 0; t < 2; t++) {
        int v = tid + t * 256;
        rowv[t] = v >> 5;
        int col = (v & 31) * 4;
        int ca = m0 + col; if (ca > HW - 4) ca = HW - 4;
        int cb = n0 + col; if (cb > HW - 4) cb = HW - 4;
        colA[t] = ca; colB[t] = cb;
    }
    auto issue_chunk = [&](int s, int stage) {
        int k20 = s * 16;
        uint32_t sA = sbase + stage * (SSTR2 * 4);
        uint32_t sB = sA + MATW2 * 4;
        #pragma unroll
        for (int t = 0; t < 2; t++) {
            int v = tid + t * 256;
            uint32_t so = ((v >> 5) * LDW2 + (v & 31) * 4) * 4;
            CP_A16(sA + so, (const char*)&Ag[(size_t)(k20 + rowv[t]) * HW + colA[t]]);
            CP_A16(sB + so, (const char*)&Bg[(size_t)(k20 + rowv[t]) * HW + colB[t]]);
        }
        CP_COMMIT();
    };

    float acc[4][4][4] = {};
    issue_chunk(0, 0);
    for (int s = 0; s < NCH; s++) {
        if (s + 1 < NCH) { issue_chunk(s + 1, (s + 1) & 1); CP_WAIT1(); }
        else             { CP_WAIT0(); }
        __syncthreads();
        const uint32_t* As = dyn + (s & 1) * SSTR2;
        const uint32_t* Bs = As + MATW2;
        FRAGP(As, Bs, 0)
        FRAGP(As, Bs, 8)
        __syncthreads();
    }

    // ---- fused argmin epilogue ----
    ull* rkey = (ull*)dyn;
    ull* ckey = rkey + 128;
    if (tid < 128) { rkey[tid] = ~0ull; ckey[tid] = ~0ull; }
    __syncthreads();

    const float* a2p = g_a2 + b * HW;
    const float* b2p = g_b2 + b * HW;

    #pragma unroll
    for (int i = 0; i < 4; i++) {
        int mbase = wm + (i >> 1) * 32 + gr * 4 + (i & 1) * 2;
        #pragma unroll
        for (int half = 0; half < 2; half++) {
            int ml = mbase + half;
            ull rb_ = ~0ull;
            #pragma unroll
            for (int j = 0; j < 4; j++)
                #pragma unroll
                for (int rb = 0; rb < 2; rb++) {
                    int n_g = n0 + wn + 8 * gc + 4 * rb + j;
                    if (n_g < HW) {
                        ull k = enc_key(b2p[n_g] - 2.f * acc[i][j][half * 2 + rb], n_g);
                        if (k < rb_) rb_ = k;
                    }
                }
            if (rb_ != ~0ull) atomicMin(&rkey[ml], rb_);
        }
    }
    #pragma unroll
    for (int j = 0; j < 4; j++)
        #pragma unroll
        for (int rb = 0; rb < 2; rb++) {
            int nl = wn + 8 * gc + 4 * rb + j;
            ull cbest = ~0ull;
            #pragma unroll
            for (int i = 0; i < 4; i++) {
                int mbase = m0 + wm + (i >> 1) * 32 + gr * 4 + (i & 1) * 2;
                #pragma unroll
                for (int half = 0; half < 2; half++) {
                    int m_g = mbase + half;
                    if (m_g < HW) {
                        ull k = enc_key(a2p[m_g] - 2.f * acc[i][j][half * 2 + rb], m_g);
                        if (k < cbest) cbest = k;
                    }
                }
            }
            if (cbest != ~0ull) atomicMin(&ckey[nl], cbest);
        }
    __syncthreads();
    if (tid < 128) {
        int m = m0 + tid;
        if (m < HW) atomicMin(&g_key[0][b * HW + m], rkey[tid]);
    } else {
        int n = n0 + tid - 128;
        if (n < HW) atomicMin(&g_key[1][b * HW + n], ckey[tid - 128]);
    }
}

// ---- bf16 MMA Gram from packed X: S[t] = X^T X, upper 128x128 tiles ----
__global__ void __launch_bounds__(256, 2) k_gram_mma() {
    extern __shared__ uint32_t dyn[];
    int t = blockIdx.y;
    const uint32_t* X = g_Xbf[t];
    int idx = blockIdx.x, ti = 0;
    while (idx >= 6 - ti) { idx -= 6 - ti; ti++; }
    int tj = ti + idx;
    int i0 = ti * 128, j0 = tj * 128;

    int tid = threadIdx.x, w = tid >> 5, lane = tid & 31;
    int wm = (w & 1) * 64, wn = (w >> 1) * 32;
    int gr = lane >> 2, gc = lane & 3;
    uint32_t sbase = smem_u32(dyn);

    auto issue_chunk = [&](int s, int stage) {
        int k20 = s * 16;
        uint32_t sA = sbase + stage * (SSTR2 * 4);
        uint32_t sB = sA + MATW2 * 4;
        #pragma unroll
        for (int tt = 0; tt < 2; tt++) {
            int v = tid + tt * 256;
            int row = v >> 5, col = (v & 31) * 4;
            uint32_t so = (row * LDW2 + col) * 4;
            CP_A16(sA + so, (const char*)&X[(size_t)(k20 + row) * C + i0 + col]);
            CP_A16(sB + so, (const char*)&X[(size_t)(k20 + row) * C + j0 + col]);
        }
        CP_COMMIT();
    };

    float acc[4][4][4] = {};
    issue_chunk(0, 0);
    for (int s = 0; s < NCH2; s++) {
        if (s + 1 < NCH2) { issue_chunk(s + 1, (s + 1) & 1); CP_WAIT1(); }
        else              { CP_WAIT0(); }
        __syncthreads();
        const uint32_t* As = dyn + (s & 1) * SSTR2;
        const uint32_t* Bs = As + MATW2;
        FRAGP(As, Bs, 0)
        FRAGP(As, Bs, 8)
        __syncthreads();
    }

    float* Sp = g_S[t];
    #pragma unroll
    for (int i = 0; i < 4; i++) {
        int mbase = i0 + wm + (i >> 1) * 32 + gr * 4 + (i & 1) * 2;
        #pragma unroll
        for (int half = 0; half < 2; half++)
            #pragma unroll
            for (int rb = 0; rb < 2; rb++) {
                int c2 = j0 + wn + 8 * gc + 4 * rb;
                float4 o = make_float4(acc[i][0][half * 2 + rb], acc[i][1][half * 2 + rb],
                                       acc[i][2][half * 2 + rb], acc[i][3][half * 2 + rb]);
                *(float4*)&Sp[(size_t)(mbase + half) * C + c2] = o;
            }
    }
}

// rank-based top-50 smallest d2 (ties -> lowest index)
__global__ void k_select() {
    int b = blockIdx.x, dir = blockIdx.y;
    __shared__ float sd[HW];
    __shared__ int   sn[HW];
    int i = threadIdx.x;
    ull key = g_key[dir][b * HW + i];
    const float* own = dir ? g_b2 : g_a2;
    float d2 = own[b * HW + i] + dec_val(key);
    if (d2 < 0.f) d2 = 0.f;
    sd[i] = d2;
    sn[i] = (int)(uint32_t)key;
    __syncthreads();
    float di = sd[i];
    int rank = 0;
    for (int j = 0; j < HW; j++) {
        float dj = sd[j];
        rank += (dj < di) || (dj == di && j < i);
    }
    if (rank < NM) {
        g_sel_in[dir][b * NM + rank] = i;
        g_sel_c [dir][b * NM + rank] = sn[i];
    }
}

// gather row PAIRS from transposed bf16 copy (coalesced); inv from bf16 values
__global__ void __launch_bounds__(128) k_gather2() {
    int p = blockIdx.x;            // 0..NSEL/2-1
    int dir = blockIdx.y;
    int r0 = 2 * p, r1 = r0 + 1;
    int b = r0 / NM;               // NM even -> same batch
    const uint32_t* Tin = g_sbt[dir ? 1 : 0];
    const uint32_t* Tc  = g_sbt[dir ? 0 : 1];
    const uint32_t* in0 = Tin + ((size_t)b * HW + g_sel_in[dir][r0]) * (C/2);
    const uint32_t* in1 = Tin + ((size_t)b * HW + g_sel_in[dir][r1]) * (C/2);
    const uint32_t* c0  = Tc  + ((size_t)b * HW + g_sel_c [dir][r0]) * (C/2);
    const uint32_t* c1  = Tc  + ((size_t)b * HW + g_sel_c [dir][r1]) * (C/2);
    uint32_t* Xin = g_Xbf[dir * 2 + 0] + (size_t)p * C;
    uint32_t* Xc  = g_Xbf[dir * 2 + 1] + (size_t)p * C;
    float lsum = 0.f;
    for (int k2 = threadIdx.x; k2 < C/2; k2 += 128) {
        uint32_t wi0 = in0[k2], wi1 = in1[k2];
        uint32_t wc0 = c0[k2],  wc1 = c1[k2];
        ((uint2*)Xin)[k2] = make_uint2(__byte_perm(wi0, wi1, 0x5410),
                                       __byte_perm(wi0, wi1, 0x7632));
        ((uint2*)Xc)[k2]  = make_uint2(__byte_perm(wc0, wc1, 0x5410),
                                       __byte_perm(wc0, wc1, 0x7632));
        float d;
        d = bf_lo(wi0) - bf_lo(wc0); lsum += d * d;
        d = bf_hi(wi0) - bf_hi(wc0); lsum += d * d;
        d = bf_lo(wi1) - bf_lo(wc1); lsum += d * d;
        d = bf_hi(wi1) - bf_hi(wc1); lsum += d * d;
    }
    float tot = blockReduceSum(lsum);
    if (threadIdx.x == 0) atomicAdd(&g_acc[1 + dir], (double)tot);
}

__global__ void k_pooled_inv(const float* __restrict__ p1, const float* __restrict__ p2) {
    float lsum = 0.f;
    for (int i = blockIdx.x * blockDim.x + threadIdx.x; i < B * C; i += gridDim.x * blockDim.x) {
        float d = p1[i] - p2[i]; lsum += d * d;
    }
    float tot = blockReduceSum(lsum);
    if (threadIdx.x == 0) atomicAdd(&g_acc[0], (double)tot);
}

__device__ __forceinline__ int tensor_n(int t) { return (t < 4) ? NSEL : B; }

// column sums: t<4 from packed bf16 X, t>=4 from pooled f32
__global__ void k_colsum_part(const float* __restrict__ p1, const float* __restrict__ p2) {
    int t = blockIdx.x, chunk = blockIdx.y, c = threadIdx.x;
    float s = 0.f;
    if (t < 4) {
        const uint32_t* X = g_Xbf[t];
        int n20 = chunk * (NSEL / 2 / 16), n21 = n20 + NSEL / 2 / 16;
        for (int i = n20; i < n21; i++) {
            uint32_t w = X[(size_t)i * C + c];
            s += bf_lo(w) + bf_hi(w);
        }
    } else {
        const float* X = (t == 4) ? p1 : p2;
        int n0 = chunk * (B / 16), n1 = n0 + B / 16;
        for (int i = n0; i < n1; i++) s += X[(size_t)i * C + c];
    }
    g_csp[t][chunk][c] = s;
}
__global__ void k_colsum_fin() {
    int t = blockIdx.x, c = threadIdx.x;
    float s = 0.f;
    #pragma unroll
    for (int k = 0; k < 16; k++) s += g_csp[t][k][c];
    g_colsum[t][c] = s;
}

// exact fp32 Gram for the 2 pooled tensors (n=64), upper 64x64 tiles
__global__ void __launch_bounds__(256) k_gram(const float* __restrict__ p1,
                                              const float* __restrict__ p2) {
    int t = 4 + blockIdx.y;
    const float* X = (t == 4) ? p1 : p2;
    int n = B;
    int idx = blockIdx.x, ti = 0;
    while (idx >= 12 - ti) { idx -= 12 - ti; ti++; }
    int tj = ti + idx;
    int i0 = ti * 64, j0 = tj * 64;

    __shared__ float As[16][64], Bs[16][64];
    int tid = threadIdx.x;
    int tx = tid & 15, ty = tid >> 4;
    int lk = tid >> 4, lo = (tid & 15) * 4;
    float acc[4][4] = {};
    for (int k0 = 0; k0 < n; k0 += 16) {
        *(float4*)&As[lk][lo] = *(const float4*)&X[(size_t)(k0 + lk) * C + i0 + lo];
        *(float4*)&Bs[lk][lo] = *(const float4*)&X[(size_t)(k0 + lk) * C + j0 + lo];
        __syncthreads();
        #pragma unroll
        for (int kk = 0; kk < 16; kk++) {
            float a[4], bb[4];
            *(float4*)a  = *(float4*)&As[kk][ty * 4];
            *(float4*)bb = *(float4*)&Bs[kk][tx * 4];
            #pragma unroll
            for (int i = 0; i < 4; i++)
                #pragma unroll
                for (int j = 0; j < 4; j++) acc[i][j] += a[i] * bb[j];
        }
        __syncthreads();
    }
    float* Sp = g_S[t];
    #pragma unroll
    for (int i = 0; i < 4; i++) {
        int c1 = i0 + ty * 4 + i;
        *(float4*)&Sp[(size_t)c1 * C + j0 + tx * 4] = *(float4*)acc[i];
    }
}

__global__ void k_std() {
    int t = blockIdx.x, c = threadIdx.x;
    float n  = (float)tensor_n(t);
    float mu = g_colsum[t][c] / n;
    float Scc = g_S[t][(size_t)c * C + c];
    float var = (Scc - n * mu * mu) / (n - 1.f);
    float sd  = sqrtf(var + EPSV);
    float contrib = fmaxf(1.f - sd, 0.f);
    float tot = blockReduceSum(contrib);
    if (threadIdx.x == 0) atomicAdd(&g_acc[3 + t], (double)tot);
}

__global__ void k_cov() {
    int t = blockIdx.y;
    float n = (float)tensor_n(t);
    float inv_nm1 = 1.f / (n - 1.f);
    int idx = blockIdx.x, ti = 0;
    while (idx >= 12 - ti) { idx -= 12 - ti; ti++; }
    int tj = ti + idx;
    int i0 = ti * 64, j0 = tj * 64;
    const float* Sp = g_S[t];
    float lsum = 0.f;
    #pragma unroll
    for (int it = 0; it < 16; it++) {
        int e = it * 256 + threadIdx.x;
        int r = e >> 6, cc = e & 63;
        int c1 = i0 + r, c2 = j0 + cc;
        if (c2 > c1) {
            float mu1 = g_colsum[t][c1] / n;
            float mu2 = g_colsum[t][c2] / n;
            float cov = (Sp[(size_t)c1 * C + c2] - n * mu1 * mu2) * inv_nm1;
            lsum += 2.f * cov * cov;
        }
    }
    float tot = blockReduceSum(lsum);
    if (threadIdx.x == 0) atomicAdd(&g_acc[10 + t], (double)tot);
}

__global__ void k_final(float* __restrict__ out) {
    double inv_g = g_acc[0] / (double)(B * C);
    double inv1  = g_acc[1] / (double)((size_t)NSEL * C);
    double inv2  = g_acc[2] / (double)((size_t)NSEL * C);
    double stdt[6], covt[6];
    for (int t = 0; t < 6; t++) {
        stdt[t] = (g_acc[3 + t] / (double)C) * 0.5;
        covt[t] = g_acc[10 + t] / (double)C;
    }
    double glob = 25.0 * inv_g + 25.0 * (stdt[4] + stdt[5]) + (covt[4] + covt[5]);
    double loc  = 0.5 * (25.0 * inv1 + 25.0 * inv2)
                + 0.5 * (25.0 * (stdt[0] + stdt[1]) + 25.0 * (stdt[2] + stdt[3]))
                + 0.5 * ((covt[0] + covt[1]) + (covt[2] + covt[3]));
    out[0] = (float)(0.5 * glob + 0.5 * loc);
}

// ---------------- launch ----------------
extern "C" void kernel_launch(void* const* d_in, const int* in_sizes, int n_in,
                              void* d_out, int out_size) {
    const float* s1 = (const float*)d_in[0];
    const float* p1 = (const float*)d_in[1];
    const float* s2 = (const float*)d_in[2];
    const float* p2 = (const float*)d_in[3];
    float* out = (float*)d_out;

    cudaFuncSetAttribute(k_packall,    cudaFuncAttributeMaxDynamicSharedMemorySize, PKSM);
    cudaFuncSetAttribute(k_gemm_fused, cudaFuncAttributeMaxDynamicSharedMemorySize, GS2);
    cudaFuncSetAttribute(k_gram_mma,   cudaFuncAttributeMaxDynamicSharedMemorySize, GS2);

    k_init<<<1, 32>>>();
    k_keyinit<<<(2 * B * HW + 255) / 256, 256>>>();
    k_packall<<<dim3(B * (HW / 32), 2), 256, PKSM>>>(s1, s2);
    k_gemm_fused<<<dim3(5, 5, B), 256, GS2>>>();
    k_select<<<dim3(B, 2), HW>>>();
    k_gather2<<<dim3(NSEL / 2, 2), 128>>>();
    k_pooled_inv<<<48, 256>>>(p1, p2);
    k_colsum_part<<<dim3(6, 16), C>>>(p1, p2);
    k_colsum_fin<<<6, C>>>();
    k_gram_mma<<<dim3(21, 4), 256, GS2>>>();
    k_gram<<<dim3(78, 2), 256>>>(p1, p2);
    k_std<<<6, C>>>();
    k_cov<<<dim3(78, 6), 256>>>();
    k_final<<<1, 1>>>(out);
}

// round 14
// speedup vs baseline: 1.7269x; 1.0089x over previous
#include <cuda_runtime.h>
#include <cstdint>
#include <math.h>

#define B    64
#define C    768
#define HW   576
#define NM   50
#define NSEL (B*NM)   // 3200
#define EPSV 1e-5f
#define KC   32
#define NCH  (C/KC)    // 24
#define NCH2 (NSEL/KC) // 100
#define NSPL 4
#define SPLC (NCH2/NSPL) // 25 chunks per split

typedef unsigned long long ull;

// ---------------- scratch ----------------
__device__ float    g_a2[B*HW], g_b2[B*HW];
__device__ ull      g_key[2][B*HW];
__device__ int      g_sel_in[2][NSEL];
__device__ int      g_sel_c [2][NSEL];
__device__ uint32_t g_sbf[2][(size_t)B*(C/2)*HW];      // packed bf16x2 spatial [b][k2][m]  (GEMM layout)
__device__ uint32_t g_sbt[2][(size_t)B*HW*(C/2)];      // packed bf16x2 spatial [b][m][k2]  (gather layout)
__device__ uint32_t g_Xbf[4][(size_t)(NSEL/2)*C];      // packed bf16x2 gathered [n2][c]
__device__ float    g_S[6][(size_t)C*C];
__device__ float    g_Sp[4][NSPL][(size_t)C*C];        // split-K partials for t<4
__device__ float    g_csp[6][16][C];
__device__ float    g_colsum[6][C];
__device__ double   g_acc[32];

// ---------------- helpers ----------------
__device__ __forceinline__ void mma_bf16(float c[4],
                                         uint32_t a0, uint32_t a1, uint32_t a2, uint32_t a3,
                                         uint32_t b0, uint32_t b1) {
    asm volatile(
        "mma.sync.aligned.m16n8k16.row.col.f32.bf16.bf16.f32 "
        "{%0,%1,%2,%3}, {%4,%5,%6,%7}, {%8,%9}, {%0,%1,%2,%3};"
        : "+f"(c[0]), "+f"(c[1]), "+f"(c[2]), "+f"(c[3])
        : "r"(a0), "r"(a1), "r"(a2), "r"(a3), "r"(b0), "r"(b1));
}
__device__ __forceinline__ uint32_t packbf(float lo, float hi) {
    uint32_t r;
    asm("cvt.rn.bf16x2.f32 %0, %1, %2;" : "=r"(r) : "f"(hi), "f"(lo));
    return r;
}
__device__ __forceinline__ float bf_lo(uint32_t w) { return __uint_as_float(w << 16); }
__device__ __forceinline__ float bf_hi(uint32_t w) { return __uint_as_float(w & 0xffff0000u); }

#define CP_CG16(d, s) asm volatile("cp.async.cg.shared.global [%0], [%1], 16;" :: "r"(d), "l"(s))
#define CP_COMMIT()  asm volatile("cp.async.commit_group;" ::: "memory")
#define CP_WAIT1()   asm volatile("cp.async.wait_group 1;" ::: "memory")
#define CP_WAIT0()   asm volatile("cp.async.wait_group 0;" ::: "memory")

__device__ __forceinline__ uint32_t smem_u32(const void* p) {
    uint32_t a;
    asm("{ .reg .u64 t; cvta.to.shared.u64 t, %1; cvt.u32.u64 %0, t; }" : "=r"(a) : "l"(p));
    return a;
}
__device__ __forceinline__ ull enc_key(float f, int idx) {
    uint32_t u = __float_as_uint(f);
    u = (u & 0x80000000u) ? ~u : (u | 0x80000000u);
    return ((ull)u << 32) | (uint32_t)idx;
}
__device__ __forceinline__ float dec_val(ull k) {
    uint32_t e = (uint32_t)(k >> 32);
    uint32_t u = (e & 0x80000000u) ? (e ^ 0x80000000u) : ~e;
    return __uint_as_float(u);
}

__device__ __forceinline__ float blockReduceSum(float v) {
    __shared__ float sw[32];
    int lane = threadIdx.x & 31, w = threadIdx.x >> 5;
    #pragma unroll
    for (int o = 16; o; o >>= 1) v += __shfl_xor_sync(~0u, v, o);
    if (lane == 0) sw[w] = v;
    __syncthreads();
    int nw = (blockDim.x + 31) >> 5;
    v = (threadIdx.x < nw) ? sw[threadIdx.x] : 0.f;
    if (w == 0) {
        #pragma unroll
        for (int o = 16; o; o >>= 1) v += __shfl_xor_sync(~0u, v, o);
    }
    return v;
}

// ---------------- small kernels ----------------
__global__ void k_init() { if (threadIdx.x < 32) g_acc[threadIdx.x] = 0.0; }
__global__ void k_keyinit() {
    int i = blockIdx.x * blockDim.x + threadIdx.x;
    if (i < 2 * B * HW) ((ull*)g_key)[i] = ~0ull;
}

// ---- single pass: f32 spatial -> both bf16 layouts + exact f32 norms ----
#define PAD   385
#define PKSM  (32 * PAD * 4 + 8 * 32 * 4)   // 50304 B
__global__ void __launch_bounds__(256) k_packall(const float* __restrict__ s1,
                                                 const float* __restrict__ s2) {
    extern __shared__ uint32_t sm[];                 // [32][PAD]
    float* nsum = (float*)(sm + 32 * PAD);           // [8][32]
    int t = blockIdx.y;
    const float* src = t ? s2 : s1;
    int b  = blockIdx.x / (HW / 32);
    int m0 = (blockIdx.x % (HW / 32)) * 32;
    int tid = threadIdx.x, tx = tid & 31, ty = tid >> 5;
    int m = m0 + tx;

    const float* base = src + (size_t)b * C * HW + m;
    float s = 0.f;
    for (int k2 = ty; k2 < C/2; k2 += 8) {
        float v0 = base[(size_t)(2 * k2) * HW];
        float v1 = base[(size_t)(2 * k2 + 1) * HW];
        s += v0 * v0 + v1 * v1;
        sm[tx * PAD + k2] = packbf(v0, v1);
    }
    nsum[ty * 32 + tx] = s;
    __syncthreads();
    if (ty == 0) {
        float tot = 0.f;
        #pragma unroll
        for (int q = 0; q < 8; q++) tot += nsum[q * 32 + tx];
        (t ? g_b2 : g_a2)[b * HW + m] = tot;
    }
    uint32_t* dstT = g_sbt[t] + ((size_t)b * HW + m0) * (C/2);
    for (int idx = tid; idx < 32 * (C/2); idx += 256) {
        int r = idx / (C/2), k2 = idx % (C/2);
        dstT[(size_t)r * (C/2) + k2] = sm[r * PAD + k2];
    }
    uint32_t* dstK = g_sbf[t] + (size_t)b * (C/2) * HW + m0;
    for (int idx = tid; idx < 32 * (C/2); idx += 256) {
        int k2 = idx >> 5, mm = idx & 31;
        dstK[(size_t)k2 * HW + mm] = sm[mm * PAD + k2];
    }
}

// ---------------- bf16 MMA machinery ----------------
#define LDW2   136                 // words/row; 136 % 32 == 8 -> conflict-free
#define MATW2  (16*LDW2)
#define SSTR2  (2*MATW2)
#define GS2    (2 * SSTR2 * 4)     // 34816 B

#define FRAGP(As, Bs, kb2)                                                       \
    {                                                                            \
        uint4 A0 = *(const uint4*)&As[(kb2 + gc    ) * LDW2 + wm      + gr * 4]; \
        uint4 A1 = *(const uint4*)&As[(kb2 + gc + 4) * LDW2 + wm      + gr * 4]; \
        uint4 A2 = *(const uint4*)&As[(kb2 + gc    ) * LDW2 + wm + 32 + gr * 4]; \
        uint4 A3 = *(const uint4*)&As[(kb2 + gc + 4) * LDW2 + wm + 32 + gr * 4]; \
        uint4 B0 = *(const uint4*)&Bs[(kb2 + gc    ) * LDW2 + wn      + gr * 4]; \
        uint4 B1 = *(const uint4*)&Bs[(kb2 + gc + 4) * LDW2 + wn      + gr * 4]; \
        mma_bf16(acc[0][0], A0.x, A0.y, A1.x, A1.y, B0.x, B1.x);                 \
        mma_bf16(acc[0][1], A0.x, A0.y, A1.x, A1.y, B0.y, B1.y);                 \
        mma_bf16(acc[0][2], A0.x, A0.y, A1.x, A1.y, B0.z, B1.z);                 \
        mma_bf16(acc[0][3], A0.x, A0.y, A1.x, A1.y, B0.w, B1.w);                 \
        mma_bf16(acc[1][0], A0.z, A0.w, A1.z, A1.w, B0.x, B1.x);                 \
        mma_bf16(acc[1][1], A0.z, A0.w, A1.z, A1.w, B0.y, B1.y);                 \
        mma_bf16(acc[1][2], A0.z, A0.w, A1.z, A1.w, B0.z, B1.z);                 \
        mma_bf16(acc[1][3], A0.z, A0.w, A1.z, A1.w, B0.w, B1.w);                 \
        mma_bf16(acc[2][0], A2.x, A2.y, A3.x, A3.y, B0.x, B1.x);                 \
        mma_bf16(acc[2][1], A2.x, A2.y, A3.x, A3.y, B0.y, B1.y);                 \
        mma_bf16(acc[2][2], A2.x, A2.y, A3.x, A3.y, B0.z, B1.z);                 \
        mma_bf16(acc[2][3], A2.x, A2.y, A3.x, A3.y, B0.w, B1.w);                 \
        mma_bf16(acc[3][0], A2.z, A2.w, A3.z, A3.w, B0.x, B1.x);                 \
        mma_bf16(acc[3][1], A2.z, A2.w, A3.z, A3.w, B0.y, B1.y);                 \
        mma_bf16(acc[3][2], A2.z, A2.w, A3.z, A3.w, B0.z, B1.z);                 \
        mma_bf16(acc[3][3], A2.z, A2.w, A3.z, A3.w, B0.w, B1.w);                 \
    }

// ---- fused bf16 GEMM + row/col argmin. CTA 128x128, 8 warps (2m x 4n), 2-stage ----
__global__ void __launch_bounds__(256, 2) k_gemm_fused() {
    extern __shared__ uint32_t dyn[];
    int b  = blockIdx.z;
    int m0 = blockIdx.y * 128, n0 = blockIdx.x * 128;
    int tid = threadIdx.x, w = tid >> 5, lane = tid & 31;
    int wm = (w & 1) * 64, wn = (w >> 1) * 32;
    int gr = lane >> 2, gc = lane & 3;

    const uint32_t* Ag = g_sbf[0] + (size_t)b * (C/2) * HW;
    const uint32_t* Bg = g_sbf[1] + (size_t)b * (C/2) * HW;
    uint32_t sbase = smem_u32(dyn);

    int rowv[2], colA[2], colB[2];
    #pragma unroll
    for (int t = 0; t < 2; t++) {
        int v = tid + t * 256;
        rowv[t] = v >> 5;
        int col = (v & 31) * 4;
        int ca = m0 + col; if (ca > HW - 4) ca = HW - 4;
        int cb = n0 + col; if (cb > HW - 4) cb = HW - 4;
        colA[t] = ca; colB[t] = cb;
    }
    auto issue_chunk = [&](int s, int stage) {
        int k20 = s * 16;
        uint32_t sA = sbase + stage * (SSTR2 * 4);
        uint32_t sB = sA + MATW2 * 4;
        #pragma unroll
        for (int t = 0; t < 2; t++) {
            int v = tid + t * 256;
            uint32_t so = ((v >> 5) * LDW2 + (v & 31) * 4) * 4;
            CP_CG16(sA + so, (const char*)&Ag[(size_t)(k20 + rowv[t]) * HW + colA[t]]);
            CP_CG16(sB + so, (const char*)&Bg[(size_t)(k20 + rowv[t]) * HW + colB[t]]);
        }
        CP_COMMIT();
    };

    float acc[4][4][4] = {};
    issue_chunk(0, 0);
    for (int s = 0; s < NCH; s++) {
        if (s + 1 < NCH) { issue_chunk(s + 1, (s + 1) & 1); CP_WAIT1(); }
        else             { CP_WAIT0(); }
        __syncthreads();
        const uint32_t* As = dyn + (s & 1) * SSTR2;
        const uint32_t* Bs = As + MATW2;
        FRAGP(As, Bs, 0)
        FRAGP(As, Bs, 8)
        __syncthreads();
    }

    // ---- fused argmin epilogue ----
    ull* rkey = (ull*)dyn;
    ull* ckey = rkey + 128;
    if (tid < 128) { rkey[tid] = ~0ull; ckey[tid] = ~0ull; }
    __syncthreads();

    const float* a2p = g_a2 + b * HW;
    const float* b2p = g_b2 + b * HW;

    #pragma unroll
    for (int i = 0; i < 4; i++) {
        int mbase = wm + (i >> 1) * 32 + gr * 4 + (i & 1) * 2;
        #pragma unroll
        for (int half = 0; half < 2; half++) {
            int ml = mbase + half;
            ull rb_ = ~0ull;
            #pragma unroll
            for (int j = 0; j < 4; j++)
                #pragma unroll
                for (int rb = 0; rb < 2; rb++) {
                    int n_g = n0 + wn + 8 * gc + 4 * rb + j;
                    if (n_g < HW) {
                        ull k = enc_key(b2p[n_g] - 2.f * acc[i][j][half * 2 + rb], n_g);
                        if (k < rb_) rb_ = k;
                    }
                }
            if (rb_ != ~0ull) atomicMin(&rkey[ml], rb_);
        }
    }
    #pragma unroll
    for (int j = 0; j < 4; j++)
        #pragma unroll
        for (int rb = 0; rb < 2; rb++) {
            int nl = wn + 8 * gc + 4 * rb + j;
            ull cbest = ~0ull;
            #pragma unroll
            for (int i = 0; i < 4; i++) {
                int mbase = m0 + wm + (i >> 1) * 32 + gr * 4 + (i & 1) * 2;
                #pragma unroll
                for (int half = 0; half < 2; half++) {
                    int m_g = mbase + half;
                    if (m_g < HW) {
                        ull k = enc_key(a2p[m_g] - 2.f * acc[i][j][half * 2 + rb], m_g);
                        if (k < cbest) cbest = k;
                    }
                }
            }
            if (cbest != ~0ull) atomicMin(&ckey[nl], cbest);
        }
    __syncthreads();
    if (tid < 128) {
        int m = m0 + tid;
        if (m < HW) atomicMin(&g_key[0][b * HW + m], rkey[tid]);
    } else {
        int n = n0 + tid - 128;
        if (n < HW) atomicMin(&g_key[1][b * HW + n], ckey[tid - 128]);
    }
}

// ---- split-K bf16 MMA Gram: partial S over 25-chunk k-range per split ----
// stage indexing is RELATIVE to s0 (fixes R13 parity bug for odd splits)
__global__ void __launch_bounds__(256, 2) k_gram_mma() {
    extern __shared__ uint32_t dyn[];
    int t   = blockIdx.y & 3;
    int spl = blockIdx.y >> 2;
    const uint32_t* X = g_Xbf[t];
    int idx = blockIdx.x, ti = 0;
    while (idx >= 6 - ti) { idx -= 6 - ti; ti++; }
    int tj = ti + idx;
    int i0 = ti * 128, j0 = tj * 128;

    int tid = threadIdx.x, w = tid >> 5, lane = tid & 31;
    int wm = (w & 1) * 64, wn = (w >> 1) * 32;
    int gr = lane >> 2, gc = lane & 3;
    uint32_t sbase = smem_u32(dyn);

    int s0 = spl * SPLC;
    auto issue_chunk = [&](int r, int stage) {    // r = relative chunk
        int k20 = (s0 + r) * 16;
        uint32_t sA = sbase + stage * (SSTR2 * 4);
        uint32_t sB = sA + MATW2 * 4;
        #pragma unroll
        for (int tt = 0; tt < 2; tt++) {
            int v = tid + tt * 256;
            int row = v >> 5, col = (v & 31) * 4;
            uint32_t so = (row * LDW2 + col) * 4;
            CP_CG16(sA + so, (const char*)&X[(size_t)(k20 + row) * C + i0 + col]);
            CP_CG16(sB + so, (const char*)&X[(size_t)(k20 + row) * C + j0 + col]);
        }
        CP_COMMIT();
    };

    float acc[4][4][4] = {};
    issue_chunk(0, 0);
    for (int r = 0; r < SPLC; r++) {
        if (r + 1 < SPLC) { issue_chunk(r + 1, (r + 1) & 1); CP_WAIT1(); }
        else              { CP_WAIT0(); }
        __syncthreads();
        const uint32_t* As = dyn + (r & 1) * SSTR2;
        const uint32_t* Bs = As + MATW2;
        FRAGP(As, Bs, 0)
        FRAGP(As, Bs, 8)
        __syncthreads();
    }

    float* Sp = g_Sp[t][spl];
    #pragma unroll
    for (int i = 0; i < 4; i++) {
        int mbase = i0 + wm + (i >> 1) * 32 + gr * 4 + (i & 1) * 2;
        #pragma unroll
        for (int half = 0; half < 2; half++)
            #pragma unroll
            for (int rb = 0; rb < 2; rb++) {
                int c2 = j0 + wn + 8 * gc + 4 * rb;
                float4 o = make_float4(acc[i][0][half * 2 + rb], acc[i][1][half * 2 + rb],
                                       acc[i][2][half * 2 + rb], acc[i][3][half * 2 + rb]);
                *(float4*)&Sp[(size_t)(mbase + half) * C + c2] = o;
            }
    }
}

// reduce split partials into g_S[t]
__global__ void k_sred() {
    int t = blockIdx.y;
    size_t i = (size_t)blockIdx.x * 256 + threadIdx.x;
    float s = g_Sp[t][0][i] + g_Sp[t][1][i] + g_Sp[t][2][i] + g_Sp[t][3][i];
    g_S[t][i] = s;
}

// rank-based top-50 smallest d2 (ties -> lowest index)
__global__ void k_select() {
    int b = blockIdx.x, dir = blockIdx.y;
    __shared__ float sd[HW];
    __shared__ int   sn[HW];
    int i = threadIdx.x;
    ull key = g_key[dir][b * HW + i];
    const float* own = dir ? g_b2 : g_a2;
    float d2 = own[b * HW + i] + dec_val(key);
    if (d2 < 0.f) d2 = 0.f;
    sd[i] = d2;
    sn[i] = (int)(uint32_t)key;
    __syncthreads();
    float di = sd[i];
    int rank = 0;
    for (int j = 0; j < HW; j++) {
        float dj = sd[j];
        rank += (dj < di) || (dj == di && j < i);
    }
    if (rank < NM) {
        g_sel_in[dir][b * NM + rank] = i;
        g_sel_c [dir][b * NM + rank] = sn[i];
    }
}

// gather row PAIRS from transposed bf16 copy (coalesced); inv from bf16 values
__global__ void __launch_bounds__(128) k_gather2() {
    int p = blockIdx.x;
    int dir = blockIdx.y;
    int r0 = 2 * p, r1 = r0 + 1;
    int b = r0 / NM;
    const uint32_t* Tin = g_sbt[dir ? 1 : 0];
    const uint32_t* Tc  = g_sbt[dir ? 0 : 1];
    const uint32_t* in0 = Tin + ((size_t)b * HW + g_sel_in[dir][r0]) * (C/2);
    const uint32_t* in1 = Tin + ((size_t)b * HW + g_sel_in[dir][r1]) * (C/2);
    const uint32_t* c0  = Tc  + ((size_t)b * HW + g_sel_c [dir][r0]) * (C/2);
    const uint32_t* c1  = Tc  + ((size_t)b * HW + g_sel_c [dir][r1]) * (C/2);
    uint32_t* Xin = g_Xbf[dir * 2 + 0] + (size_t)p * C;
    uint32_t* Xc  = g_Xbf[dir * 2 + 1] + (size_t)p * C;
    float lsum = 0.f;
    for (int k2 = threadIdx.x; k2 < C/2; k2 += 128) {
        uint32_t wi0 = in0[k2], wi1 = in1[k2];
        uint32_t wc0 = c0[k2],  wc1 = c1[k2];
        ((uint2*)Xin)[k2] = make_uint2(__byte_perm(wi0, wi1, 0x5410),
                                       __byte_perm(wi0, wi1, 0x7632));
        ((uint2*)Xc)[k2]  = make_uint2(__byte_perm(wc0, wc1, 0x5410),
                                       __byte_perm(wc0, wc1, 0x7632));
        float d;
        d = bf_lo(wi0) - bf_lo(wc0); lsum += d * d;
        d = bf_hi(wi0) - bf_hi(wc0); lsum += d * d;
        d = bf_lo(wi1) - bf_lo(wc1); lsum += d * d;
        d = bf_hi(wi1) - bf_hi(wc1); lsum += d * d;
    }
    float tot = blockReduceSum(lsum);
    if (threadIdx.x == 0) atomicAdd(&g_acc[1 + dir], (double)tot);
}

__global__ void k_pooled_inv(const float* __restrict__ p1, const float* __restrict__ p2) {
    float lsum = 0.f;
    for (int i = blockIdx.x * blockDim.x + threadIdx.x; i < B * C; i += gridDim.x * blockDim.x) {
        float d = p1[i] - p2[i]; lsum += d * d;
    }
    float tot = blockReduceSum(lsum);
    if (threadIdx.x == 0) atomicAdd(&g_acc[0], (double)tot);
}

__device__ __forceinline__ int tensor_n(int t) { return (t < 4) ? NSEL : B; }

// column sums: t<4 from packed bf16 X, t>=4 from pooled f32
__global__ void k_colsum_part(const float* __restrict__ p1, const float* __restrict__ p2) {
    int t = blockIdx.x, chunk = blockIdx.y, c = threadIdx.x;
    float s = 0.f;
    if (t < 4) {
        const uint32_t* X = g_Xbf[t];
        int n20 = chunk * (NSEL / 2 / 16), n21 = n20 + NSEL / 2 / 16;
        for (int i = n20; i < n21; i++) {
            uint32_t w = X[(size_t)i * C + c];
            s += bf_lo(w) + bf_hi(w);
        }
    } else {
        const float* X = (t == 4) ? p1 : p2;
        int n0 = chunk * (B / 16), n1 = n0 + B / 16;
        for (int i = n0; i < n1; i++) s += X[(size_t)i * C + c];
    }
    g_csp[t][chunk][c] = s;
}
__global__ void k_colsum_fin() {
    int t = blockIdx.x, c = threadIdx.x;
    float s = 0.f;
    #pragma unroll
    for (int k = 0; k < 16; k++) s += g_csp[t][k][c];
    g_colsum[t][c] = s;
}

// exact fp32 Gram for the 2 pooled tensors (n=64), upper 64x64 tiles
__global__ void __launch_bounds__(256) k_gram(const float* __restrict__ p1,
                                              const float* __restrict__ p2) {
    int t = 4 + blockIdx.y;
    const float* X = (t == 4) ? p1 : p2;
    int n = B;
    int idx = blockIdx.x, ti = 0;
    while (idx >= 12 - ti) { idx -= 12 - ti; ti++; }
    int tj = ti + idx;
    int i0 = ti * 64, j0 = tj * 64;

    __shared__ float As[16][64], Bs[16][64];
    int tid = threadIdx.x;
    int tx = tid & 15, ty = tid >> 4;
    int lk = tid >> 4, lo = (tid & 15) * 4;
    float acc[4][4] = {};
    for (int k0 = 0; k0 < n; k0 += 16) {
        *(float4*)&As[lk][lo] = *(const float4*)&X[(size_t)(k0 + lk) * C + i0 + lo];
        *(float4*)&Bs[lk][lo] = *(const float4*)&X[(size_t)(k0 + lk) * C + j0 + lo];
        __syncthreads();
        #pragma unroll
        for (int kk = 0; kk < 16; kk++) {
            float a[4], bb[4];
            *(float4*)a  = *(float4*)&As[kk][ty * 4];
            *(float4*)bb = *(float4*)&Bs[kk][tx * 4];
            #pragma unroll
            for (int i = 0; i < 4; i++)
                #pragma unroll
                for (int j = 0; j < 4; j++) acc[i][j] += a[i] * bb[j];
        }
        __syncthreads();
    }
    float* Sp = g_S[t];
    #pragma unroll
    for (int i = 0; i < 4; i++) {
        int c1 = i0 + ty * 4 + i;
        *(float4*)&Sp[(size_t)c1 * C + j0 + tx * 4] = *(float4*)acc[i];
    }
}

__global__ void k_std() {
    int t = blockIdx.x, c = threadIdx.x;
    float n  = (float)tensor_n(t);
    float mu = g_colsum[t][c] / n;
    float Scc = g_S[t][(size_t)c * C + c];
    float var = (Scc - n * mu * mu) / (n - 1.f);
    float sd  = sqrtf(var + EPSV);
    float contrib = fmaxf(1.f - sd, 0.f);
    float tot = blockReduceSum(contrib);
    if (threadIdx.x == 0) atomicAdd(&g_acc[3 + t], (double)tot);
}

__global__ void k_cov() {
    int t = blockIdx.y;
    float n = (float)tensor_n(t);
    float inv_nm1 = 1.f / (n - 1.f);
    int idx = blockIdx.x, ti = 0;
    while (idx >= 12 - ti) { idx -= 12 - ti; ti++; }
    int tj = ti + idx;
    int i0 = ti * 64, j0 = tj * 64;
    const float* Sp = g_S[t];
    float lsum = 0.f;
    #pragma unroll
    for (int it = 0; it < 16; it++) {
        int e = it * 256 + threadIdx.x;
        int r = e >> 6, cc = e & 63;
        int c1 = i0 + r, c2 = j0 + cc;
        if (c2 > c1) {
            float mu1 = g_colsum[t][c1] / n;
            float mu2 = g_colsum[t][c2] / n;
            float cov = (Sp[(size_t)c1 * C + c2] - n * mu1 * mu2) * inv_nm1;
            lsum += 2.f * cov * cov;
        }
    }
    float tot = blockReduceSum(lsum);
    if (threadIdx.x == 0) atomicAdd(&g_acc[10 + t], (double)tot);
}

__global__ void k_final(float* __restrict__ out) {
    double inv_g = g_acc[0] / (double)(B * C);
    double inv1  = g_acc[1] / (double)((size_t)NSEL * C);
    double inv2  = g_acc[2] / (double)((size_t)NSEL * C);
    double stdt[6], covt[6];
    for (int t = 0; t < 6; t++) {
        stdt[t] = (g_acc[3 + t] / (double)C) * 0.5;
        covt[t] = g_acc[10 + t] / (double)C;
    }
    double glob = 25.0 * inv_g + 25.0 * (stdt[4] + stdt[5]) + (covt[4] + covt[5]);
    double loc  = 0.5 * (25.0 * inv1 + 25.0 * inv2)
                + 0.5 * (25.0 * (stdt[0] + stdt[1]) + 25.0 * (stdt[2] + stdt[3]))
                + 0.5 * ((covt[0] + covt[1]) + (covt[2] + covt[3]));
    out[0] = (float)(0.5 * glob + 0.5 * loc);
}

// ---------------- launch ----------------
extern "C" void kernel_launch(void* const* d_in, const int* in_sizes, int n_in,
                              void* d_out, int out_size) {
    const float* s1 = (const float*)d_in[0];
    const float* p1 = (const float*)d_in[1];
    const float* s2 = (const float*)d_in[2];
    const float* p2 = (const float*)d_in[3];
    float* out = (float*)d_out;

    cudaFuncSetAttribute(k_packall,    cudaFuncAttributeMaxDynamicSharedMemorySize, PKSM);
    cudaFuncSetAttribute(k_gemm_fused, cudaFuncAttributeMaxDynamicSharedMemorySize, GS2);
    cudaFuncSetAttribute(k_gram_mma,   cudaFuncAttributeMaxDynamicSharedMemorySize, GS2);

    k_init<<<1, 32>>>();
    k_keyinit<<<(2 * B * HW + 255) / 256, 256>>>();
    k_packall<<<dim3(B * (HW / 32), 2), 256, PKSM>>>(s1, s2);
    k_gemm_fused<<<dim3(5, 5, B), 256, GS2>>>();
    k_select<<<dim3(B, 2), HW>>>();
    k_gather2<<<dim3(NSEL / 2, 2), 128>>>();
    k_pooled_inv<<<48, 256>>>(p1, p2);
    k_colsum_part<<<dim3(6, 16), C>>>(p1, p2);
    k_colsum_fin<<<6, C>>>();
    k_gram_mma<<<dim3(21, 4 * NSPL), 256, GS2>>>();
    k_sred<<<dim3(C * C / 256, 4), 256>>>();
    k_gram<<<dim3(78, 2), 256>>>(p1, p2);
    k_std<<<6, C>>>();
    k_cov<<<dim3(78, 6), 256>>>();
    k_final<<<1, 1>>>(out);
}

// round 15
// speedup vs baseline: 1.8351x; 1.0627x over previous
#include <cuda_runtime.h>
#include <cstdint>
#include <math.h>

#define B    64
#define C    768
#define HW   576
#define NM   50
#define NSEL (B*NM)   // 3200
#define EPSV 1e-5f
#define KC   32
#define NCH  (C/KC)    // 24
#define NCH2 (NSEL/KC) // 100
#define NSPL 4
#define SPLC (NCH2/NSPL) // 25

typedef unsigned long long ull;

// ---------------- scratch ----------------
__device__ float    g_a2[B*HW], g_b2[B*HW];
__device__ ull      g_key[2][B*HW];
__device__ int      g_sel_in[2][NSEL];
__device__ int      g_sel_c [2][NSEL];
__device__ uint32_t g_sbf[2][(size_t)B*(C/2)*HW];      // packed bf16x2 spatial [b][k2][m]
__device__ uint32_t g_sbt[2][(size_t)B*HW*(C/2)];      // packed bf16x2 spatial [b][m][k2]
__device__ uint32_t g_Xbf[4][(size_t)(NSEL/2)*C];      // packed bf16x2 gathered [n2][c]
__device__ float    g_S[6][(size_t)C*C];
__device__ float    g_Sp[4][NSPL][(size_t)C*C];
__device__ float    g_csp[6][16][C];
__device__ float    g_colsum[6][C];
__device__ double   g_acc[32];

// ---------------- helpers ----------------
__device__ __forceinline__ void mma_bf16(float c[4],
                                         uint32_t a0, uint32_t a1, uint32_t a2, uint32_t a3,
                                         uint32_t b0, uint32_t b1) {
    asm volatile(
        "mma.sync.aligned.m16n8k16.row.col.f32.bf16.bf16.f32 "
        "{%0,%1,%2,%3}, {%4,%5,%6,%7}, {%8,%9}, {%0,%1,%2,%3};"
        : "+f"(c[0]), "+f"(c[1]), "+f"(c[2]), "+f"(c[3])
        : "r"(a0), "r"(a1), "r"(a2), "r"(a3), "r"(b0), "r"(b1));
}
__device__ __forceinline__ uint32_t packbf(float lo, float hi) {
    uint32_t r;
    asm("cvt.rn.bf16x2.f32 %0, %1, %2;" : "=r"(r) : "f"(hi), "f"(lo));
    return r;
}
__device__ __forceinline__ float bf_lo(uint32_t w) { return __uint_as_float(w << 16); }
__device__ __forceinline__ float bf_hi(uint32_t w) { return __uint_as_float(w & 0xffff0000u); }

#define CP_CG16(d, s) asm volatile("cp.async.cg.shared.global [%0], [%1], 16;" :: "r"(d), "l"(s))
#define CP_COMMIT()  asm volatile("cp.async.commit_group;" ::: "memory")
#define CP_WAIT1()   asm volatile("cp.async.wait_group 1;" ::: "memory")
#define CP_WAIT0()   asm volatile("cp.async.wait_group 0;" ::: "memory")

__device__ __forceinline__ uint32_t smem_u32(const void* p) {
    uint32_t a;
    asm("{ .reg .u64 t; cvta.to.shared.u64 t, %1; cvt.u32.u64 %0, t; }" : "=r"(a) : "l"(p));
    return a;
}
__device__ __forceinline__ ull enc_key(float f, int idx) {
    uint32_t u = __float_as_uint(f);
    u = (u & 0x80000000u) ? ~u : (u | 0x80000000u);
    return ((ull)u << 32) | (uint32_t)idx;
}
__device__ __forceinline__ float dec_val(ull k) {
    uint32_t e = (uint32_t)(k >> 32);
    uint32_t u = (e & 0x80000000u) ? (e ^ 0x80000000u) : ~e;
    return __uint_as_float(u);
}

__device__ __forceinline__ float blockReduceSum(float v) {
    __shared__ float sw[32];
    int lane = threadIdx.x & 31, w = threadIdx.x >> 5;
    #pragma unroll
    for (int o = 16; o; o >>= 1) v += __shfl_xor_sync(~0u, v, o);
    if (lane == 0) sw[w] = v;
    __syncthreads();
    int nw = (blockDim.x + 31) >> 5;
    v = (threadIdx.x < nw) ? sw[threadIdx.x] : 0.f;
    if (w == 0) {
        #pragma unroll
        for (int o = 16; o; o >>= 1) v += __shfl_xor_sync(~0u, v, o);
    }
    return v;
}

// ---------------- small kernels ----------------
__global__ void k_init() {
    int i = blockIdx.x * blockDim.x + threadIdx.x;
    if (i < 2 * B * HW) ((ull*)g_key)[i] = ~0ull;
    if (blockIdx.x == 0 && threadIdx.x < 32) g_acc[threadIdx.x] = 0.0;
}

// ---- single pass: f32 spatial -> both bf16 layouts + exact f32 norms ----
#define PAD   385
#define PKSM  (32 * PAD * 4 + 8 * 32 * 4)   // 50304 B
__global__ void __launch_bounds__(256) k_packall(const float* __restrict__ s1,
                                                 const float* __restrict__ s2) {
    extern __shared__ uint32_t sm[];                 // [32][PAD]
    float* nsum = (float*)(sm + 32 * PAD);           // [8][32]
    int t = blockIdx.y;
    const float* src = t ? s2 : s1;
    int b  = blockIdx.x / (HW / 32);
    int m0 = (blockIdx.x % (HW / 32)) * 32;
    int tid = threadIdx.x, tx = tid & 31, ty = tid >> 5;
    int m = m0 + tx;

    const float* base = src + (size_t)b * C * HW + m;
    float s = 0.f;
    for (int k2 = ty; k2 < C/2; k2 += 8) {
        float v0 = base[(size_t)(2 * k2) * HW];
        float v1 = base[(size_t)(2 * k2 + 1) * HW];
        s += v0 * v0 + v1 * v1;
        sm[tx * PAD + k2] = packbf(v0, v1);
    }
    nsum[ty * 32 + tx] = s;
    __syncthreads();
    if (ty == 0) {
        float tot = 0.f;
        #pragma unroll
        for (int q = 0; q < 8; q++) tot += nsum[q * 32 + tx];
        (t ? g_b2 : g_a2)[b * HW + m] = tot;
    }
    uint32_t* dstT = g_sbt[t] + ((size_t)b * HW + m0) * (C/2);
    for (int idx = tid; idx < 32 * (C/2); idx += 256) {
        int r = idx / (C/2), k2 = idx % (C/2);
        dstT[(size_t)r * (C/2) + k2] = sm[r * PAD + k2];
    }
    uint32_t* dstK = g_sbf[t] + (size_t)b * (C/2) * HW + m0;
    for (int idx = tid; idx < 32 * (C/2); idx += 256) {
        int k2 = idx >> 5, mm = idx & 31;
        dstK[(size_t)k2 * HW + mm] = sm[mm * PAD + k2];
    }
}

// ---------------- bf16 MMA machinery ----------------
#define LDW2   136                 // words/row; 136 % 32 == 8 -> conflict-free
#define MATW2  (16*LDW2)
#define SSTR2  (2*MATW2)
#define GS2    (2 * SSTR2 * 4)     // 34816 B

// full 128m x 32n fragment step (used by gram)
#define FRAGP(As, Bs, kb2)                                                       \
    {                                                                            \
        uint4 A0 = *(const uint4*)&As[(kb2 + gc    ) * LDW2 + wm      + gr * 4]; \
        uint4 A1 = *(const uint4*)&As[(kb2 + gc + 4) * LDW2 + wm      + gr * 4]; \
        uint4 A2 = *(const uint4*)&As[(kb2 + gc    ) * LDW2 + wm + 32 + gr * 4]; \
        uint4 A3 = *(const uint4*)&As[(kb2 + gc + 4) * LDW2 + wm + 32 + gr * 4]; \
        uint4 B0 = *(const uint4*)&Bs[(kb2 + gc    ) * LDW2 + wn      + gr * 4]; \
        uint4 B1 = *(const uint4*)&Bs[(kb2 + gc + 4) * LDW2 + wn      + gr * 4]; \
        mma_bf16(acc[0][0], A0.x, A0.y, A1.x, A1.y, B0.x, B1.x);                 \
        mma_bf16(acc[0][1], A0.x, A0.y, A1.x, A1.y, B0.y, B1.y);                 \
        mma_bf16(acc[0][2], A0.x, A0.y, A1.x, A1.y, B0.z, B1.z);                 \
        mma_bf16(acc[0][3], A0.x, A0.y, A1.x, A1.y, B0.w, B1.w);                 \
        mma_bf16(acc[1][0], A0.z, A0.w, A1.z, A1.w, B0.x, B1.x);                 \
        mma_bf16(acc[1][1], A0.z, A0.w, A1.z, A1.w, B0.y, B1.y);                 \
        mma_bf16(acc[1][2], A0.z, A0.w, A1.z, A1.w, B0.z, B1.z);                 \
        mma_bf16(acc[1][3], A0.z, A0.w, A1.z, A1.w, B0.w, B1.w);                 \
        mma_bf16(acc[2][0], A2.x, A2.y, A3.x, A3.y, B0.x, B1.x);                 \
        mma_bf16(acc[2][1], A2.x, A2.y, A3.x, A3.y, B0.y, B1.y);                 \
        mma_bf16(acc[2][2], A2.x, A2.y, A3.x, A3.y, B0.z, B1.z);                 \
        mma_bf16(acc[2][3], A2.x, A2.y, A3.x, A3.y, B0.w, B1.w);                 \
        mma_bf16(acc[3][0], A2.z, A2.w, A3.z, A3.w, B0.x, B1.x);                 \
        mma_bf16(acc[3][1], A2.z, A2.w, A3.z, A3.w, B0.y, B1.y);                 \
        mma_bf16(acc[3][2], A2.z, A2.w, A3.z, A3.w, B0.z, B1.z);                 \
        mma_bf16(acc[3][3], A2.z, A2.w, A3.z, A3.w, B0.w, B1.w);                 \
    }

// 96m x 32n fragment step (gemm): 3 m-frags; frag2 via uint2 at wm+32+gr*2
#define FRAGP96(As, Bs, kb2)                                                     \
    {                                                                            \
        uint4 A0 = *(const uint4*)&As[(kb2 + gc    ) * LDW2 + wm      + gr * 4]; \
        uint4 A2 = *(const uint4*)&As[(kb2 + gc + 4) * LDW2 + wm      + gr * 4]; \
        uint2 A1 = *(const uint2*)&As[(kb2 + gc    ) * LDW2 + wm + 32 + gr * 2]; \
        uint2 A3 = *(const uint2*)&As[(kb2 + gc + 4) * LDW2 + wm + 32 + gr * 2]; \
        uint4 B0 = *(const uint4*)&Bs[(kb2 + gc    ) * LDW2 + wn      + gr * 4]; \
        uint4 B1 = *(const uint4*)&Bs[(kb2 + gc + 4) * LDW2 + wn      + gr * 4]; \
        mma_bf16(acc[0][0], A0.x, A0.y, A2.x, A2.y, B0.x, B1.x);                 \
        mma_bf16(acc[0][1], A0.x, A0.y, A2.x, A2.y, B0.y, B1.y);                 \
        mma_bf16(acc[0][2], A0.x, A0.y, A2.x, A2.y, B0.z, B1.z);                 \
        mma_bf16(acc[0][3], A0.x, A0.y, A2.x, A2.y, B0.w, B1.w);                 \
        mma_bf16(acc[1][0], A0.z, A0.w, A2.z, A2.w, B0.x, B1.x);                 \
        mma_bf16(acc[1][1], A0.z, A0.w, A2.z, A2.w, B0.y, B1.y);                 \
        mma_bf16(acc[1][2], A0.z, A0.w, A2.z, A2.w, B0.z, B1.z);                 \
        mma_bf16(acc[1][3], A0.z, A0.w, A2.z, A2.w, B0.w, B1.w);                 \
        mma_bf16(acc[2][0], A1.x, A1.y, A3.x, A3.y, B0.x, B1.x);                 \
        mma_bf16(acc[2][1], A1.x, A1.y, A3.x, A3.y, B0.y, B1.y);                 \
        mma_bf16(acc[2][2], A1.x, A1.y, A3.x, A3.y, B0.z, B1.z);                 \
        mma_bf16(acc[2][3], A1.x, A1.y, A3.x, A3.y, B0.w, B1.w);                 \
    }

// ---- fused bf16 GEMM + argmin. CTA 96x128 (m exact: 6*96=576), 8 warps (2m x 4n) ----
__global__ void __launch_bounds__(256, 2) k_gemm_fused() {
    extern __shared__ uint32_t dyn[];
    int b  = blockIdx.z;
    int m0 = blockIdx.y * 96, n0 = blockIdx.x * 128;
    int tid = threadIdx.x, w = tid >> 5, lane = tid & 31;
    int wm = (w & 1) * 48, wn = (w >> 1) * 32;
    int gr = lane >> 2, gc = lane & 3;

    const uint32_t* Ag = g_sbf[0] + (size_t)b * (C/2) * HW;
    const uint32_t* Bg = g_sbf[1] + (size_t)b * (C/2) * HW;
    uint32_t sbase = smem_u32(dyn);

    // A: 16 rows x 24 uint4 (96 words) = 384 slots; B: 16 x 32 = 512 slots
    int arow = tid / 24, acol = (tid % 24) * 4;               // slot tid (<384 always for tid<256)
    int arow2 = (tid + 256) / 24, acol2 = ((tid + 256) % 24) * 4;  // slot tid+256, only tid<128
    int brow[2], bcol[2];
    #pragma unroll
    for (int t = 0; t < 2; t++) {
        int v = tid + t * 256;
        brow[t] = v >> 5;
        int cb = n0 + (v & 31) * 4; if (cb > HW - 4) cb = HW - 4;
        bcol[t] = cb;
    }
    auto issue_chunk = [&](int s, int stage) {
        int k20 = s * 16;
        uint32_t sA = sbase + stage * (SSTR2 * 4);
        uint32_t sB = sA + MATW2 * 4;
        CP_CG16(sA + (arow * LDW2 + acol) * 4, (const char*)&Ag[(size_t)(k20 + arow) * HW + m0 + acol]);
        if (tid < 128)
            CP_CG16(sA + (arow2 * LDW2 + acol2) * 4, (const char*)&Ag[(size_t)(k20 + arow2) * HW + m0 + acol2]);
        #pragma unroll
        for (int t = 0; t < 2; t++) {
            int v = tid + t * 256;
            uint32_t so = (brow[t] * LDW2 + (v & 31) * 4) * 4;
            CP_CG16(sB + so, (const char*)&Bg[(size_t)(k20 + brow[t]) * HW + bcol[t]]);
        }
        CP_COMMIT();
    };

    float acc[3][4][4] = {};
    issue_chunk(0, 0);
    for (int s = 0; s < NCH; s++) {
        if (s + 1 < NCH) { issue_chunk(s + 1, (s + 1) & 1); CP_WAIT1(); }
        else             { CP_WAIT0(); }
        __syncthreads();
        const uint32_t* As = dyn + (s & 1) * SSTR2;
        const uint32_t* Bs = As + MATW2;
        FRAGP96(As, Bs, 0)
        FRAGP96(As, Bs, 8)
        __syncthreads();
    }

    // ---- fused argmin epilogue ----
    ull* rkey = (ull*)dyn;          // [96]
    ull* ckey = rkey + 96;          // [128]
    if (tid < 224) { if (tid < 96) rkey[tid] = ~0ull; else ckey[tid - 96] = ~0ull; }
    __syncthreads();

    const float* a2p = g_a2 + b * HW;
    const float* b2p = g_b2 + b * HW;

    // m mapping: i<2 -> wm + gr*4 + i*2 + half ; i==2 -> wm + 32 + gr*2 + half
    #pragma unroll
    for (int i = 0; i < 3; i++) {
        int mbase = (i < 2) ? (wm + gr * 4 + i * 2) : (wm + 32 + gr * 2);
        #pragma unroll
        for (int half = 0; half < 2; half++) {
            int ml = mbase + half;
            ull rb_ = ~0ull;
            #pragma unroll
            for (int j = 0; j < 4; j++)
                #pragma unroll
                for (int rb = 0; rb < 2; rb++) {
                    int n_g = n0 + wn + 8 * gc + 4 * rb + j;
                    if (n_g < HW) {
                        ull k = enc_key(b2p[n_g] - 2.f * acc[i][j][half * 2 + rb], n_g);
                        if (k < rb_) rb_ = k;
                    }
                }
            if (rb_ != ~0ull) atomicMin(&rkey[ml], rb_);
        }
    }
    #pragma unroll
    for (int j = 0; j < 4; j++)
        #pragma unroll
        for (int rb = 0; rb < 2; rb++) {
            int nl = wn + 8 * gc + 4 * rb + j;
            ull cbest = ~0ull;
            #pragma unroll
            for (int i = 0; i < 3; i++) {
                int mbase = m0 + ((i < 2) ? (wm + gr * 4 + i * 2) : (wm + 32 + gr * 2));
                #pragma unroll
                for (int half = 0; half < 2; half++) {
                    int m_g = mbase + half;   // always < 576
                    ull k = enc_key(a2p[m_g] - 2.f * acc[i][j][half * 2 + rb], m_g);
                    if (k < cbest) cbest = k;
                }
            }
            if (cbest != ~0ull) atomicMin(&ckey[nl], cbest);
        }
    __syncthreads();
    if (tid < 96) {
        atomicMin(&g_key[0][b * HW + m0 + tid], rkey[tid]);
    } else if (tid >= 128) {
        int n = n0 + tid - 128;
        if (n < HW) atomicMin(&g_key[1][b * HW + n], ckey[tid - 128]);
    }
}

// ---- split-K bf16 MMA Gram: 128x128 tiles (zero waste), relative stage indexing ----
__global__ void __launch_bounds__(256, 2) k_gram_mma() {
    extern __shared__ uint32_t dyn[];
    int t   = blockIdx.y & 3;
    int spl = blockIdx.y >> 2;
    const uint32_t* X = g_Xbf[t];
    int idx = blockIdx.x, ti = 0;
    while (idx >= 6 - ti) { idx -= 6 - ti; ti++; }
    int tj = ti + idx;
    int i0 = ti * 128, j0 = tj * 128;

    int tid = threadIdx.x, w = tid >> 5, lane = tid & 31;
    int wm = (w & 1) * 64, wn = (w >> 1) * 32;
    int gr = lane >> 2, gc = lane & 3;
    uint32_t sbase = smem_u32(dyn);

    int s0 = spl * SPLC;
    auto issue_chunk = [&](int r, int stage) {
        int k20 = (s0 + r) * 16;
        uint32_t sA = sbase + stage * (SSTR2 * 4);
        uint32_t sB = sA + MATW2 * 4;
        #pragma unroll
        for (int tt = 0; tt < 2; tt++) {
            int v = tid + tt * 256;
            int row = v >> 5, col = (v & 31) * 4;
            uint32_t so = (row * LDW2 + col) * 4;
            CP_CG16(sA + so, (const char*)&X[(size_t)(k20 + row) * C + i0 + col]);
            CP_CG16(sB + so, (const char*)&X[(size_t)(k20 + row) * C + j0 + col]);
        }
        CP_COMMIT();
    };

    float acc[4][4][4] = {};
    issue_chunk(0, 0);
    for (int r = 0; r < SPLC; r++) {
        if (r + 1 < SPLC) { issue_chunk(r + 1, (r + 1) & 1); CP_WAIT1(); }
        else              { CP_WAIT0(); }
        __syncthreads();
        const uint32_t* As = dyn + (r & 1) * SSTR2;
        const uint32_t* Bs = As + MATW2;
        FRAGP(As, Bs, 0)
        FRAGP(As, Bs, 8)
        __syncthreads();
    }

    float* Sp = g_Sp[t][spl];
    #pragma unroll
    for (int i = 0; i < 4; i++) {
        int mbase = i0 + wm + (i >> 1) * 32 + gr * 4 + (i & 1) * 2;
        #pragma unroll
        for (int half = 0; half < 2; half++)
            #pragma unroll
            for (int rb = 0; rb < 2; rb++) {
                int c2 = j0 + wn + 8 * gc + 4 * rb;
                float4 o = make_float4(acc[i][0][half * 2 + rb], acc[i][1][half * 2 + rb],
                                       acc[i][2][half * 2 + rb], acc[i][3][half * 2 + rb]);
                *(float4*)&Sp[(size_t)(mbase + half) * C + c2] = o;
            }
    }
}

__global__ void k_sred() {
    int t = blockIdx.y;
    size_t i = (size_t)blockIdx.x * 256 + threadIdx.x;
    float s = g_Sp[t][0][i] + g_Sp[t][1][i] + g_Sp[t][2][i] + g_Sp[t][3][i];
    g_S[t][i] = s;
}

// rank-based top-50 smallest d2 (ties -> lowest index)
__global__ void k_select() {
    int b = blockIdx.x, dir = blockIdx.y;
    __shared__ float sd[HW];
    __shared__ int   sn[HW];
    int i = threadIdx.x;
    ull key = g_key[dir][b * HW + i];
    const float* own = dir ? g_b2 : g_a2;
    float d2 = own[b * HW + i] + dec_val(key);
    if (d2 < 0.f) d2 = 0.f;
    sd[i] = d2;
    sn[i] = (int)(uint32_t)key;
    __syncthreads();
    float di = sd[i];
    int rank = 0;
    for (int j = 0; j < HW; j++) {
        float dj = sd[j];
        rank += (dj < di) || (dj == di && j < i);
    }
    if (rank < NM) {
        g_sel_in[dir][b * NM + rank] = i;
        g_sel_c [dir][b * NM + rank] = sn[i];
    }
}

// gather row PAIRS from transposed bf16 copy (coalesced); inv from bf16 values
__global__ void __launch_bounds__(128) k_gather2() {
    int p = blockIdx.x;
    int dir = blockIdx.y;
    int r0 = 2 * p, r1 = r0 + 1;
    int b = r0 / NM;
    const uint32_t* Tin = g_sbt[dir ? 1 : 0];
    const uint32_t* Tc  = g_sbt[dir ? 0 : 1];
    const uint32_t* in0 = Tin + ((size_t)b * HW + g_sel_in[dir][r0]) * (C/2);
    const uint32_t* in1 = Tin + ((size_t)b * HW + g_sel_in[dir][r1]) * (C/2);
    const uint32_t* c0  = Tc  + ((size_t)b * HW + g_sel_c [dir][r0]) * (C/2);
    const uint32_t* c1  = Tc  + ((size_t)b * HW + g_sel_c [dir][r1]) * (C/2);
    uint32_t* Xin = g_Xbf[dir * 2 + 0] + (size_t)p * C;
    uint32_t* Xc  = g_Xbf[dir * 2 + 1] + (size_t)p * C;
    float lsum = 0.f;
    for (int k2 = threadIdx.x; k2 < C/2; k2 += 128) {
        uint32_t wi0 = in0[k2], wi1 = in1[k2];
        uint32_t wc0 = c0[k2],  wc1 = c1[k2];
        ((uint2*)Xin)[k2] = make_uint2(__byte_perm(wi0, wi1, 0x5410),
                                       __byte_perm(wi0, wi1, 0x7632));
        ((uint2*)Xc)[k2]  = make_uint2(__byte_perm(wc0, wc1, 0x5410),
                                       __byte_perm(wc0, wc1, 0x7632));
        float d;
        d = bf_lo(wi0) - bf_lo(wc0); lsum += d * d;
        d = bf_hi(wi0) - bf_hi(wc0); lsum += d * d;
        d = bf_lo(wi1) - bf_lo(wc1); lsum += d * d;
        d = bf_hi(wi1) - bf_hi(wc1); lsum += d * d;
    }
    float tot = blockReduceSum(lsum);
    if (threadIdx.x == 0) atomicAdd(&g_acc[1 + dir], (double)tot);
}

__global__ void k_pooled_inv(const float* __restrict__ p1, const float* __restrict__ p2) {
    float lsum = 0.f;
    for (int i = blockIdx.x * blockDim.x + threadIdx.x; i < B * C; i += gridDim.x * blockDim.x) {
        float d = p1[i] - p2[i]; lsum += d * d;
    }
    float tot = blockReduceSum(lsum);
    if (threadIdx.x == 0) atomicAdd(&g_acc[0], (double)tot);
}

__device__ __forceinline__ int tensor_n(int t) { return (t < 4) ? NSEL : B; }

__global__ void k_colsum_part(const float* __restrict__ p1, const float* __restrict__ p2) {
    int t = blockIdx.x, chunk = blockIdx.y, c = threadIdx.x;
    float s = 0.f;
    if (t < 4) {
        const uint32_t* X = g_Xbf[t];
        int n20 = chunk * (NSEL / 2 / 16), n21 = n20 + NSEL / 2 / 16;
        for (int i = n20; i < n21; i++) {
            uint32_t w = X[(size_t)i * C + c];
            s += bf_lo(w) + bf_hi(w);
        }
    } else {
        const float* X = (t == 4) ? p1 : p2;
        int n0 = chunk * (B / 16), n1 = n0 + B / 16;
        for (int i = n0; i < n1; i++) s += X[(size_t)i * C + c];
    }
    g_csp[t][chunk][c] = s;
}
__global__ void k_colsum_fin() {
    int t = blockIdx.x, c = threadIdx.x;
    float s = 0.f;
    #pragma unroll
    for (int k = 0; k < 16; k++) s += g_csp[t][k][c];
    g_colsum[t][c] = s;
}

// exact fp32 Gram for the 2 pooled tensors (n=64), upper 64x64 tiles
__global__ void __launch_bounds__(256) k_gram(const float* __restrict__ p1,
                                              const float* __restrict__ p2) {
    int t = 4 + blockIdx.y;
    const float* X = (t == 4) ? p1 : p2;
    int n = B;
    int idx = blockIdx.x, ti = 0;
    while (idx >= 12 - ti) { idx -= 12 - ti; ti++; }
    int tj = ti + idx;
    int i0 = ti * 64, j0 = tj * 64;

    __shared__ float As[16][64], Bs[16][64];
    int tid = threadIdx.x;
    int tx = tid & 15, ty = tid >> 4;
    int lk = tid >> 4, lo = (tid & 15) * 4;
    float acc[4][4] = {};
    for (int k0 = 0; k0 < n; k0 += 16) {
        *(float4*)&As[lk][lo] = *(const float4*)&X[(size_t)(k0 + lk) * C + i0 + lo];
        *(float4*)&Bs[lk][lo] = *(const float4*)&X[(size_t)(k0 + lk) * C + j0 + lo];
        __syncthreads();
        #pragma unroll
        for (int kk = 0; kk < 16; kk++) {
            float a[4], bb[4];
            *(float4*)a  = *(float4*)&As[kk][ty * 4];
            *(float4*)bb = *(float4*)&Bs[kk][tx * 4];
            #pragma unroll
            for (int i = 0; i < 4; i++)
                #pragma unroll
                for (int j = 0; j < 4; j++) acc[i][j] += a[i] * bb[j];
        }
        __syncthreads();
    }
    float* Sp = g_S[t];
    #pragma unroll
    for (int i = 0; i < 4; i++) {
        int c1 = i0 + ty * 4 + i;
        *(float4*)&Sp[(size_t)c1 * C + j0 + tx * 4] = *(float4*)acc[i];
    }
}

__global__ void k_std() {
    int t = blockIdx.x, c = threadIdx.x;
    float n  = (float)tensor_n(t);
    float mu = g_colsum[t][c] / n;
    float Scc = g_S[t][(size_t)c * C + c];
    float var = (Scc - n * mu * mu) / (n - 1.f);
    float sd  = sqrtf(var + EPSV);
    float contrib = fmaxf(1.f - sd, 0.f);
    float tot = blockReduceSum(contrib);
    if (threadIdx.x == 0) atomicAdd(&g_acc[3 + t], (double)tot);
}

__global__ void k_cov() {
    int t = blockIdx.y;
    float n = (float)tensor_n(t);
    float inv_nm1 = 1.f / (n - 1.f);
    int idx = blockIdx.x, ti = 0;
    while (idx >= 12 - ti) { idx -= 12 - ti; ti++; }
    int tj = ti + idx;
    int i0 = ti * 64, j0 = tj * 64;
    const float* Sp = g_S[t];
    float lsum = 0.f;
    #pragma unroll
    for (int it = 0; it < 16; it++) {
        int e = it * 256 + threadIdx.x;
        int r = e >> 6, cc = e & 63;
        int c1 = i0 + r, c2 = j0 + cc;
        if (c2 > c1) {
            float mu1 = g_colsum[t][c1] / n;
            float mu2 = g_colsum[t][c2] / n;
            float cov = (Sp[(size_t)c1 * C + c2] - n * mu1 * mu2) * inv_nm1;
            lsum += 2.f * cov * cov;
        }
    }
    float tot = blockReduceSum(lsum);
    if (threadIdx.x == 0) atomicAdd(&g_acc[10 + t], (double)tot);
}

__global__ void k_final(float* __restrict__ out) {
    double inv_g = g_acc[0] / (double)(B * C);
    double inv1  = g_acc[1] / (double)((size_t)NSEL * C);
    double inv2  = g_acc[2] / (double)((size_t)NSEL * C);
    double stdt[6], covt[6];
    for (int t = 0; t < 6; t++) {
        stdt[t] = (g_acc[3 + t] / (double)C) * 0.5;
        covt[t] = g_acc[10 + t] / (double)C;
    }
    double glob = 25.0 * inv_g + 25.0 * (stdt[4] + stdt[5]) + (covt[4] + covt[5]);
    double loc  = 0.5 * (25.0 * inv1 + 25.0 * inv2)
                + 0.5 * (25.0 * (stdt[0] + stdt[1]) + 25.0 * (stdt[2] + stdt[3]))
                + 0.5 * ((covt[0] + covt[1]) + (covt[2] + covt[3]));
    out[0] = (float)(0.5 * glob + 0.5 * loc);
}

// ---------------- launch ----------------
extern "C" void kernel_launch(void* const* d_in, const int* in_sizes, int n_in,
                              void* d_out, int out_size) {
    const float* s1 = (const float*)d_in[0];
    const float* p1 = (const float*)d_in[1];
    const float* s2 = (const float*)d_in[2];
    const float* p2 = (const float*)d_in[3];
    float* out = (float*)d_out;

    cudaFuncSetAttribute(k_packall,    cudaFuncAttributeMaxDynamicSharedMemorySize, PKSM);
    cudaFuncSetAttribute(k_gemm_fused, cudaFuncAttributeMaxDynamicSharedMemorySize, GS2);
    cudaFuncSetAttribute(k_gram_mma,   cudaFuncAttributeMaxDynamicSharedMemorySize, GS2);

    k_init<<<(2 * B * HW + 255) / 256, 256>>>();
    k_packall<<<dim3(B * (HW / 32), 2), 256, PKSM>>>(s1, s2);
    k_gemm_fused<<<dim3(5, 6, B), 256, GS2>>>();
    k_select<<<dim3(B, 2), HW>>>();
    k_gather2<<<dim3(NSEL / 2, 2), 128>>>();
    k_pooled_inv<<<48, 256>>>(p1, p2);
    k_colsum_part<<<dim3(6, 16), C>>>(p1, p2);
    k_colsum_fin<<<6, C>>>();
    k_gram_mma<<<dim3(21, 4 * NSPL), 256, GS2>>>();
    k_sred<<<dim3(C * C / 256, 4), 256>>>();
    k_gram<<<dim3(78, 2), 256>>>(p1, p2);
    k_std<<<6, C>>>();
    k_cov<<<dim3(78, 6), 256>>>();
    k_final<<<1, 1>>>(out);
}

// round 16
// speedup vs baseline: 1.8698x; 1.0189x over previous
#include <cuda_runtime.h>
#include <cstdint>
#include <math.h>

#define B    64
#define C    768
#define HW   576
#define NM   50
#define NSEL (B*NM)   // 3200
#define EPSV 1e-5f
#define KC   32
#define NCH  (C/KC)    // 24
#define NCH2 (NSEL/KC) // 100
#define NSPL 4
#define SPLC (NCH2/NSPL) // 25

typedef unsigned long long ull;

// ---------------- scratch ----------------
__device__ float    g_a2[B*HW], g_b2[B*HW];
__device__ ull      g_key[2][B*HW];
__device__ int      g_sel_in[2][NSEL];
__device__ int      g_sel_c [2][NSEL];
__device__ uint32_t g_sbf[2][(size_t)B*(C/2)*HW];      // packed bf16x2 spatial [b][k2][m]
__device__ uint32_t g_sbt[2][(size_t)B*HW*(C/2)];      // packed bf16x2 spatial [b][m][k2]
__device__ uint32_t g_Xbf[4][(size_t)(NSEL/2)*C];      // packed bf16x2 gathered [n2][c]
__device__ float    g_S[2][(size_t)C*C];               // pooled grams only
__device__ float    g_Sp[4][NSPL][(size_t)C*C];        // split-K partials for t<4
__device__ float    g_csp[6][16][C];
__device__ float    g_colsum[6][C];
__device__ double   g_acc[32];

// ---------------- helpers ----------------
__device__ __forceinline__ void mma_bf16(float c[4],
                                         uint32_t a0, uint32_t a1, uint32_t a2, uint32_t a3,
                                         uint32_t b0, uint32_t b1) {
    asm volatile(
        "mma.sync.aligned.m16n8k16.row.col.f32.bf16.bf16.f32 "
        "{%0,%1,%2,%3}, {%4,%5,%6,%7}, {%8,%9}, {%0,%1,%2,%3};"
        : "+f"(c[0]), "+f"(c[1]), "+f"(c[2]), "+f"(c[3])
        : "r"(a0), "r"(a1), "r"(a2), "r"(a3), "r"(b0), "r"(b1));
}
__device__ __forceinline__ uint32_t packbf(float lo, float hi) {
    uint32_t r;
    asm("cvt.rn.bf16x2.f32 %0, %1, %2;" : "=r"(r) : "f"(hi), "f"(lo));
    return r;
}
__device__ __forceinline__ float bf_lo(uint32_t w) { return __uint_as_float(w << 16); }
__device__ __forceinline__ float bf_hi(uint32_t w) { return __uint_as_float(w & 0xffff0000u); }

#define CP_CG16(d, s) asm volatile("cp.async.cg.shared.global [%0], [%1], 16;" :: "r"(d), "l"(s))
#define CP_COMMIT()  asm volatile("cp.async.commit_group;" ::: "memory")
#define CP_WAIT1()   asm volatile("cp.async.wait_group 1;" ::: "memory")
#define CP_WAIT0()   asm volatile("cp.async.wait_group 0;" ::: "memory")

__device__ __forceinline__ uint32_t smem_u32(const void* p) {
    uint32_t a;
    asm("{ .reg .u64 t; cvta.to.shared.u64 t, %1; cvt.u32.u64 %0, t; }" : "=r"(a) : "l"(p));
    return a;
}
__device__ __forceinline__ ull enc_key(float f, int idx) {
    uint32_t u = __float_as_uint(f);
    u = (u & 0x80000000u) ? ~u : (u | 0x80000000u);
    return ((ull)u << 32) | (uint32_t)idx;
}
__device__ __forceinline__ float dec_val(ull k) {
    uint32_t e = (uint32_t)(k >> 32);
    uint32_t u = (e & 0x80000000u) ? (e ^ 0x80000000u) : ~e;
    return __uint_as_float(u);
}

__device__ __forceinline__ float blockReduceSum(float v) {
    __shared__ float sw[32];
    int lane = threadIdx.x & 31, w = threadIdx.x >> 5;
    #pragma unroll
    for (int o = 16; o; o >>= 1) v += __shfl_xor_sync(~0u, v, o);
    if (lane == 0) sw[w] = v;
    __syncthreads();
    int nw = (blockDim.x + 31) >> 5;
    v = (threadIdx.x < nw) ? sw[threadIdx.x] : 0.f;
    if (w == 0) {
        #pragma unroll
        for (int o = 16; o; o >>= 1) v += __shfl_xor_sync(~0u, v, o);
    }
    return v;
}

// ---------------- small kernels ----------------
__global__ void k_init() {
    int i = blockIdx.x * blockDim.x + threadIdx.x;
    if (i < 2 * B * HW) ((ull*)g_key)[i] = ~0ull;
    if (blockIdx.x == 0 && threadIdx.x < 32) g_acc[threadIdx.x] = 0.0;
}

// ---- single pass: f32 spatial -> both bf16 layouts + exact f32 norms ----
#define PAD   385
#define PKSM  (32 * PAD * 4 + 8 * 32 * 4)   // 50304 B
__global__ void __launch_bounds__(256) k_packall(const float* __restrict__ s1,
                                                 const float* __restrict__ s2) {
    extern __shared__ uint32_t sm[];                 // [32][PAD]
    float* nsum = (float*)(sm + 32 * PAD);           // [8][32]
    int t = blockIdx.y;
    const float* src = t ? s2 : s1;
    int b  = blockIdx.x / (HW / 32);
    int m0 = (blockIdx.x % (HW / 32)) * 32;
    int tid = threadIdx.x, tx = tid & 31, ty = tid >> 5;
    int m = m0 + tx;

    const float* base = src + (size_t)b * C * HW + m;
    float s = 0.f;
    for (int k2 = ty; k2 < C/2; k2 += 8) {
        float v0 = base[(size_t)(2 * k2) * HW];
        float v1 = base[(size_t)(2 * k2 + 1) * HW];
        s += v0 * v0 + v1 * v1;
        sm[tx * PAD + k2] = packbf(v0, v1);
    }
    nsum[ty * 32 + tx] = s;
    __syncthreads();
    if (ty == 0) {
        float tot = 0.f;
        #pragma unroll
        for (int q = 0; q < 8; q++) tot += nsum[q * 32 + tx];
        (t ? g_b2 : g_a2)[b * HW + m] = tot;
    }
    uint32_t* dstT = g_sbt[t] + ((size_t)b * HW + m0) * (C/2);
    for (int idx = tid; idx < 32 * (C/2); idx += 256) {
        int r = idx / (C/2), k2 = idx % (C/2);
        dstT[(size_t)r * (C/2) + k2] = sm[r * PAD + k2];
    }
    uint32_t* dstK = g_sbf[t] + (size_t)b * (C/2) * HW + m0;
    for (int idx = tid; idx < 32 * (C/2); idx += 256) {
        int k2 = idx >> 5, mm = idx & 31;
        dstK[(size_t)k2 * HW + mm] = sm[mm * PAD + k2];
    }
}

// ---------------- bf16 MMA machinery ----------------
#define LDW2   136
#define MATW2  (16*LDW2)
#define SSTR2  (2*MATW2)
#define GS2    (2 * SSTR2 * 4)     // 34816 B

#define FRAGP(As, Bs, kb2)                                                       \
    {                                                                            \
        uint4 A0 = *(const uint4*)&As[(kb2 + gc    ) * LDW2 + wm      + gr * 4]; \
        uint4 A1 = *(const uint4*)&As[(kb2 + gc + 4) * LDW2 + wm      + gr * 4]; \
        uint4 A2 = *(const uint4*)&As[(kb2 + gc    ) * LDW2 + wm + 32 + gr * 4]; \
        uint4 A3 = *(const uint4*)&As[(kb2 + gc + 4) * LDW2 + wm + 32 + gr * 4]; \
        uint4 B0 = *(const uint4*)&Bs[(kb2 + gc    ) * LDW2 + wn      + gr * 4]; \
        uint4 B1 = *(const uint4*)&Bs[(kb2 + gc + 4) * LDW2 + wn      + gr * 4]; \
        mma_bf16(acc[0][0], A0.x, A0.y, A1.x, A1.y, B0.x, B1.x);                 \
        mma_bf16(acc[0][1], A0.x, A0.y, A1.x, A1.y, B0.y, B1.y);                 \
        mma_bf16(acc[0][2], A0.x, A0.y, A1.x, A1.y, B0.z, B1.z);                 \
        mma_bf16(acc[0][3], A0.x, A0.y, A1.x, A1.y, B0.w, B1.w);                 \
        mma_bf16(acc[1][0], A0.z, A0.w, A1.z, A1.w, B0.x, B1.x);                 \
        mma_bf16(acc[1][1], A0.z, A0.w, A1.z, A1.w, B0.y, B1.y);                 \
        mma_bf16(acc[1][2], A0.z, A0.w, A1.z, A1.w, B0.z, B1.z);                 \
        mma_bf16(acc[1][3], A0.z, A0.w, A1.z, A1.w, B0.w, B1.w);                 \
        mma_bf16(acc[2][0], A2.x, A2.y, A3.x, A3.y, B0.x, B1.x);                 \
        mma_bf16(acc[2][1], A2.x, A2.y, A3.x, A3.y, B0.y, B1.y);                 \
        mma_bf16(acc[2][2], A2.x, A2.y, A3.x, A3.y, B0.z, B1.z);                 \
        mma_bf16(acc[2][3], A2.x, A2.y, A3.x, A3.y, B0.w, B1.w);                 \
        mma_bf16(acc[3][0], A2.z, A2.w, A3.z, A3.w, B0.x, B1.x);                 \
        mma_bf16(acc[3][1], A2.z, A2.w, A3.z, A3.w, B0.y, B1.y);                 \
        mma_bf16(acc[3][2], A2.z, A2.w, A3.z, A3.w, B0.z, B1.z);                 \
        mma_bf16(acc[3][3], A2.z, A2.w, A3.z, A3.w, B0.w, B1.w);                 \
    }

#define FRAGP96(As, Bs, kb2)                                                     \
    {                                                                            \
        uint4 A0 = *(const uint4*)&As[(kb2 + gc    ) * LDW2 + wm      + gr * 4]; \
        uint4 A2 = *(const uint4*)&As[(kb2 + gc + 4) * LDW2 + wm      + gr * 4]; \
        uint2 A1 = *(const uint2*)&As[(kb2 + gc    ) * LDW2 + wm + 32 + gr * 2]; \
        uint2 A3 = *(const uint2*)&As[(kb2 + gc + 4) * LDW2 + wm + 32 + gr * 2]; \
        uint4 B0 = *(const uint4*)&Bs[(kb2 + gc    ) * LDW2 + wn      + gr * 4]; \
        uint4 B1 = *(const uint4*)&Bs[(kb2 + gc + 4) * LDW2 + wn      + gr * 4]; \
        mma_bf16(acc[0][0], A0.x, A0.y, A2.x, A2.y, B0.x, B1.x);                 \
        mma_bf16(acc[0][1], A0.x, A0.y, A2.x, A2.y, B0.y, B1.y);                 \
        mma_bf16(acc[0][2], A0.x, A0.y, A2.x, A2.y, B0.z, B1.z);                 \
        mma_bf16(acc[0][3], A0.x, A0.y, A2.x, A2.y, B0.w, B1.w);                 \
        mma_bf16(acc[1][0], A0.z, A0.w, A2.z, A2.w, B0.x, B1.x);                 \
        mma_bf16(acc[1][1], A0.z, A0.w, A2.z, A2.w, B0.y, B1.y);                 \
        mma_bf16(acc[1][2], A0.z, A0.w, A2.z, A2.w, B0.z, B1.z);                 \
        mma_bf16(acc[1][3], A0.z, A0.w, A2.z, A2.w, B0.w, B1.w);                 \
        mma_bf16(acc[2][0], A1.x, A1.y, A3.x, A3.y, B0.x, B1.x);                 \
        mma_bf16(acc[2][1], A1.x, A1.y, A3.x, A3.y, B0.y, B1.y);                 \
        mma_bf16(acc[2][2], A1.x, A1.y, A3.x, A3.y, B0.z, B1.z);                 \
        mma_bf16(acc[2][3], A1.x, A1.y, A3.x, A3.y, B0.w, B1.w);                 \
    }

// ---- fused bf16 GEMM + argmin. CTA 96x128, 8 warps (2m x 4n) ----
__global__ void __launch_bounds__(256, 2) k_gemm_fused() {
    extern __shared__ uint32_t dyn[];
    int b  = blockIdx.z;
    int m0 = blockIdx.y * 96, n0 = blockIdx.x * 128;
    int tid = threadIdx.x, w = tid >> 5, lane = tid & 31;
    int wm = (w & 1) * 48, wn = (w >> 1) * 32;
    int gr = lane >> 2, gc = lane & 3;

    const uint32_t* Ag = g_sbf[0] + (size_t)b * (C/2) * HW;
    const uint32_t* Bg = g_sbf[1] + (size_t)b * (C/2) * HW;
    uint32_t sbase = smem_u32(dyn);

    int arow = tid / 24, acol = (tid % 24) * 4;
    int arow2 = (tid + 256) / 24, acol2 = ((tid + 256) % 24) * 4;
    int brow[2], bcol[2];
    #pragma unroll
    for (int t = 0; t < 2; t++) {
        int v = tid + t * 256;
        brow[t] = v >> 5;
        int cb = n0 + (v & 31) * 4; if (cb > HW - 4) cb = HW - 4;
        bcol[t] = cb;
    }
    auto issue_chunk = [&](int s, int stage) {
        int k20 = s * 16;
        uint32_t sA = sbase + stage * (SSTR2 * 4);
        uint32_t sB = sA + MATW2 * 4;
        CP_CG16(sA + (arow * LDW2 + acol) * 4, (const char*)&Ag[(size_t)(k20 + arow) * HW + m0 + acol]);
        if (tid < 128)
            CP_CG16(sA + (arow2 * LDW2 + acol2) * 4, (const char*)&Ag[(size_t)(k20 + arow2) * HW + m0 + acol2]);
        #pragma unroll
        for (int t = 0; t < 2; t++) {
            int v = tid + t * 256;
            uint32_t so = (brow[t] * LDW2 + (v & 31) * 4) * 4;
            CP_CG16(sB + so, (const char*)&Bg[(size_t)(k20 + brow[t]) * HW + bcol[t]]);
        }
        CP_COMMIT();
    };

    float acc[3][4][4] = {};
    issue_chunk(0, 0);
    for (int s = 0; s < NCH; s++) {
        if (s + 1 < NCH) { issue_chunk(s + 1, (s + 1) & 1); CP_WAIT1(); }
        else             { CP_WAIT0(); }
        __syncthreads();
        const uint32_t* As = dyn + (s & 1) * SSTR2;
        const uint32_t* Bs = As + MATW2;
        FRAGP96(As, Bs, 0)
        FRAGP96(As, Bs, 8)
        __syncthreads();
    }

    // ---- fused argmin epilogue ----
    ull* rkey = (ull*)dyn;          // [96]
    ull* ckey = rkey + 96;          // [128]
    if (tid < 224) { if (tid < 96) rkey[tid] = ~0ull; else ckey[tid - 96] = ~0ull; }
    __syncthreads();

    const float* a2p = g_a2 + b * HW;
    const float* b2p = g_b2 + b * HW;

    #pragma unroll
    for (int i = 0; i < 3; i++) {
        int mbase = (i < 2) ? (wm + gr * 4 + i * 2) : (wm + 32 + gr * 2);
        #pragma unroll
        for (int half = 0; half < 2; half++) {
            int ml = mbase + half;
            ull rb_ = ~0ull;
            #pragma unroll
            for (int j = 0; j < 4; j++)
                #pragma unroll
                for (int rb = 0; rb < 2; rb++) {
                    int n_g = n0 + wn + 8 * gc + 4 * rb + j;
                    if (n_g < HW) {
                        ull k = enc_key(b2p[n_g] - 2.f * acc[i][j][half * 2 + rb], n_g);
                        if (k < rb_) rb_ = k;
                    }
                }
            if (rb_ != ~0ull) atomicMin(&rkey[ml], rb_);
        }
    }
    #pragma unroll
    for (int j = 0; j < 4; j++)
        #pragma unroll
        for (int rb = 0; rb < 2; rb++) {
            int nl = wn + 8 * gc + 4 * rb + j;
            ull cbest = ~0ull;
            #pragma unroll
            for (int i = 0; i < 3; i++) {
                int mbase = m0 + ((i < 2) ? (wm + gr * 4 + i * 2) : (wm + 32 + gr * 2));
                #pragma unroll
                for (int half = 0; half < 2; half++) {
                    int m_g = mbase + half;
                    ull k = enc_key(a2p[m_g] - 2.f * acc[i][j][half * 2 + rb], m_g);
                    if (k < cbest) cbest = k;
                }
            }
            if (cbest != ~0ull) atomicMin(&ckey[nl], cbest);
        }
    __syncthreads();
    if (tid < 96) {
        atomicMin(&g_key[0][b * HW + m0 + tid], rkey[tid]);
    } else if (tid >= 128) {
        int n = n0 + tid - 128;
        if (n < HW) atomicMin(&g_key[1][b * HW + n], ckey[tid - 128]);
    }
}

// ---- split-K bf16 MMA Gram: 128x128 tiles, relative stage indexing ----
__global__ void __launch_bounds__(256, 2) k_gram_mma() {
    extern __shared__ uint32_t dyn[];
    int t   = blockIdx.y & 3;
    int spl = blockIdx.y >> 2;
    const uint32_t* X = g_Xbf[t];
    int idx = blockIdx.x, ti = 0;
    while (idx >= 6 - ti) { idx -= 6 - ti; ti++; }
    int tj = ti + idx;
    int i0 = ti * 128, j0 = tj * 128;

    int tid = threadIdx.x, w = tid >> 5, lane = tid & 31;
    int wm = (w & 1) * 64, wn = (w >> 1) * 32;
    int gr = lane >> 2, gc = lane & 3;
    uint32_t sbase = smem_u32(dyn);

    int s0 = spl * SPLC;
    auto issue_chunk = [&](int r, int stage) {
        int k20 = (s0 + r) * 16;
        uint32_t sA = sbase + stage * (SSTR2 * 4);
        uint32_t sB = sA + MATW2 * 4;
        #pragma unroll
        for (int tt = 0; tt < 2; tt++) {
            int v = tid + tt * 256;
            int row = v >> 5, col = (v & 31) * 4;
            uint32_t so = (row * LDW2 + col) * 4;
            CP_CG16(sA + so, (const char*)&X[(size_t)(k20 + row) * C + i0 + col]);
            CP_CG16(sB + so, (const char*)&X[(size_t)(k20 + row) * C + j0 + col]);
        }
        CP_COMMIT();
    };

    float acc[4][4][4] = {};
    issue_chunk(0, 0);
    for (int r = 0; r < SPLC; r++) {
        if (r + 1 < SPLC) { issue_chunk(r + 1, (r + 1) & 1); CP_WAIT1(); }
        else              { CP_WAIT0(); }
        __syncthreads();
        const uint32_t* As = dyn + (r & 1) * SSTR2;
        const uint32_t* Bs = As + MATW2;
        FRAGP(As, Bs, 0)
        FRAGP(As, Bs, 8)
        __syncthreads();
    }

    float* Sp = g_Sp[t][spl];
    #pragma unroll
    for (int i = 0; i < 4; i++) {
        int mbase = i0 + wm + (i >> 1) * 32 + gr * 4 + (i & 1) * 2;
        #pragma unroll
        for (int half = 0; half < 2; half++)
            #pragma unroll
            for (int rb = 0; rb < 2; rb++) {
                int c2 = j0 + wn + 8 * gc + 4 * rb;
                float4 o = make_float4(acc[i][0][half * 2 + rb], acc[i][1][half * 2 + rb],
                                       acc[i][2][half * 2 + rb], acc[i][3][half * 2 + rb]);
                *(float4*)&Sp[(size_t)(mbase + half) * C + c2] = o;
            }
    }
}

// rank-based top-50 smallest d2 (ties -> lowest index); float4 rank loop
__global__ void k_select() {
    int b = blockIdx.x, dir = blockIdx.y;
    __shared__ float sd[HW];
    __shared__ int   sn[HW];
    int i = threadIdx.x;
    ull key = g_key[dir][b * HW + i];
    const float* own = dir ? g_b2 : g_a2;
    float d2 = own[b * HW + i] + dec_val(key);
    if (d2 < 0.f) d2 = 0.f;
    sd[i] = d2;
    sn[i] = (int)(uint32_t)key;
    __syncthreads();
    float di = sd[i];
    int rank = 0;
    #pragma unroll 4
    for (int j4 = 0; j4 < HW / 4; j4++) {
        float4 v = *(const float4*)&sd[j4 * 4];
        int j = j4 * 4;
        rank += (v.x < di) || (v.x == di && j     < i);
        rank += (v.y < di) || (v.y == di && j + 1 < i);
        rank += (v.z < di) || (v.z == di && j + 2 < i);
        rank += (v.w < di) || (v.w == di && j + 3 < i);
    }
    if (rank < NM) {
        g_sel_in[dir][b * NM + rank] = i;
        g_sel_c [dir][b * NM + rank] = sn[i];
    }
}

// gather row PAIRS from transposed bf16 copy (coalesced); inv from bf16 values
__global__ void __launch_bounds__(128) k_gather2() {
    int p = blockIdx.x;
    int dir = blockIdx.y;
    int r0 = 2 * p, r1 = r0 + 1;
    int b = r0 / NM;
    const uint32_t* Tin = g_sbt[dir ? 1 : 0];
    const uint32_t* Tc  = g_sbt[dir ? 0 : 1];
    const uint32_t* in0 = Tin + ((size_t)b * HW + g_sel_in[dir][r0]) * (C/2);
    const uint32_t* in1 = Tin + ((size_t)b * HW + g_sel_in[dir][r1]) * (C/2);
    const uint32_t* c0  = Tc  + ((size_t)b * HW + g_sel_c [dir][r0]) * (C/2);
    const uint32_t* c1  = Tc  + ((size_t)b * HW + g_sel_c [dir][r1]) * (C/2);
    uint32_t* Xin = g_Xbf[dir * 2 + 0] + (size_t)p * C;
    uint32_t* Xc  = g_Xbf[dir * 2 + 1] + (size_t)p * C;
    float lsum = 0.f;
    for (int k2 = threadIdx.x; k2 < C/2; k2 += 128) {
        uint32_t wi0 = in0[k2], wi1 = in1[k2];
        uint32_t wc0 = c0[k2],  wc1 = c1[k2];
        ((uint2*)Xin)[k2] = make_uint2(__byte_perm(wi0, wi1, 0x5410),
                                       __byte_perm(wi0, wi1, 0x7632));
        ((uint2*)Xc)[k2]  = make_uint2(__byte_perm(wc0, wc1, 0x5410),
                                       __byte_perm(wc0, wc1, 0x7632));
        float d;
        d = bf_lo(wi0) - bf_lo(wc0); lsum += d * d;
        d = bf_hi(wi0) - bf_hi(wc0); lsum += d * d;
        d = bf_lo(wi1) - bf_lo(wc1); lsum += d * d;
        d = bf_hi(wi1) - bf_hi(wc1); lsum += d * d;
    }
    float tot = blockReduceSum(lsum);
    if (threadIdx.x == 0) atomicAdd(&g_acc[1 + dir], (double)tot);
}

__global__ void k_pooled_inv(const float* __restrict__ p1, const float* __restrict__ p2) {
    float lsum = 0.f;
    for (int i = blockIdx.x * blockDim.x + threadIdx.x; i < B * C; i += gridDim.x * blockDim.x) {
        float d = p1[i] - p2[i]; lsum += d * d;
    }
    float tot = blockReduceSum(lsum);
    if (threadIdx.x == 0) atomicAdd(&g_acc[0], (double)tot);
}

__device__ __forceinline__ int tensor_n(int t) { return (t < 4) ? NSEL : B; }

// S lookup: t<4 from split partials (fixed order sum), t>=4 from pooled grams
__device__ __forceinline__ float S_at(int t, int c1, int c2) {
    size_t i = (size_t)c1 * C + c2;
    if (t < 4)
        return g_Sp[t][0][i] + g_Sp[t][1][i] + g_Sp[t][2][i] + g_Sp[t][3][i];
    return g_S[t - 4][i];
}

__global__ void k_colsum_part(const float* __restrict__ p1, const float* __restrict__ p2) {
    int t = blockIdx.x, chunk = blockIdx.y, c = threadIdx.x;
    float s = 0.f;
    if (t < 4) {
        const uint32_t* X = g_Xbf[t];
        int n20 = chunk * (NSEL / 2 / 16), n21 = n20 + NSEL / 2 / 16;
        for (int i = n20; i < n21; i++) {
            uint32_t w = X[(size_t)i * C + c];
            s += bf_lo(w) + bf_hi(w);
        }
    } else {
        const float* X = (t == 4) ? p1 : p2;
        int n0 = chunk * (B / 16), n1 = n0 + B / 16;
        for (int i = n0; i < n1; i++) s += X[(size_t)i * C + c];
    }
    g_csp[t][chunk][c] = s;
}
__global__ void k_colsum_fin() {
    int t = blockIdx.x, c = threadIdx.x;
    float s = 0.f;
    #pragma unroll
    for (int k = 0; k < 16; k++) s += g_csp[t][k][c];
    g_colsum[t][c] = s;
}

// exact fp32 Gram for the 2 pooled tensors (n=64), upper 64x64 tiles
__global__ void __launch_bounds__(256) k_gram(const float* __restrict__ p1,
                                              const float* __restrict__ p2) {
    int t = blockIdx.y;                 // 0 or 1 -> pooled
    const float* X = t ? p2 : p1;
    int n = B;
    int idx = blockIdx.x, ti = 0;
    while (idx >= 12 - ti) { idx -= 12 - ti; ti++; }
    int tj = ti + idx;
    int i0 = ti * 64, j0 = tj * 64;

    __shared__ float As[16][64], Bs[16][64];
    int tid = threadIdx.x;
    int tx = tid & 15, ty = tid >> 4;
    int lk = tid >> 4, lo = (tid & 15) * 4;
    float acc[4][4] = {};
    for (int k0 = 0; k0 < n; k0 += 16) {
        *(float4*)&As[lk][lo] = *(const float4*)&X[(size_t)(k0 + lk) * C + i0 + lo];
        *(float4*)&Bs[lk][lo] = *(const float4*)&X[(size_t)(k0 + lk) * C + j0 + lo];
        __syncthreads();
        #pragma unroll
        for (int kk = 0; kk < 16; kk++) {
            float a[4], bb[4];
            *(float4*)a  = *(float4*)&As[kk][ty * 4];
            *(float4*)bb = *(float4*)&Bs[kk][tx * 4];
            #pragma unroll
            for (int i = 0; i < 4; i++)
                #pragma unroll
                for (int j = 0; j < 4; j++) acc[i][j] += a[i] * bb[j];
        }
        __syncthreads();
    }
    float* Sp = g_S[t];
    #pragma unroll
    for (int i = 0; i < 4; i++) {
        int c1 = i0 + ty * 4 + i;
        *(float4*)&Sp[(size_t)c1 * C + j0 + tx * 4] = *(float4*)acc[i];
    }
}

__global__ void k_std() {
    int t = blockIdx.x, c = threadIdx.x;
    float n  = (float)tensor_n(t);
    float mu = g_colsum[t][c] / n;
    float Scc = S_at(t, c, c);
    float var = (Scc - n * mu * mu) / (n - 1.f);
    float sd  = sqrtf(var + EPSV);
    float contrib = fmaxf(1.f - sd, 0.f);
    float tot = blockReduceSum(contrib);
    if (threadIdx.x == 0) atomicAdd(&g_acc[3 + t], (double)tot);
}

__global__ void k_cov() {
    int t = blockIdx.y;
    float n = (float)tensor_n(t);
    float inv_nm1 = 1.f / (n - 1.f);
    int idx = blockIdx.x, ti = 0;
    while (idx >= 12 - ti) { idx -= 12 - ti; ti++; }
    int tj = ti + idx;
    int i0 = ti * 64, j0 = tj * 64;
    float lsum = 0.f;
    #pragma unroll
    for (int it = 0; it < 16; it++) {
        int e = it * 256 + threadIdx.x;
        int r = e >> 6, cc = e & 63;
        int c1 = i0 + r, c2 = j0 + cc;
        if (c2 > c1) {
            float mu1 = g_colsum[t][c1] / n;
            float mu2 = g_colsum[t][c2] / n;
            float cov = (S_at(t, c1, c2) - n * mu1 * mu2) * inv_nm1;
            lsum += 2.f * cov * cov;
        }
    }
    float tot = blockReduceSum(lsum);
    if (threadIdx.x == 0) atomicAdd(&g_acc[10 + t], (double)tot);
}

__global__ void k_final(float* __restrict__ out) {
    double inv_g = g_acc[0] / (double)(B * C);
    double inv1  = g_acc[1] / (double)((size_t)NSEL * C);
    double inv2  = g_acc[2] / (double)((size_t)NSEL * C);
    double stdt[6], covt[6];
    for (int t = 0; t < 6; t++) {
        stdt[t] = (g_acc[3 + t] / (double)C) * 0.5;
        covt[t] = g_acc[10 + t] / (double)C;
    }
    double glob = 25.0 * inv_g + 25.0 * (stdt[4] + stdt[5]) + (covt[4] + covt[5]);
    double loc  = 0.5 * (25.0 * inv1 + 25.0 * inv2)
                + 0.5 * (25.0 * (stdt[0] + stdt[1]) + 25.0 * (stdt[2] + stdt[3]))
                + 0.5 * ((covt[0] + covt[1]) + (covt[2] + covt[3]));
    out[0] = (float)(0.5 * glob + 0.5 * loc);
}

// ---------------- launch ----------------
extern "C" void kernel_launch(void* const* d_in, const int* in_sizes, int n_in,
                              void* d_out, int out_size) {
    const float* s1 = (const float*)d_in[0];
    const float* p1 = (const float*)d_in[1];
    const float* s2 = (const float*)d_in[2];
    const float* p2 = (const float*)d_in[3];
    float* out = (float*)d_out;

    cudaFuncSetAttribute(k_packall,    cudaFuncAttributeMaxDynamicSharedMemorySize, PKSM);
    cudaFuncSetAttribute(k_gemm_fused, cudaFuncAttributeMaxDynamicSharedMemorySize, GS2);
    cudaFuncSetAttribute(k_gram_mma,   cudaFuncAttributeMaxDynamicSharedMemorySize, GS2);

    k_init<<<(2 * B * HW + 255) / 256, 256>>>();
    k_packall<<<dim3(B * (HW / 32), 2), 256, PKSM>>>(s1, s2);
    k_gemm_fused<<<dim3(5, 6, B), 256, GS2>>>();
    k_select<<<dim3(B, 2), HW>>>();
    k_gather2<<<dim3(NSEL / 2, 2), 128>>>();
    k_pooled_inv<<<48, 256>>>(p1, p2);
    k_colsum_part<<<dim3(6, 16), C>>>(p1, p2);
    k_colsum_fin<<<6, C>>>();
    k_gram_mma<<<dim3(21, 4 * NSPL), 256, GS2>>>();
    k_gram<<<dim3(78, 2), 256>>>(p1, p2);
    k_std<<<6, C>>>();
    k_cov<<<dim3(78, 6), 256>>>();
    k_final<<<1, 1>>>(out);
}

// round 17
// speedup vs baseline: 1.8844x; 1.0078x over previous
#include <cuda_runtime.h>
#include <cstdint>
#include <math.h>

#define B    64
#define C    768
#define HW   576
#define NM   50
#define NSEL (B*NM)   // 3200
#define EPSV 1e-5f
#define KC   32
#define NCH  (C/KC)    // 24
#define NCH2 (NSEL/KC) // 100
#define NSPL 4
#define SPLC (NCH2/NSPL) // 25

typedef unsigned long long ull;

// ---------------- scratch ----------------
__device__ float    g_a2[B*HW], g_b2[B*HW];
__device__ ull      g_key[2][B*HW];
__device__ int      g_sel_in[2][NSEL];
__device__ int      g_sel_c [2][NSEL];
__device__ uint32_t g_sbf[2][(size_t)B*(C/2)*HW];      // packed bf16x2 spatial [b][k2][m]
__device__ uint32_t g_sbt[2][(size_t)B*HW*(C/2)];      // packed bf16x2 spatial [b][m][k2]
__device__ uint32_t g_Xbf[4][(size_t)(NSEL/2)*C];      // packed bf16x2 gathered [n2][c]
__device__ float    g_S[2][(size_t)C*C];               // pooled grams
__device__ float    g_Sp[4][NSPL][(size_t)C*C];        // split-K partials
__device__ float    g_csp[6][16][C];
__device__ float    g_colsum[6][C];
__device__ double   g_acc[32];

// ---------------- helpers ----------------
__device__ __forceinline__ void mma_bf16(float c[4],
                                         uint32_t a0, uint32_t a1, uint32_t a2, uint32_t a3,
                                         uint32_t b0, uint32_t b1) {
    asm volatile(
        "mma.sync.aligned.m16n8k16.row.col.f32.bf16.bf16.f32 "
        "{%0,%1,%2,%3}, {%4,%5,%6,%7}, {%8,%9}, {%0,%1,%2,%3};"
        : "+f"(c[0]), "+f"(c[1]), "+f"(c[2]), "+f"(c[3])
        : "r"(a0), "r"(a1), "r"(a2), "r"(a3), "r"(b0), "r"(b1));
}
__device__ __forceinline__ uint32_t packbf(float lo, float hi) {
    uint32_t r;
    asm("cvt.rn.bf16x2.f32 %0, %1, %2;" : "=r"(r) : "f"(hi), "f"(lo));
    return r;
}
__device__ __forceinline__ float bf_lo(uint32_t w) { return __uint_as_float(w << 16); }
__device__ __forceinline__ float bf_hi(uint32_t w) { return __uint_as_float(w & 0xffff0000u); }

#define CP_CG16(d, s) asm volatile("cp.async.cg.shared.global [%0], [%1], 16;" :: "r"(d), "l"(s))
#define CP_COMMIT()  asm volatile("cp.async.commit_group;" ::: "memory")
#define CP_WAIT1()   asm volatile("cp.async.wait_group 1;" ::: "memory")
#define CP_WAIT0()   asm volatile("cp.async.wait_group 0;" ::: "memory")

__device__ __forceinline__ uint32_t smem_u32(const void* p) {
    uint32_t a;
    asm("{ .reg .u64 t; cvta.to.shared.u64 t, %1; cvt.u32.u64 %0, t; }" : "=r"(a) : "l"(p));
    return a;
}
__device__ __forceinline__ ull enc_key(float f, int idx) {
    uint32_t u = __float_as_uint(f);
    u = (u & 0x80000000u) ? ~u : (u | 0x80000000u);
    return ((ull)u << 32) | (uint32_t)idx;
}
__device__ __forceinline__ float dec_val(ull k) {
    uint32_t e = (uint32_t)(k >> 32);
    uint32_t u = (e & 0x80000000u) ? (e ^ 0x80000000u) : ~e;
    return __uint_as_float(u);
}

__device__ __forceinline__ float blockReduceSum(float v) {
    __shared__ float sw[32];
    int lane = threadIdx.x & 31, w = threadIdx.x >> 5;
    #pragma unroll
    for (int o = 16; o; o >>= 1) v += __shfl_xor_sync(~0u, v, o);
    if (lane == 0) sw[w] = v;
    __syncthreads();
    int nw = (blockDim.x + 31) >> 5;
    v = (threadIdx.x < nw) ? sw[threadIdx.x] : 0.f;
    if (w == 0) {
        #pragma unroll
        for (int o = 16; o; o >>= 1) v += __shfl_xor_sync(~0u, v, o);
    }
    return v;
}

// ---------------- small kernels ----------------
__global__ void k_init() {
    int i = blockIdx.x * blockDim.x + threadIdx.x;
    if (i < 2 * B * HW) ((ull*)g_key)[i] = ~0ull;
    if (blockIdx.x == 0 && threadIdx.x < 32) g_acc[threadIdx.x] = 0.0;
}

// ---- single pass: f32 spatial -> both bf16 layouts + exact f32 norms ----
#define PAD   385
#define PKSM  (32 * PAD * 4 + 8 * 32 * 4)
__global__ void __launch_bounds__(256) k_packall(const float* __restrict__ s1,
                                                 const float* __restrict__ s2) {
    extern __shared__ uint32_t sm[];
    float* nsum = (float*)(sm + 32 * PAD);
    int t = blockIdx.y;
    const float* src = t ? s2 : s1;
    int b  = blockIdx.x / (HW / 32);
    int m0 = (blockIdx.x % (HW / 32)) * 32;
    int tid = threadIdx.x, tx = tid & 31, ty = tid >> 5;
    int m = m0 + tx;

    const float* base = src + (size_t)b * C * HW + m;
    float s = 0.f;
    for (int k2 = ty; k2 < C/2; k2 += 8) {
        float v0 = base[(size_t)(2 * k2) * HW];
        float v1 = base[(size_t)(2 * k2 + 1) * HW];
        s += v0 * v0 + v1 * v1;
        sm[tx * PAD + k2] = packbf(v0, v1);
    }
    nsum[ty * 32 + tx] = s;
    __syncthreads();
    if (ty == 0) {
        float tot = 0.f;
        #pragma unroll
        for (int q = 0; q < 8; q++) tot += nsum[q * 32 + tx];
        (t ? g_b2 : g_a2)[b * HW + m] = tot;
    }
    uint32_t* dstT = g_sbt[t] + ((size_t)b * HW + m0) * (C/2);
    for (int idx = tid; idx < 32 * (C/2); idx += 256) {
        int r = idx / (C/2), k2 = idx % (C/2);
        dstT[(size_t)r * (C/2) + k2] = sm[r * PAD + k2];
    }
    uint32_t* dstK = g_sbf[t] + (size_t)b * (C/2) * HW + m0;
    for (int idx = tid; idx < 32 * (C/2); idx += 256) {
        int k2 = idx >> 5, mm = idx & 31;
        dstK[(size_t)k2 * HW + mm] = sm[mm * PAD + k2];
    }
}

// ---------------- bf16 MMA machinery ----------------
#define LDW2   136
#define MATW2  (16*LDW2)
#define SSTR2  (2*MATW2)
#define GS2    (2 * SSTR2 * 4)

// 128m x 32n step (gram)
#define FRAGP(As, Bs, kb2)                                                       \
    {                                                                            \
        uint4 A0 = *(const uint4*)&As[(kb2 + gc    ) * LDW2 + wm      + gr * 4]; \
        uint4 A1 = *(const uint4*)&As[(kb2 + gc + 4) * LDW2 + wm      + gr * 4]; \
        uint4 A2 = *(const uint4*)&As[(kb2 + gc    ) * LDW2 + wm + 32 + gr * 4]; \
        uint4 A3 = *(const uint4*)&As[(kb2 + gc + 4) * LDW2 + wm + 32 + gr * 4]; \
        uint4 B0 = *(const uint4*)&Bs[(kb2 + gc    ) * LDW2 + wn      + gr * 4]; \
        uint4 B1 = *(const uint4*)&Bs[(kb2 + gc + 4) * LDW2 + wn      + gr * 4]; \
        mma_bf16(acc[0][0], A0.x, A0.y, A1.x, A1.y, B0.x, B1.x);                 \
        mma_bf16(acc[0][1], A0.x, A0.y, A1.x, A1.y, B0.y, B1.y);                 \
        mma_bf16(acc[0][2], A0.x, A0.y, A1.x, A1.y, B0.z, B1.z);                 \
        mma_bf16(acc[0][3], A0.x, A0.y, A1.x, A1.y, B0.w, B1.w);                 \
        mma_bf16(acc[1][0], A0.z, A0.w, A1.z, A1.w, B0.x, B1.x);                 \
        mma_bf16(acc[1][1], A0.z, A0.w, A1.z, A1.w, B0.y, B1.y);                 \
        mma_bf16(acc[1][2], A0.z, A0.w, A1.z, A1.w, B0.z, B1.z);                 \
        mma_bf16(acc[1][3], A0.z, A0.w, A1.z, A1.w, B0.w, B1.w);                 \
        mma_bf16(acc[2][0], A2.x, A2.y, A3.x, A3.y, B0.x, B1.x);                 \
        mma_bf16(acc[2][1], A2.x, A2.y, A3.x, A3.y, B0.y, B1.y);                 \
        mma_bf16(acc[2][2], A2.x, A2.y, A3.x, A3.y, B0.z, B1.z);                 \
        mma_bf16(acc[2][3], A2.x, A2.y, A3.x, A3.y, B0.w, B1.w);                 \
        mma_bf16(acc[3][0], A2.z, A2.w, A3.z, A3.w, B0.x, B1.x);                 \
        mma_bf16(acc[3][1], A2.z, A2.w, A3.z, A3.w, B0.y, B1.y);                 \
        mma_bf16(acc[3][2], A2.z, A2.w, A3.z, A3.w, B0.z, B1.z);                 \
        mma_bf16(acc[3][3], A2.z, A2.w, A3.z, A3.w, B0.w, B1.w);                 \
    }

// 96m x 24n step (gemm): 3 m-frags x 3 n-frags.
// B: lane gr loads 3 scalar words at wn + gr*3 + j; frag col p=2gc+rb -> n = wn + 6gc + 3rb + j
#define FRAGP96(As, Bs, kb2)                                                         \
    {                                                                                \
        uint4 A0 = *(const uint4*)&As[(kb2 + gc    ) * LDW2 + wm      + gr * 4];     \
        uint4 A2 = *(const uint4*)&As[(kb2 + gc + 4) * LDW2 + wm      + gr * 4];     \
        uint2 A1 = *(const uint2*)&As[(kb2 + gc    ) * LDW2 + wm + 32 + gr * 2];     \
        uint2 A3 = *(const uint2*)&As[(kb2 + gc + 4) * LDW2 + wm + 32 + gr * 2];     \
        const uint32_t* bl = &Bs[(kb2 + gc    ) * LDW2 + wn + gr * 3];               \
        const uint32_t* bh = &Bs[(kb2 + gc + 4) * LDW2 + wn + gr * 3];               \
        uint32_t b00 = bl[0], b01 = bl[1], b02 = bl[2];                              \
        uint32_t b10 = bh[0], b11 = bh[1], b12 = bh[2];                              \
        mma_bf16(acc[0][0], A0.x, A0.y, A2.x, A2.y, b00, b10);                       \
        mma_bf16(acc[0][1], A0.x, A0.y, A2.x, A2.y, b01, b11);                       \
        mma_bf16(acc[0][2], A0.x, A0.y, A2.x, A2.y, b02, b12);                       \
        mma_bf16(acc[1][0], A0.z, A0.w, A2.z, A2.w, b00, b10);                       \
        mma_bf16(acc[1][1], A0.z, A0.w, A2.z, A2.w, b01, b11);                       \
        mma_bf16(acc[1][2], A0.z, A0.w, A2.z, A2.w, b02, b12);                       \
        mma_bf16(acc[2][0], A1.x, A1.y, A3.x, A3.y, b00, b10);                       \
        mma_bf16(acc[2][1], A1.x, A1.y, A3.x, A3.y, b01, b11);                       \
        mma_bf16(acc[2][2], A1.x, A1.y, A3.x, A3.y, b02, b12);                       \
    }

// ---- fused bf16 GEMM + argmin. CTA 96x96 (zero waste: 6x6x96=576), 8 warps (2m x 4n) ----
__global__ void __launch_bounds__(256, 2) k_gemm_fused() {
    extern __shared__ uint32_t dyn[];
    int b  = blockIdx.z;
    int m0 = blockIdx.y * 96, n0 = blockIdx.x * 96;
    int tid = threadIdx.x, w = tid >> 5, lane = tid & 31;
    int wm = (w & 1) * 48, wn = (w >> 1) * 24;
    int gr = lane >> 2, gc = lane & 3;

    const uint32_t* Ag = g_sbf[0] + (size_t)b * (C/2) * HW;
    const uint32_t* Bg = g_sbf[1] + (size_t)b * (C/2) * HW;
    uint32_t sbase = smem_u32(dyn);

    // 768 copy slots: [0,384) A tile (16x24 uint4), [384,768) B tile; 3 per thread
    int srow[3], scol[3], smat[3];
    #pragma unroll
    for (int t = 0; t < 3; t++) {
        int v = tid + t * 256;
        smat[t] = v >= 384;
        int u = smat[t] ? v - 384 : v;
        srow[t] = u / 24;
        scol[t] = (u % 24) * 4;
    }
    auto issue_chunk = [&](int s, int stage) {
        int k20 = s * 16;
        uint32_t sA = sbase + stage * (SSTR2 * 4);
        uint32_t sB = sA + MATW2 * 4;
        #pragma unroll
        for (int t = 0; t < 3; t++) {
            const uint32_t* src = smat[t] ? Bg : Ag;
            int base0 = smat[t] ? n0 : m0;
            uint32_t dst = (smat[t] ? sB : sA) + (srow[t] * LDW2 + scol[t]) * 4;
            CP_CG16(dst, (const char*)&src[(size_t)(k20 + srow[t]) * HW + base0 + scol[t]]);
        }
        CP_COMMIT();
    };

    float acc[3][3][4] = {};
    issue_chunk(0, 0);
    for (int s = 0; s < NCH; s++) {
        if (s + 1 < NCH) { issue_chunk(s + 1, (s + 1) & 1); CP_WAIT1(); }
        else             { CP_WAIT0(); }
        __syncthreads();
        const uint32_t* As = dyn + (s & 1) * SSTR2;
        const uint32_t* Bs = As + MATW2;
        FRAGP96(As, Bs, 0)
        FRAGP96(As, Bs, 8)
        __syncthreads();
    }

    // ---- fused argmin epilogue (all indices in-bounds by construction) ----
    ull* rkey = (ull*)dyn;          // [96]
    ull* ckey = rkey + 96;          // [96]
    if (tid < 192) { if (tid < 96) rkey[tid] = ~0ull; else ckey[tid - 96] = ~0ull; }
    __syncthreads();

    const float* a2p = g_a2 + b * HW;
    const float* b2p = g_b2 + b * HW;

    #pragma unroll
    for (int i = 0; i < 3; i++) {
        int mbase = (i < 2) ? (wm + gr * 4 + i * 2) : (wm + 32 + gr * 2);
        #pragma unroll
        for (int half = 0; half < 2; half++) {
            int ml = mbase + half;
            ull rb_ = ~0ull;
            #pragma unroll
            for (int j = 0; j < 3; j++)
                #pragma unroll
                for (int rb = 0; rb < 2; rb++) {
                    int n_g = n0 + wn + 6 * gc + 3 * rb + j;
                    ull k = enc_key(b2p[n_g] - 2.f * acc[i][j][half * 2 + rb], n_g);
                    if (k < rb_) rb_ = k;
                }
            atomicMin(&rkey[ml], rb_);
        }
    }
    #pragma unroll
    for (int j = 0; j < 3; j++)
        #pragma unroll
        for (int rb = 0; rb < 2; rb++) {
            int nl = wn + 6 * gc + 3 * rb + j;
            ull cbest = ~0ull;
            #pragma unroll
            for (int i = 0; i < 3; i++) {
                int mbase = m0 + ((i < 2) ? (wm + gr * 4 + i * 2) : (wm + 32 + gr * 2));
                #pragma unroll
                for (int half = 0; half < 2; half++) {
                    int m_g = mbase + half;
                    ull k = enc_key(a2p[m_g] - 2.f * acc[i][j][half * 2 + rb], m_g);
                    if (k < cbest) cbest = k;
                }
            }
            atomicMin(&ckey[nl], cbest);
        }
    __syncthreads();
    if (tid < 96) {
        atomicMin(&g_key[0][b * HW + m0 + tid], rkey[tid]);
    } else if (tid >= 128 && tid < 224) {
        atomicMin(&g_key[1][b * HW + n0 + tid - 128], ckey[tid - 128]);
    }
}

// ---- split-K bf16 MMA Gram: 128x128 tiles, relative stage indexing ----
__global__ void __launch_bounds__(256, 2) k_gram_mma() {
    extern __shared__ uint32_t dyn[];
    int t   = blockIdx.y & 3;
    int spl = blockIdx.y >> 2;
    const uint32_t* X = g_Xbf[t];
    int idx = blockIdx.x, ti = 0;
    while (idx >= 6 - ti) { idx -= 6 - ti; ti++; }
    int tj = ti + idx;
    int i0 = ti * 128, j0 = tj * 128;

    int tid = threadIdx.x, w = tid >> 5, lane = tid & 31;
    int wm = (w & 1) * 64, wn = (w >> 1) * 32;
    int gr = lane >> 2, gc = lane & 3;
    uint32_t sbase = smem_u32(dyn);

    int s0 = spl * SPLC;
    auto issue_chunk = [&](int r, int stage) {
        int k20 = (s0 + r) * 16;
        uint32_t sA = sbase + stage * (SSTR2 * 4);
        uint32_t sB = sA + MATW2 * 4;
        #pragma unroll
        for (int tt = 0; tt < 2; tt++) {
            int v = tid + tt * 256;
            int row = v >> 5, col = (v & 31) * 4;
            uint32_t so = (row * LDW2 + col) * 4;
            CP_CG16(sA + so, (const char*)&X[(size_t)(k20 + row) * C + i0 + col]);
            CP_CG16(sB + so, (const char*)&X[(size_t)(k20 + row) * C + j0 + col]);
        }
        CP_COMMIT();
    };

    float acc[4][4][4] = {};
    issue_chunk(0, 0);
    for (int r = 0; r < SPLC; r++) {
        if (r + 1 < SPLC) { issue_chunk(r + 1, (r + 1) & 1); CP_WAIT1(); }
        else              { CP_WAIT0(); }
        __syncthreads();
        const uint32_t* As = dyn + (r & 1) * SSTR2;
        const uint32_t* Bs = As + MATW2;
        FRAGP(As, Bs, 0)
        FRAGP(As, Bs, 8)
        __syncthreads();
    }

    float* Sp = g_Sp[t][spl];
    #pragma unroll
    for (int i = 0; i < 4; i++) {
        int mbase = i0 + wm + (i >> 1) * 32 + gr * 4 + (i & 1) * 2;
        #pragma unroll
        for (int half = 0; half < 2; half++)
            #pragma unroll
            for (int rb = 0; rb < 2; rb++) {
                int c2 = j0 + wn + 8 * gc + 4 * rb;
                float4 o = make_float4(acc[i][0][half * 2 + rb], acc[i][1][half * 2 + rb],
                                       acc[i][2][half * 2 + rb], acc[i][3][half * 2 + rb]);
                *(float4*)&Sp[(size_t)(mbase + half) * C + c2] = o;
            }
    }
}

// rank-based top-50 smallest d2 (ties -> lowest index); scalar loop (R15 form)
__global__ void k_select() {
    int b = blockIdx.x, dir = blockIdx.y;
    __shared__ float sd[HW];
    __shared__ int   sn[HW];
    int i = threadIdx.x;
    ull key = g_key[dir][b * HW + i];
    const float* own = dir ? g_b2 : g_a2;
    float d2 = own[b * HW + i] + dec_val(key);
    if (d2 < 0.f) d2 = 0.f;
    sd[i] = d2;
    sn[i] = (int)(uint32_t)key;
    __syncthreads();
    float di = sd[i];
    int rank = 0;
    for (int j = 0; j < HW; j++) {
        float dj = sd[j];
        rank += (dj < di) || (dj == di && j < i);
    }
    if (rank < NM) {
        g_sel_in[dir][b * NM + rank] = i;
        g_sel_c [dir][b * NM + rank] = sn[i];
    }
}

// gather row PAIRS from transposed bf16 copy (coalesced); inv from bf16 values
__global__ void __launch_bounds__(128) k_gather2() {
    int p = blockIdx.x;
    int dir = blockIdx.y;
    int r0 = 2 * p, r1 = r0 + 1;
    int b = r0 / NM;
    const uint32_t* Tin = g_sbt[dir ? 1 : 0];
    const uint32_t* Tc  = g_sbt[dir ? 0 : 1];
    const uint32_t* in0 = Tin + ((size_t)b * HW + g_sel_in[dir][r0]) * (C/2);
    const uint32_t* in1 = Tin + ((size_t)b * HW + g_sel_in[dir][r1]) * (C/2);
    const uint32_t* c0  = Tc  + ((size_t)b * HW + g_sel_c [dir][r0]) * (C/2);
    const uint32_t* c1  = Tc  + ((size_t)b * HW + g_sel_c [dir][r1]) * (C/2);
    uint32_t* Xin = g_Xbf[dir * 2 + 0] + (size_t)p * C;
    uint32_t* Xc  = g_Xbf[dir * 2 + 1] + (size_t)p * C;
    float lsum = 0.f;
    for (int k2 = threadIdx.x; k2 < C/2; k2 += 128) {
        uint32_t wi0 = in0[k2], wi1 = in1[k2];
        uint32_t wc0 = c0[k2],  wc1 = c1[k2];
        ((uint2*)Xin)[k2] = make_uint2(__byte_perm(wi0, wi1, 0x5410),
                                       __byte_perm(wi0, wi1, 0x7632));
        ((uint2*)Xc)[k2]  = make_uint2(__byte_perm(wc0, wc1, 0x5410),
                                       __byte_perm(wc0, wc1, 0x7632));
        float d;
        d = bf_lo(wi0) - bf_lo(wc0); lsum += d * d;
        d = bf_hi(wi0) - bf_hi(wc0); lsum += d * d;
        d = bf_lo(wi1) - bf_lo(wc1); lsum += d * d;
        d = bf_hi(wi1) - bf_hi(wc1); lsum += d * d;
    }
    float tot = blockReduceSum(lsum);
    if (threadIdx.x == 0) atomicAdd(&g_acc[1 + dir], (double)tot);
}

__global__ void k_pooled_inv(const float* __restrict__ p1, const float* __restrict__ p2) {
    float lsum = 0.f;
    for (int i = blockIdx.x * blockDim.x + threadIdx.x; i < B * C; i += gridDim.x * blockDim.x) {
        float d = p1[i] - p2[i]; lsum += d * d;
    }
    float tot = blockReduceSum(lsum);
    if (threadIdx.x == 0) atomicAdd(&g_acc[0], (double)tot);
}

__device__ __forceinline__ int tensor_n(int t) { return (t < 4) ? NSEL : B; }

__device__ __forceinline__ float S_at(int t, int c1, int c2) {
    size_t i = (size_t)c1 * C + c2;
    if (t < 4)
        return g_Sp[t][0][i] + g_Sp[t][1][i] + g_Sp[t][2][i] + g_Sp[t][3][i];
    return g_S[t - 4][i];
}

__global__ void k_colsum_part(const float* __restrict__ p1, const float* __restrict__ p2) {
    int t = blockIdx.x, chunk = blockIdx.y, c = threadIdx.x;
    float s = 0.f;
    if (t < 4) {
        const uint32_t* X = g_Xbf[t];
        int n20 = chunk * (NSEL / 2 / 16), n21 = n20 + NSEL / 2 / 16;
        for (int i = n20; i < n21; i++) {
            uint32_t w = X[(size_t)i * C + c];
            s += bf_lo(w) + bf_hi(w);
        }
    } else {
        const float* X = (t == 4) ? p1 : p2;
        int n0 = chunk * (B / 16), n1 = n0 + B / 16;
        for (int i = n0; i < n1; i++) s += X[(size_t)i * C + c];
    }
    g_csp[t][chunk][c] = s;
}
__global__ void k_colsum_fin() {
    int t = blockIdx.x, c = threadIdx.x;
    float s = 0.f;
    #pragma unroll
    for (int k = 0; k < 16; k++) s += g_csp[t][k][c];
    g_colsum[t][c] = s;
}

// exact fp32 Gram for the 2 pooled tensors (n=64), upper 64x64 tiles
__global__ void __launch_bounds__(256) k_gram(const float* __restrict__ p1,
                                              const float* __restrict__ p2) {
    int t = blockIdx.y;
    const float* X = t ? p2 : p1;
    int n = B;
    int idx = blockIdx.x, ti = 0;
    while (idx >= 12 - ti) { idx -= 12 - ti; ti++; }
    int tj = ti + idx;
    int i0 = ti * 64, j0 = tj * 64;

    __shared__ float As[16][64], Bs[16][64];
    int tid = threadIdx.x;
    int tx = tid & 15, ty = tid >> 4;
    int lk = tid >> 4, lo = (tid & 15) * 4;
    float acc[4][4] = {};
    for (int k0 = 0; k0 < n; k0 += 16) {
        *(float4*)&As[lk][lo] = *(const float4*)&X[(size_t)(k0 + lk) * C + i0 + lo];
        *(float4*)&Bs[lk][lo] = *(const float4*)&X[(size_t)(k0 + lk) * C + j0 + lo];
        __syncthreads();
        #pragma unroll
        for (int kk = 0; kk < 16; kk++) {
            float a[4], bb[4];
            *(float4*)a  = *(float4*)&As[kk][ty * 4];
            *(float4*)bb = *(float4*)&Bs[kk][tx * 4];
            #pragma unroll
            for (int i = 0; i < 4; i++)
                #pragma unroll
                for (int j = 0; j < 4; j++) acc[i][j] += a[i] * bb[j];
        }
        __syncthreads();
    }
    float* Sp = g_S[t];
    #pragma unroll
    for (int i = 0; i < 4; i++) {
        int c1 = i0 + ty * 4 + i;
        *(float4*)&Sp[(size_t)c1 * C + j0 + tx * 4] = *(float4*)acc[i];
    }
}

__global__ void k_std() {
    int t = blockIdx.x, c = threadIdx.x;
    float n  = (float)tensor_n(t);
    float mu = g_colsum[t][c] / n;
    float Scc = S_at(t, c, c);
    float var = (Scc - n * mu * mu) / (n - 1.f);
    float sd  = sqrtf(var + EPSV);
    float contrib = fmaxf(1.f - sd, 0.f);
    float tot = blockReduceSum(contrib);
    if (threadIdx.x == 0) atomicAdd(&g_acc[3 + t], (double)tot);
}

__global__ void k_cov() {
    int t = blockIdx.y;
    float n = (float)tensor_n(t);
    float inv_nm1 = 1.f / (n - 1.f);
    int idx = blockIdx.x, ti = 0;
    while (idx >= 12 - ti) { idx -= 12 - ti; ti++; }
    int tj = ti + idx;
    int i0 = ti * 64, j0 = tj * 64;
    float lsum = 0.f;
    #pragma unroll
    for (int it = 0; it < 16; it++) {
        int e = it * 256 + threadIdx.x;
        int r = e >> 6, cc = e & 63;
        int c1 = i0 + r, c2 = j0 + cc;
        if (c2 > c1) {
            float mu1 = g_colsum[t][c1] / n;
            float mu2 = g_colsum[t][c2] / n;
            float cov = (S_at(t, c1, c2) - n * mu1 * mu2) * inv_nm1;
            lsum += 2.f * cov * cov;
        }
    }
    float tot = blockReduceSum(lsum);
    if (threadIdx.x == 0) atomicAdd(&g_acc[10 + t], (double)tot);
}

__global__ void k_final(float* __restrict__ out) {
    double inv_g = g_acc[0] / (double)(B * C);
    double inv1  = g_acc[1] / (double)((size_t)NSEL * C);
    double inv2  = g_acc[2] / (double)((size_t)NSEL * C);
    double stdt[6], covt[6];
    for (int t = 0; t < 6; t++) {
        stdt[t] = (g_acc[3 + t] / (double)C) * 0.5;
        covt[t] = g_acc[10 + t] / (double)C;
    }
    double glob = 25.0 * inv_g + 25.0 * (stdt[4] + stdt[5]) + (covt[4] + covt[5]);
    double loc  = 0.5 * (25.0 * inv1 + 25.0 * inv2)
                + 0.5 * (25.0 * (stdt[0] + stdt[1]) + 25.0 * (stdt[2] + stdt[3]))
                + 0.5 * ((covt[0] + covt[1]) + (covt[2] + covt[3]));
    out[0] = (float)(0.5 * glob + 0.5 * loc);
}

// ---------------- launch ----------------
extern "C" void kernel_launch(void* const* d_in, const int* in_sizes, int n_in,
                              void* d_out, int out_size) {
    const float* s1 = (const float*)d_in[0];
    const float* p1 = (const float*)d_in[1];
    const float* s2 = (const float*)d_in[2];
    const float* p2 = (const float*)d_in[3];
    float* out = (float*)d_out;

    cudaFuncSetAttribute(k_packall,    cudaFuncAttributeMaxDynamicSharedMemorySize, PKSM);
    cudaFuncSetAttribute(k_gemm_fused, cudaFuncAttributeMaxDynamicSharedMemorySize, GS2);
    cudaFuncSetAttribute(k_gram_mma,   cudaFuncAttributeMaxDynamicSharedMemorySize, GS2);

    k_init<<<(2 * B * HW + 255) / 256, 256>>>();
    k_packall<<<dim3(B * (HW / 32), 2), 256, PKSM>>>(s1, s2);
    k_gemm_fused<<<dim3(6, 6, B), 256, GS2>>>();
    k_select<<<dim3(B, 2), HW>>>();
    k_gather2<<<dim3(NSEL / 2, 2), 128>>>();
    k_pooled_inv<<<48, 256>>>(p1, p2);
    k_colsum_part<<<dim3(6, 16), C>>>(p1, p2);
    k_colsum_fin<<<6, C>>>();
    k_gram_mma<<<dim3(21, 4 * NSPL), 256, GS2>>>();
    k_gram<<<dim3(78, 2), 256>>>(p1, p2);
    k_std<<<6, C>>>();
    k_cov<<<dim3(78, 6), 256>>>();
    k_final<<<1, 1>>>(out);
}